// round 8
// baseline (speedup 1.0000x reference)
#include <cuda_runtime.h>
#include <cuda_fp16.h>
#include <math.h>
#include <stdint.h>

// Problem constants
#define Bc   8
#define Nc   512
#define Tc   64
#define NINc 64
#define NHc  128
#define Rc   (Bc * Nc)   // 4096 rows
#define NCTA 128

// ---------------- scratch (device globals) ----------------------------------
__device__ float g_dinv[Rc];
__device__ __half g_Anh[Bc * Nc * Nc];          // An hi (4 MB)
__device__ __half g_Anl[Bc * Nc * Nc];          // An lo
__device__ float g_es[Rc * NHc];                // static embedding fp32
__device__ float g_Wes[128 * 512];              // Wi[0:128] interleaved fp32
__device__ float g_bbig[512];
__device__ float g_Ges[Rc * 512];               // es @ Wes + bbig (fp32, interleaved)
__device__ __half g_WTh[512 * 256];             // Wcomb^T hi: [n][k]
__device__ __half g_WTl[512 * 256];
__device__ __half g_WoTh[64 * 128];             // Wout^T hi: [n][k]
__device__ __half g_WoTl[64 * 128];
__device__ __half g_Hh[Rc * NHc];               // H = An@h, hi/lo, row-major
__device__ __half g_Hl[Rc * NHc];
__device__ __half g_hrh[2][Rc * NHc];           // h row-major hi/lo (double buffered)
__device__ __half g_hrl[2][Rc * NHc];
__device__ __half g_hTh[2][Bc * NHc * Nc];      // h transposed per batch [b][j][n]
__device__ __half g_hTl[2][Bc * NHc * Nc];
__device__ float g_c[Rc * NHc];                 // cell state
__device__ float g_Xi[Rc * NINc];               // running output accumulator
__device__ unsigned g_count;                    // grid barrier arrive counter
__device__ unsigned g_sense;                    // grid barrier generation

// ---------------- helpers ----------------------------------------------------
__device__ __forceinline__ uint32_t smem_u32(const void* p) {
    uint32_t a;
    asm("{ .reg .u64 t; cvta.to.shared.u64 t, %1; cvt.u32.u64 %0, t; }" : "=r"(a) : "l"(p));
    return a;
}
// fast sigmoid / tanh via MUFU paths
__device__ __forceinline__ float sigm(float x) {
    return __fdividef(1.f, 1.f + __expf(-x));
}
__device__ __forceinline__ float ftanh(float x) {
    float e = __expf(2.f * x);
    return 1.f - __fdividef(2.f, e + 1.f);
}
__device__ __forceinline__ void hsplit(float v, __half& hi, __half& lo) {
    hi = __float2half_rn(v);
    lo = __float2half_rn(v - __half2float(hi));
}
__device__ __forceinline__ void cpa16(uint32_t dst, const void* src) {
    asm volatile("cp.async.cg.shared.global [%0], [%1], 16;" :: "r"(dst), "l"(src) : "memory");
}
#define CP_COMMIT() asm volatile("cp.async.commit_group;" ::: "memory")
#define CP_WAIT1()  asm volatile("cp.async.wait_group 1;" ::: "memory")
#define CP_WAIT0()  asm volatile("cp.async.wait_group 0;" ::: "memory")

__device__ __forceinline__ void ldsm4(uint32_t* r, uint32_t a) {
    asm volatile("ldmatrix.sync.aligned.m8n8.x4.shared.b16 {%0,%1,%2,%3}, [%4];"
        : "=r"(r[0]), "=r"(r[1]), "=r"(r[2]), "=r"(r[3]) : "r"(a));
}
// main pass: fp16 operands, fp32 accumulator
__device__ __forceinline__ void mmaf(float* d, const uint32_t* a, const uint32_t* b) {
    asm volatile("mma.sync.aligned.m16n8k16.row.col.f32.f16.f16.f32 "
        "{%0,%1,%2,%3}, {%4,%5,%6,%7}, {%8,%9}, {%0,%1,%2,%3};"
        : "+f"(d[0]), "+f"(d[1]), "+f"(d[2]), "+f"(d[3])
        : "r"(a[0]), "r"(a[1]), "r"(a[2]), "r"(a[3]), "r"(b[0]), "r"(b[1]));
}
// correction pass: fp16 accumulator (2x rate)
__device__ __forceinline__ void mmah(uint32_t* d, const uint32_t* a, const uint32_t* b) {
    asm volatile("mma.sync.aligned.m16n8k16.row.col.f16.f16.f16.f16 "
        "{%0,%1}, {%2,%3,%4,%5}, {%6,%7}, {%0,%1};"
        : "+r"(d[0]), "+r"(d[1])
        : "r"(a[0]), "r"(a[1]), "r"(a[2]), "r"(a[3]), "r"(b[0]), "r"(b[1]));
}
// merge fp16 correction acc into fp32 acc (layout-matched)
__device__ __forceinline__ void hmerge(float* d, const uint32_t* h) {
    __half2 q0 = *(const __half2*)&h[0];
    __half2 q1 = *(const __half2*)&h[1];
    d[0] += __half2float(q0.x); d[1] += __half2float(q0.y);
    d[2] += __half2float(q1.x); d[3] += __half2float(q1.y);
}

// grid-wide sense barrier (128 CTAs, all co-resident)
__device__ __forceinline__ void gbar(unsigned gen) {
    __syncthreads();
    if (threadIdx.x == 0) {
        unsigned prev;
        asm volatile("atom.release.gpu.add.u32 %0, [%1], %2;"
                     : "=r"(prev) : "l"(&g_count), "r"(1u) : "memory");
        if (prev == NCTA - 1) {
            g_count = 0u;
            asm volatile("st.release.gpu.u32 [%0], %1;" :: "l"(&g_sense), "r"(gen) : "memory");
        } else {
            unsigned s;
            do {
                asm volatile("ld.acquire.gpu.u32 %0, [%1];" : "=r"(s) : "l"(&g_sense) : "memory");
            } while (s < gen);
        }
    }
    __syncthreads();
}

#define RS 144        // stage tile row stride (72 halves)
#define GH_T   9216   // gH tile: 64 rows x RS
#define GG_T   18432  // gG tile: 128 rows x RS
#define STG_SZ 36864  // stage size (both phases)
#define SM_WT    73728
#define WT_RSB   528
#define WT_SZ    67584
#define SM_TOTAL (SM_WT + 2 * WT_SZ)   // 208896
// out-phase stage offsets (within [0,73728))
#define OUT_RSB  272
#define OUT_HA   0
#define OUT_HAL  8704
#define OUT_WB   17408
#define OUT_WBL  34816

// ---------------------------------------------------------------------------
__global__ void k_dinv(const float* __restrict__ A) {
    int row = blockIdx.x;
    const float* arow = A + (size_t)row * Nc;
    float s = 0.f;
    for (int j = threadIdx.x; j < Nc; j += blockDim.x) s += arow[j];
    __shared__ float sh[128];
    sh[threadIdx.x] = s;
    __syncthreads();
    for (int off = 64; off > 0; off >>= 1) {
        if (threadIdx.x < off) sh[threadIdx.x] += sh[threadIdx.x + off];
        __syncthreads();
    }
    if (threadIdx.x == 0) {
        float d = sh[0];
        g_dinv[row] = (d > 0.f) ? rsqrtf(d) : 0.f;
    }
}

__global__ void k_an(const float* __restrict__ A) {
    int idx = blockIdx.x * blockDim.x + threadIdx.x;
    int e = idx * 4;
    int b   = e >> 18;
    int rem = e & 262143;
    int i   = rem >> 9;
    int j   = rem & 511;
    float4 a = *(const float4*)(A + (size_t)e);
    float di = g_dinv[b * 512 + i];
    const float* dj = g_dinv + b * 512 + j;
    float v[4] = { a.x * di * dj[0], a.y * di * dj[1], a.z * di * dj[2], a.w * di * dj[3] };
    __half h[4], l[4];
#pragma unroll
    for (int q = 0; q < 4; q++) hsplit(v[q], h[q], l[q]);
    __half2* ph = (__half2*)(g_Anh + (size_t)e);
    __half2* pl = (__half2*)(g_Anl + (size_t)e);
    ph[0] = __halves2half2(h[0], h[1]); ph[1] = __halves2half2(h[2], h[3]);
    pl[0] = __halves2half2(l[0], l[1]); pl[1] = __halves2half2(l[2], l[3]);
}

// ---------------------------------------------------------------------------
__global__ void k_prep(const float* __restrict__ Wii, const float* __restrict__ bii,
                       const float* __restrict__ Whi, const float* __restrict__ bhi,
                       const float* __restrict__ Wif, const float* __restrict__ bif_,
                       const float* __restrict__ Whf, const float* __restrict__ bhf,
                       const float* __restrict__ Wig, const float* __restrict__ big_,
                       const float* __restrict__ Whg, const float* __restrict__ bhg,
                       const float* __restrict__ Wio, const float* __restrict__ bio,
                       const float* __restrict__ Who, const float* __restrict__ bho,
                       const float* __restrict__ Wpe, const float* __restrict__ bpe) {
    int n = blockIdx.x;
    int g = n & 3;
    int j = n >> 2;
    int t = threadIdx.x;
    const float* Wi = (g == 0) ? Wii : (g == 1) ? Wif : (g == 2) ? Wig : Wio;
    const float* Wh = (g == 0) ? Whi : (g == 1) ? Whf : (g == 2) ? Whg : Who;
    const float* bi = (g == 0) ? bii : (g == 1) ? bif_ : (g == 2) ? big_ : bio;
    const float* bh = (g == 0) ? bhi : (g == 1) ? bhf : (g == 2) ? bhg : bho;

    __shared__ float wcol[128];
    wcol[t] = Wi[(128 + t) * 128 + j];
    __syncthreads();

    g_Wes[t * 512 + n] = Wi[t * 128 + j];

    float acc = 0.f;
    const float* wpet = Wpe + t * 128;
#pragma unroll 8
    for (int m = 0; m < 128; m++) acc += wpet[m] * wcol[m];

    __half hh, ll;
    hsplit(acc, hh, ll);
    g_WTh[n * 256 + t] = hh;
    g_WTl[n * 256 + t] = ll;
    float whv = Wh[t * 128 + j];
    hsplit(whv, hh, ll);
    g_WTh[n * 256 + 128 + t] = hh;
    g_WTl[n * 256 + 128 + t] = ll;

    if (t == 0) {
        float ba = bi[j] + bh[j];
        for (int m = 0; m < 128; m++) ba += bpe[m] * wcol[m];
        g_bbig[n] = ba;
    }
}

// ---------------------------------------------------------------------------
// k_init: es = X0@Wse + bse ; zero h & c ; Xi = X0 ; out t=0 ; barrier reset ;
//         WoutT hi/lo (rows 0..63)
// ---------------------------------------------------------------------------
__global__ void k_init(const float* __restrict__ X, const float* __restrict__ Wse,
                       const float* __restrict__ bse, const float* __restrict__ Wout,
                       float* __restrict__ out) {
    int row = blockIdx.x;
    int t = threadIdx.x;
    if (row == 0 && t == 0) { g_count = 0u; g_sense = 0u; }
    if (row < 64) {
        __half hh, ll;
        hsplit(Wout[t * 64 + row], hh, ll);
        g_WoTh[row * 128 + t] = hh;
        g_WoTl[row * 128 + t] = ll;
    }
    __shared__ float x0[64];
    if (t < 64) {
        float v = X[(size_t)row * 4096 + t];
        x0[t] = v;
        g_Xi[row * 64 + t] = v;
        out[(size_t)row * 4096 + t] = v;
    }
    __syncthreads();
    float acc = bse[t];
#pragma unroll 8
    for (int k = 0; k < 64; k++) acc += x0[k] * Wse[k * 128 + t];
    g_es[row * 128 + t] = acc;

    __half z = __float2half(0.f);
    g_hrh[0][(size_t)row * 128 + t] = z;
    g_hrl[0][(size_t)row * 128 + t] = z;
    int bb = row >> 9, nn = row & 511;
    g_hTh[0][(size_t)(bb * 128 + t) * 512 + nn] = z;
    g_hTl[0][(size_t)(bb * 128 + t) * 512 + nn] = z;
    g_c[row * 128 + t] = 0.f;
}

// ---------------------------------------------------------------------------
// k_ges: Ges = es @ Wes + bbig (4096 x 512, K=128) fp32, runs once
// ---------------------------------------------------------------------------
__global__ void __launch_bounds__(256) k_ges() {
    int m0 = (blockIdx.x >> 2) * 64;
    int n0 = (blockIdx.x & 3) * 128;

    __shared__ __align__(16) float As[16][68];
    __shared__ __align__(16) float Bs[16][132];

    int tid = threadIdx.x;
    int ty = tid >> 4, tx = tid & 15;
    int ar = tid >> 2, ac = (tid & 3) * 4;
    int br = tid >> 5, bc = (tid & 31) * 4;

    float acc[4][8] = {};

    for (int k0 = 0; k0 < 128; k0 += 16) {
        float4 av = *(const float4*)&g_es[(size_t)(m0 + ar) * 128 + k0 + ac];
        float4 bv0 = *(const float4*)&g_Wes[(size_t)(k0 + br) * 512 + n0 + bc];
        float4 bv1 = *(const float4*)&g_Wes[(size_t)(k0 + br + 8) * 512 + n0 + bc];
        As[ac + 0][ar] = av.x; As[ac + 1][ar] = av.y;
        As[ac + 2][ar] = av.z; As[ac + 3][ar] = av.w;
        *(float4*)&Bs[br][bc] = bv0;
        *(float4*)&Bs[br + 8][bc] = bv1;
        __syncthreads();
#pragma unroll
        for (int kk = 0; kk < 16; kk++) {
            float4 a4 = *(const float4*)&As[kk][ty * 4];
            float4 b0 = *(const float4*)&Bs[kk][tx * 8];
            float4 b1 = *(const float4*)&Bs[kk][tx * 8 + 4];
            float av4[4] = { a4.x, a4.y, a4.z, a4.w };
            float bv8[8] = { b0.x, b0.y, b0.z, b0.w, b1.x, b1.y, b1.z, b1.w };
#pragma unroll
            for (int i = 0; i < 4; i++)
#pragma unroll
                for (int jq = 0; jq < 8; jq++) acc[i][jq] += av4[i] * bv8[jq];
        }
        __syncthreads();
    }

    float bb[8];
#pragma unroll
    for (int q = 0; q < 8; q++) bb[q] = g_bbig[n0 + tx * 8 + q];
#pragma unroll
    for (int r = 0; r < 4; r++) {
        int rr = m0 + ty * 4 + r;
        float* dst = &g_Ges[(size_t)rr * 512 + n0 + tx * 8];
#pragma unroll
        for (int q = 0; q < 8; q++) dst[q] = acc[r][q] + bb[q];
    }
}

// ---------------------------------------------------------------------------
// phase gH: H = An @ h, CTA tile 64x64 (8b x 8m x 2n = 128 tiles)
// ---------------------------------------------------------------------------
__device__ __forceinline__ void phase_gH(char* dsm, int hin, int cta, int tid) {
    uint32_t sbase = smem_u32(dsm);
    int wid = tid >> 5, lane = tid & 31;
    int wm = wid >> 2, wn = wid & 3;
    int b  = cta >> 4;
    int m0 = ((cta >> 1) & 7) * 64;
    int n0 = (cta & 1) * 64;

    float acc[2][2][4];
    uint32_t hacc[2][2][2];
#pragma unroll
    for (int i = 0; i < 2; i++)
#pragma unroll
        for (int j = 0; j < 2; j++) {
#pragma unroll
            for (int q = 0; q < 4; q++) acc[i][j][q] = 0.f;
            hacc[i][j][0] = 0u; hacc[i][j][1] = 0u;
        }

    const __half* Ah0 = g_Anh + (size_t)b * 262144 + (size_t)m0 * 512;
    const __half* Al0 = g_Anl + (size_t)b * 262144 + (size_t)m0 * 512;
    const __half* Bh0 = g_hTh[hin] + (size_t)b * 65536 + (size_t)n0 * 512;
    const __half* Bl0 = g_hTl[hin] + (size_t)b * 65536 + (size_t)n0 * 512;

    auto issue = [&](int cc, uint32_t buf) {
        int kc = cc * 64;
#pragma unroll
        for (int i = 0; i < 2; i++) {
            int idx = tid + i * 256, r = idx >> 3, c = idx & 7;
            uint32_t d = buf + r * RS + c * 16;
            size_t off = (size_t)r * 512 + kc + c * 8;
            cpa16(d,            Ah0 + off);
            cpa16(d + GH_T,     Al0 + off);
            cpa16(d + 2 * GH_T, Bh0 + off);
            cpa16(d + 3 * GH_T, Bl0 + off);
        }
    };

    issue(0, sbase);
    CP_COMMIT();

#pragma unroll 1
    for (int cc = 0; cc < 8; cc++) {
        if (cc + 1 < 8) issue(cc + 1, sbase + ((cc + 1) & 1) * STG_SZ);
        CP_COMMIT();
        CP_WAIT1();
        __syncthreads();

        uint32_t buf = sbase + (cc & 1) * STG_SZ;
        uint32_t aH = buf + (uint32_t)(wm * 32 + (lane & 15)) * RS + ((lane >> 4) * 16);
        uint32_t aL = aH + GH_T;
        uint32_t bH = buf + 2 * GH_T
                    + (uint32_t)(wn * 16 + (lane & 7) + ((lane >> 4) & 1) * 8) * RS
                    + (((lane >> 3) & 1) * 16);
        uint32_t bL = bH + GH_T;
#pragma unroll
        for (int ks = 0; ks < 4; ks++) {
            uint32_t ah[2][4], al[2][4], bh[4], bl[4];
            ldsm4(ah[0], aH + ks * 32); ldsm4(ah[1], aH + 16 * RS + ks * 32);
            ldsm4(al[0], aL + ks * 32); ldsm4(al[1], aL + 16 * RS + ks * 32);
            ldsm4(bh, bH + ks * 32);
            ldsm4(bl, bL + ks * 32);
#pragma unroll
            for (int mf = 0; mf < 2; mf++) {
                mmaf(acc[mf][0], ah[mf], &bh[0]); mmaf(acc[mf][1], ah[mf], &bh[2]);
                mmah(hacc[mf][0], al[mf], &bh[0]); mmah(hacc[mf][1], al[mf], &bh[2]);
                mmah(hacc[mf][0], ah[mf], &bl[0]); mmah(hacc[mf][1], ah[mf], &bl[2]);
            }
        }
        __syncthreads();
    }
    CP_WAIT0();

    int rbase = b * 512 + m0 + wm * 32 + (lane >> 2);
    int cbase = n0 + wn * 16 + (lane & 3) * 2;
#pragma unroll
    for (int mf = 0; mf < 2; mf++) {
#pragma unroll
        for (int nf = 0; nf < 2; nf++) {
            int col = cbase + nf * 8;
            float* d = acc[mf][nf];
            hmerge(d, hacc[mf][nf]);
            __half h0, l0, h1, l1;
            int r0 = rbase + mf * 16;
            hsplit(d[0], h0, l0); hsplit(d[1], h1, l1);
            *(__half2*)(g_Hh + (size_t)r0 * 128 + col) = __halves2half2(h0, h1);
            *(__half2*)(g_Hl + (size_t)r0 * 128 + col) = __halves2half2(l0, l1);
            hsplit(d[2], h0, l0); hsplit(d[3], h1, l1);
            *(__half2*)(g_Hh + (size_t)(r0 + 8) * 128 + col) = __halves2half2(h0, h1);
            *(__half2*)(g_Hl + (size_t)(r0 + 8) * 128 + col) = __halves2half2(l0, l1);
        }
    }
}

// ---------------------------------------------------------------------------
// phase gG: gates = Ges + [H | h] @ Wcomb, 128x128 tiles (32m x 4n).
// B persistent in smem; A streamed 4 chunks. fp16-acc correction passes.
// ---------------------------------------------------------------------------
__device__ __forceinline__ void phase_gG(char* dsm, int hin, int hout, int cta, int tid) {
    uint32_t sbase = smem_u32(dsm);
    int wid = tid >> 5, lane = tid & 31;
    int wm = wid >> 2, wn = wid & 3;
    int m0 = (cta >> 2) * 128;
    int n0 = (cta & 3) * 128;

    float acc[4][4][4];
    uint32_t hacc[4][4][2];
#pragma unroll
    for (int i = 0; i < 4; i++)
#pragma unroll
        for (int j = 0; j < 4; j++) {
#pragma unroll
            for (int q = 0; q < 4; q++) acc[i][j][q] = 0.f;
            hacc[i][j][0] = 0u; hacc[i][j][1] = 0u;
        }

    auto issue = [&](int cc, uint32_t buf) {
        int kc = cc * 64;
        const __half* Ahs;
        const __half* Als;
        if (kc < 128) {
            Ahs = g_Hh + (size_t)m0 * 128 + kc;
            Als = g_Hl + (size_t)m0 * 128 + kc;
        } else {
            Ahs = g_hrh[hin] + (size_t)m0 * 128 + (kc - 128);
            Als = g_hrl[hin] + (size_t)m0 * 128 + (kc - 128);
        }
#pragma unroll
        for (int i = 0; i < 4; i++) {
            int idx = tid + i * 256, r = idx >> 3, c = idx & 7;
            uint32_t d = buf + r * RS + c * 16;
            size_t off = (size_t)r * 128 + c * 8;
            cpa16(d,        Ahs + off);
            cpa16(d + GG_T, Als + off);
        }
    };

    issue(0, sbase);
    CP_COMMIT();

    uint32_t wtH = sbase + SM_WT
                 + (uint32_t)(wn * 32 + (lane & 7) + ((lane >> 4) & 1) * 8) * WT_RSB
                 + (((lane >> 3) & 1) * 16);
    uint32_t wtL = wtH + WT_SZ;

#pragma unroll 1
    for (int cc = 0; cc < 4; cc++) {
        if (cc + 1 < 4) issue(cc + 1, sbase + ((cc + 1) & 1) * STG_SZ);
        CP_COMMIT();
        CP_WAIT1();
        __syncthreads();

        uint32_t buf = sbase + (cc & 1) * STG_SZ;
        uint32_t aH = buf + (uint32_t)(wm * 64 + (lane & 15)) * RS + ((lane >> 4) * 16);
        uint32_t aL = aH + GG_T;
        uint32_t kb = (uint32_t)cc * 128;
#pragma unroll
        for (int ks = 0; ks < 4; ks++) {
            uint32_t ah[4][4], al[4][4], bh0[4], bh1[4], bl0[4], bl1[4];
#pragma unroll
            for (int mf = 0; mf < 4; mf++) {
                ldsm4(ah[mf], aH + mf * 16 * RS + ks * 32);
                ldsm4(al[mf], aL + mf * 16 * RS + ks * 32);
            }
            ldsm4(bh0, wtH + kb + ks * 32);
            ldsm4(bh1, wtH + 16 * WT_RSB + kb + ks * 32);
            ldsm4(bl0, wtL + kb + ks * 32);
            ldsm4(bl1, wtL + 16 * WT_RSB + kb + ks * 32);
#pragma unroll
            for (int mf = 0; mf < 4; mf++) {
                mmaf(acc[mf][0], ah[mf], &bh0[0]); mmaf(acc[mf][1], ah[mf], &bh0[2]);
                mmaf(acc[mf][2], ah[mf], &bh1[0]); mmaf(acc[mf][3], ah[mf], &bh1[2]);
                mmah(hacc[mf][0], al[mf], &bh0[0]); mmah(hacc[mf][1], al[mf], &bh0[2]);
                mmah(hacc[mf][2], al[mf], &bh1[0]); mmah(hacc[mf][3], al[mf], &bh1[2]);
                mmah(hacc[mf][0], ah[mf], &bl0[0]); mmah(hacc[mf][1], ah[mf], &bl0[2]);
                mmah(hacc[mf][2], ah[mf], &bl1[0]); mmah(hacc[mf][3], ah[mf], &bl1[2]);
            }
        }
        __syncthreads();
    }
    CP_WAIT0();
    __syncthreads();

    // stage fp32 gate tile (with corrections merged) in smem
    float* cst = (float*)dsm;   // [128][132]
#pragma unroll
    for (int mf = 0; mf < 4; mf++) {
#pragma unroll
        for (int nf = 0; nf < 4; nf++) {
            int row = wm * 64 + mf * 16 + (lane >> 2);
            int col = wn * 32 + nf * 8 + (lane & 3) * 2;
            float* d = acc[mf][nf];
            hmerge(d, hacc[mf][nf]);
            *(float2*)&cst[row * 132 + col]       = make_float2(d[0], d[1]);
            *(float2*)&cst[(row + 8) * 132 + col] = make_float2(d[2], d[3]);
        }
    }
    __syncthreads();

    // pass 1: gates -> c, h (h kept in regs); row-major coalesced writes
    float hv16[16];
    int q  = tid & 31;
    int rb = tid >> 5;
    int j  = (n0 >> 2) + q;
    __half* hrho = g_hrh[hout];
    __half* hrlo = g_hrl[hout];
#pragma unroll
    for (int i = 0; i < 16; i++) {
        int r = rb + i * 8;
        int rr = m0 + r;
        float4 pv = *(float4*)&cst[r * 132 + q * 4];
        float4 ge = *(const float4*)&g_Ges[(size_t)rr * 512 + j * 4];
        float iv = sigm(pv.x + ge.x), fv = sigm(pv.y + ge.y);
        float gv = ftanh(pv.z + ge.z), ov = sigm(pv.w + ge.w);
        size_t cidx = (size_t)rr * 128 + j;
        float cc = fv * g_c[cidx] + iv * gv;
        g_c[cidx] = cc;
        float hv = ov * ftanh(cc);
        hv16[i] = hv;
        __half hh, ll;
        hsplit(hv, hh, ll);
        hrho[cidx] = hh;
        hrlo[cidx] = ll;
    }
    __syncthreads();   // cst dead

    // pass 2: smem transpose (32 features x 128 rows)
    __half* trh = (__half*)dsm;            // [32][136]
    __half* trl = (__half*)(dsm + 8704);
#pragma unroll
    for (int i = 0; i < 16; i++) {
        int r = rb + i * 8;
        __half hh, ll;
        hsplit(hv16[i], hh, ll);
        trh[q * 136 + r] = hh;
        trl[q * 136 + r] = ll;
    }
    __syncthreads();

    // pass 3: coalesced hT writes
    __half* hTh = g_hTh[hout];
    __half* hTl = g_hTl[hout];
    int bb = m0 >> 9, nn0 = m0 & 511;
    int jr = tid >> 4, ch = tid & 15;
#pragma unroll
    for (int half = 0; half < 2; half++) {
        int jj = jr + half * 16;
        uint4 vh = *(uint4*)&trh[jj * 136 + ch * 8];
        uint4 vl = *(uint4*)&trl[jj * 136 + ch * 8];
        size_t base = (size_t)(bb * 128 + (n0 >> 2) + jj) * 512 + nn0 + ch * 8;
        *(uint4*)&hTh[base] = vh;
        *(uint4*)&hTl[base] = vl;
    }
    __syncthreads();
}

// ---------------------------------------------------------------------------
// phase out (tensor-core): Xi += h @ Wout + bout ; emit out[:, :, t, :]
// ---------------------------------------------------------------------------
__device__ __forceinline__ void phase_out(char* dsm, int t, int hidx,
                                          const float* __restrict__ bout,
                                          float* __restrict__ out, int cta, int tid) {
    uint32_t sbase = smem_u32(dsm);
    int wid = tid >> 5, lane = tid & 31;
    int mw = wid & 1, nw = wid >> 1;
    int row0 = cta * 32;
    __syncthreads();

    {
        const __half* hh = g_hrh[hidx] + (size_t)row0 * 128;
        const __half* hl = g_hrl[hidx] + (size_t)row0 * 128;
#pragma unroll
        for (int i = 0; i < 2; i++) {
            int idx = tid + i * 256, r = idx >> 4, c = idx & 15;
            cpa16(sbase + OUT_HA  + r * OUT_RSB + c * 16, hh + (size_t)r * 128 + c * 8);
            cpa16(sbase + OUT_HAL + r * OUT_RSB + c * 16, hl + (size_t)r * 128 + c * 8);
        }
#pragma unroll
        for (int i = 0; i < 4; i++) {
            int idx = tid + i * 256, r = idx >> 4, c = idx & 15;
            cpa16(sbase + OUT_WB  + r * OUT_RSB + c * 16, g_WoTh + (size_t)r * 128 + c * 8);
            cpa16(sbase + OUT_WBL + r * OUT_RSB + c * 16, g_WoTl + (size_t)r * 128 + c * 8);
        }
        CP_COMMIT();
    }

    int rA = row0 + mw * 16 + (lane >> 2);
    int cA = nw * 16 + (lane & 3) * 2;
    float2 xi[2][2], bo[2];
#pragma unroll
    for (int nf = 0; nf < 2; nf++) {
        int col = cA + nf * 8;
        xi[nf][0] = *(const float2*)&g_Xi[rA * 64 + col];
        xi[nf][1] = *(const float2*)&g_Xi[(rA + 8) * 64 + col];
        bo[nf] = *(const float2*)&bout[col];
    }

    CP_WAIT0();
    __syncthreads();

    uint32_t aH = sbase + OUT_HA + (uint32_t)(mw * 16 + (lane & 15)) * OUT_RSB + ((lane >> 4) * 16);
    uint32_t aL = aH + (OUT_HAL - OUT_HA);
    uint32_t bH = sbase + OUT_WB
                + (uint32_t)(nw * 16 + (lane & 7) + ((lane >> 4) & 1) * 8) * OUT_RSB
                + (((lane >> 3) & 1) * 16);
    uint32_t bL = bH + (OUT_WBL - OUT_WB);

    float acc[2][4] = {};
    uint32_t hacc[2][2] = {};
#pragma unroll
    for (int ks = 0; ks < 8; ks++) {
        uint32_t ah[4], al[4], bh[4], bl[4];
        ldsm4(ah, aH + ks * 32);
        ldsm4(al, aL + ks * 32);
        ldsm4(bh, bH + ks * 32);
        ldsm4(bl, bL + ks * 32);
        mmaf(acc[0], ah, &bh[0]); mmaf(acc[1], ah, &bh[2]);
        mmah(hacc[0], al, &bh[0]); mmah(hacc[1], al, &bh[2]);
        mmah(hacc[0], ah, &bl[0]); mmah(hacc[1], ah, &bl[2]);
    }

#pragma unroll
    for (int nf = 0; nf < 2; nf++) {
        hmerge(acc[nf], hacc[nf]);
        int col = cA + nf * 8;
        float2 v0 = make_float2(acc[nf][0] + xi[nf][0].x + bo[nf].x,
                                acc[nf][1] + xi[nf][0].y + bo[nf].y);
        float2 v1 = make_float2(acc[nf][2] + xi[nf][1].x + bo[nf].x,
                                acc[nf][3] + xi[nf][1].y + bo[nf].y);
        *(float2*)&g_Xi[rA * 64 + col] = v0;
        *(float2*)&g_Xi[(rA + 8) * 64 + col] = v1;
        *(float2*)&out[(size_t)rA * 4096 + t * 64 + col] = v0;
        *(float2*)&out[(size_t)(rA + 8) * 4096 + t * 64 + col] = v1;
    }
    __syncthreads();
}

// ---------------------------------------------------------------------------
// k_main: persistent kernel, 63 steps, 2 grid barriers per step.
// ---------------------------------------------------------------------------
__global__ void __launch_bounds__(256) k_main(const float* __restrict__ bout,
                                              float* __restrict__ out) {
    extern __shared__ __align__(16) char dsm[];
    int cta = blockIdx.x, tid = threadIdx.x;

    // persistent weight slice for this CTA's gG n-tile
    {
        int n0 = (cta & 3) * 128;
        uint32_t wt = smem_u32(dsm) + SM_WT;
#pragma unroll
        for (int i = 0; i < 16; i++) {
            int idx = tid + i * 256;
            int r = idx >> 5, c = idx & 31;
            cpa16(wt + r * WT_RSB + c * 16,         g_WTh + (size_t)(n0 + r) * 256 + c * 8);
            cpa16(wt + WT_SZ + r * WT_RSB + c * 16, g_WTl + (size_t)(n0 + r) * 256 + c * 8);
        }
        CP_COMMIT();
        CP_WAIT0();
    }
    __syncthreads();

    unsigned gen = 0;
#pragma unroll 1
    for (int t = 1; t < Tc; t++) {
        int hin = (t - 1) & 1, hout = t & 1;
        phase_gH(dsm, hin, cta, tid);
        if (t >= 2) phase_out(dsm, t - 1, hin, bout, out, cta, tid);
        gbar(++gen);
        phase_gG(dsm, hin, hout, cta, tid);
        gbar(++gen);
    }
    phase_out(dsm, Tc - 1, (Tc - 1) & 1, bout, out, cta, tid);
}

// ---------------------------------------------------------------------------
extern "C" void kernel_launch(void* const* d_in, const int* in_sizes, int n_in,
                              void* d_out, int out_size) {
    const float* X    = (const float*)d_in[0];
    const float* A    = (const float*)d_in[1];
    const float* Wse  = (const float*)d_in[2];
    const float* bse  = (const float*)d_in[3];
    const float* Wpe  = (const float*)d_in[4];
    const float* bpe  = (const float*)d_in[5];
    const float* Wii  = (const float*)d_in[6];
    const float* bii  = (const float*)d_in[7];
    const float* Whi  = (const float*)d_in[8];
    const float* bhi  = (const float*)d_in[9];
    const float* Wif  = (const float*)d_in[10];
    const float* bif_ = (const float*)d_in[11];
    const float* Whf  = (const float*)d_in[12];
    const float* bhf  = (const float*)d_in[13];
    const float* Wig  = (const float*)d_in[14];
    const float* big_ = (const float*)d_in[15];
    const float* Whg  = (const float*)d_in[16];
    const float* bhg  = (const float*)d_in[17];
    const float* Wio  = (const float*)d_in[18];
    const float* bio  = (const float*)d_in[19];
    const float* Who  = (const float*)d_in[20];
    const float* bho  = (const float*)d_in[21];
    const float* Wout = (const float*)d_in[22];
    const float* bout = (const float*)d_in[23];
    float* out = (float*)d_out;

    cudaFuncSetAttribute(k_main, cudaFuncAttributeMaxDynamicSharedMemorySize, SM_TOTAL);

    k_dinv<<<Rc, 128>>>(A);
    k_an<<<2048, 256>>>(A);
    k_prep<<<512, 128>>>(Wii, bii, Whi, bhi, Wif, bif_, Whf, bhf,
                         Wig, big_, Whg, bhg, Wio, bio, Who, bho, Wpe, bpe);
    k_init<<<Rc, 128>>>(X, Wse, bse, Wout, out);
    k_ges<<<256, 256>>>();
    k_main<<<NCTA, 256, SM_TOTAL>>>(bout, out);
}

// round 9
// speedup vs baseline: 1.0291x; 1.0291x over previous
#include <cuda_runtime.h>
#include <cuda_fp16.h>
#include <math.h>
#include <stdint.h>

// Problem constants
#define Bc   8
#define Nc   512
#define Tc   64
#define NINc 64
#define NHc  128
#define Rc   (Bc * Nc)   // 4096 rows
#define NCTA 128

// ---------------- scratch (device globals) ----------------------------------
__device__ float g_dinv[Rc];
__device__ __half g_Anh[Bc * Nc * Nc];          // An hi (4 MB)
__device__ __half g_Anl[Bc * Nc * Nc];          // An lo
__device__ float g_es[Rc * NHc];                // static embedding fp32
__device__ float g_Wes[128 * 512];              // Wi[0:128] interleaved fp32
__device__ float g_bbig[512];
__device__ float g_Ges[Rc * 512];               // es @ Wes + bbig (fp32, interleaved)
__device__ __half g_WTh[512 * 256];             // Wcomb^T hi: [n][k]
__device__ __half g_WTl[512 * 256];
__device__ __half g_WoTh[64 * 128];             // Wout^T hi: [n][k]
__device__ __half g_WoTl[64 * 128];
__device__ __half g_Hh[Rc * NHc];               // H = An@h, hi/lo, row-major
__device__ __half g_Hl[Rc * NHc];
__device__ __half g_hrh[2][Rc * NHc];           // h row-major hi/lo (double buffered)
__device__ __half g_hrl[2][Rc * NHc];
__device__ __half g_hTh[2][Bc * NHc * Nc];      // h transposed per batch [b][j][n]
__device__ __half g_hTl[2][Bc * NHc * Nc];
__device__ float g_c[Rc * NHc];                 // cell state
__device__ float g_Xi[Rc * NINc];               // running output accumulator
__device__ unsigned g_count;                    // grid barrier arrive counter
__device__ unsigned g_sense;                    // grid barrier generation

// ---------------- helpers ----------------------------------------------------
__device__ __forceinline__ uint32_t smem_u32(const void* p) {
    uint32_t a;
    asm("{ .reg .u64 t; cvta.to.shared.u64 t, %1; cvt.u32.u64 %0, t; }" : "=r"(a) : "l"(p));
    return a;
}
// fast sigmoid / tanh via MUFU paths
__device__ __forceinline__ float sigm(float x) {
    return __fdividef(1.f, 1.f + __expf(-x));
}
__device__ __forceinline__ float ftanh(float x) {
    float e = __expf(2.f * x);
    return 1.f - __fdividef(2.f, e + 1.f);
}
__device__ __forceinline__ void hsplit(float v, __half& hi, __half& lo) {
    hi = __float2half_rn(v);
    lo = __float2half_rn(v - __half2float(hi));
}
__device__ __forceinline__ void cpa16(uint32_t dst, const void* src) {
    asm volatile("cp.async.cg.shared.global [%0], [%1], 16;" :: "r"(dst), "l"(src) : "memory");
}
#define CP_COMMIT() asm volatile("cp.async.commit_group;" ::: "memory")
#define CP_WAIT1()  asm volatile("cp.async.wait_group 1;" ::: "memory")
#define CP_WAIT0()  asm volatile("cp.async.wait_group 0;" ::: "memory")

__device__ __forceinline__ void ldsm4(uint32_t* r, uint32_t a) {
    asm volatile("ldmatrix.sync.aligned.m8n8.x4.shared.b16 {%0,%1,%2,%3}, [%4];"
        : "=r"(r[0]), "=r"(r[1]), "=r"(r[2]), "=r"(r[3]) : "r"(a));
}
// main pass: fp16 operands, fp32 accumulator
__device__ __forceinline__ void mmaf(float* d, const uint32_t* a, const uint32_t* b) {
    asm volatile("mma.sync.aligned.m16n8k16.row.col.f32.f16.f16.f32 "
        "{%0,%1,%2,%3}, {%4,%5,%6,%7}, {%8,%9}, {%0,%1,%2,%3};"
        : "+f"(d[0]), "+f"(d[1]), "+f"(d[2]), "+f"(d[3])
        : "r"(a[0]), "r"(a[1]), "r"(a[2]), "r"(a[3]), "r"(b[0]), "r"(b[1]));
}
// correction pass: fp16 accumulator
__device__ __forceinline__ void mmah(uint32_t* d, const uint32_t* a, const uint32_t* b) {
    asm volatile("mma.sync.aligned.m16n8k16.row.col.f16.f16.f16.f16 "
        "{%0,%1}, {%2,%3,%4,%5}, {%6,%7}, {%0,%1};"
        : "+r"(d[0]), "+r"(d[1])
        : "r"(a[0]), "r"(a[1]), "r"(a[2]), "r"(a[3]), "r"(b[0]), "r"(b[1]));
}
__device__ __forceinline__ void hmerge(float* d, const uint32_t* h) {
    __half2 q0 = *(const __half2*)&h[0];
    __half2 q1 = *(const __half2*)&h[1];
    d[0] += __half2float(q0.x); d[1] += __half2float(q0.y);
    d[2] += __half2float(q1.x); d[3] += __half2float(q1.y);
}

// grid-wide sense barrier, split into arrive / wait halves
__device__ __forceinline__ void gbar_arrive(unsigned gen) {
    __syncthreads();
    if (threadIdx.x == 0) {
        unsigned prev;
        asm volatile("atom.release.gpu.add.u32 %0, [%1], %2;"
                     : "=r"(prev) : "l"(&g_count), "r"(1u) : "memory");
        if (prev == NCTA - 1) {
            g_count = 0u;
            asm volatile("st.release.gpu.u32 [%0], %1;" :: "l"(&g_sense), "r"(gen) : "memory");
        }
    }
}
__device__ __forceinline__ void gbar_wait(unsigned gen) {
    if (threadIdx.x == 0) {
        unsigned s;
        do {
            asm volatile("ld.acquire.gpu.u32 %0, [%1];" : "=r"(s) : "l"(&g_sense) : "memory");
        } while (s < gen);
    }
    __syncthreads();
}
__device__ __forceinline__ void gbar(unsigned gen) {
    gbar_arrive(gen);
    gbar_wait(gen);
}

#define RS 144        // stage tile row stride (72 halves)
#define GH_T   9216   // gH tile: 64 rows x RS
#define GG_T   18432  // gG tile: 128 rows x RS
#define STG_SZ 36864  // stage size (both phases)
#define SM_WT    73728
#define WT_RSB   528
#define WT_SZ    67584
#define SM_TOTAL (SM_WT + 2 * WT_SZ)   // 208896
// out-phase stage offsets (within [0,73728))
#define OUT_RSB  272
#define OUT_HA   0
#define OUT_HAL  8704
#define OUT_WB   17408
#define OUT_WBL  34816

// ---------------------------------------------------------------------------
__global__ void k_dinv(const float* __restrict__ A) {
    int row = blockIdx.x;
    const float* arow = A + (size_t)row * Nc;
    float s = 0.f;
    for (int j = threadIdx.x; j < Nc; j += blockDim.x) s += arow[j];
    __shared__ float sh[128];
    sh[threadIdx.x] = s;
    __syncthreads();
    for (int off = 64; off > 0; off >>= 1) {
        if (threadIdx.x < off) sh[threadIdx.x] += sh[threadIdx.x + off];
        __syncthreads();
    }
    if (threadIdx.x == 0) {
        float d = sh[0];
        g_dinv[row] = (d > 0.f) ? rsqrtf(d) : 0.f;
    }
}

__global__ void k_an(const float* __restrict__ A) {
    int idx = blockIdx.x * blockDim.x + threadIdx.x;
    int e = idx * 4;
    int b   = e >> 18;
    int rem = e & 262143;
    int i   = rem >> 9;
    int j   = rem & 511;
    float4 a = *(const float4*)(A + (size_t)e);
    float di = g_dinv[b * 512 + i];
    const float* dj = g_dinv + b * 512 + j;
    float v[4] = { a.x * di * dj[0], a.y * di * dj[1], a.z * di * dj[2], a.w * di * dj[3] };
    __half h[4], l[4];
#pragma unroll
    for (int q = 0; q < 4; q++) hsplit(v[q], h[q], l[q]);
    __half2* ph = (__half2*)(g_Anh + (size_t)e);
    __half2* pl = (__half2*)(g_Anl + (size_t)e);
    ph[0] = __halves2half2(h[0], h[1]); ph[1] = __halves2half2(h[2], h[3]);
    pl[0] = __halves2half2(l[0], l[1]); pl[1] = __halves2half2(l[2], l[3]);
}

// ---------------------------------------------------------------------------
__global__ void k_prep(const float* __restrict__ Wii, const float* __restrict__ bii,
                       const float* __restrict__ Whi, const float* __restrict__ bhi,
                       const float* __restrict__ Wif, const float* __restrict__ bif_,
                       const float* __restrict__ Whf, const float* __restrict__ bhf,
                       const float* __restrict__ Wig, const float* __restrict__ big_,
                       const float* __restrict__ Whg, const float* __restrict__ bhg,
                       const float* __restrict__ Wio, const float* __restrict__ bio,
                       const float* __restrict__ Who, const float* __restrict__ bho,
                       const float* __restrict__ Wpe, const float* __restrict__ bpe) {
    int n = blockIdx.x;
    int g = n & 3;
    int j = n >> 2;
    int t = threadIdx.x;
    const float* Wi = (g == 0) ? Wii : (g == 1) ? Wif : (g == 2) ? Wig : Wio;
    const float* Wh = (g == 0) ? Whi : (g == 1) ? Whf : (g == 2) ? Whg : Who;
    const float* bi = (g == 0) ? bii : (g == 1) ? bif_ : (g == 2) ? big_ : bio;
    const float* bh = (g == 0) ? bhi : (g == 1) ? bhf : (g == 2) ? bhg : bho;

    __shared__ float wcol[128];
    wcol[t] = Wi[(128 + t) * 128 + j];
    __syncthreads();

    g_Wes[t * 512 + n] = Wi[t * 128 + j];

    float acc = 0.f;
    const float* wpet = Wpe + t * 128;
#pragma unroll 8
    for (int m = 0; m < 128; m++) acc += wpet[m] * wcol[m];

    __half hh, ll;
    hsplit(acc, hh, ll);
    g_WTh[n * 256 + t] = hh;
    g_WTl[n * 256 + t] = ll;
    float whv = Wh[t * 128 + j];
    hsplit(whv, hh, ll);
    g_WTh[n * 256 + 128 + t] = hh;
    g_WTl[n * 256 + 128 + t] = ll;

    if (t == 0) {
        float ba = bi[j] + bh[j];
        for (int m = 0; m < 128; m++) ba += bpe[m] * wcol[m];
        g_bbig[n] = ba;
    }
}

// ---------------------------------------------------------------------------
// k_init: es = X0@Wse + bse ; zero h & c ; Xi = X0 ; out t=0 ; barrier reset ;
//         WoutT hi/lo
// ---------------------------------------------------------------------------
__global__ void k_init(const float* __restrict__ X, const float* __restrict__ Wse,
                       const float* __restrict__ bse, const float* __restrict__ Wout,
                       float* __restrict__ out) {
    int row = blockIdx.x;
    int t = threadIdx.x;
    if (row == 0 && t == 0) { g_count = 0u; g_sense = 0u; }
    if (row < 64) {
        __half hh, ll;
        hsplit(Wout[t * 64 + row], hh, ll);
        g_WoTh[row * 128 + t] = hh;
        g_WoTl[row * 128 + t] = ll;
    }
    __shared__ float x0[64];
    if (t < 64) {
        float v = X[(size_t)row * 4096 + t];
        x0[t] = v;
        g_Xi[row * 64 + t] = v;
        out[(size_t)row * 4096 + t] = v;
    }
    __syncthreads();
    float acc = bse[t];
#pragma unroll 8
    for (int k = 0; k < 64; k++) acc += x0[k] * Wse[k * 128 + t];
    g_es[row * 128 + t] = acc;

    __half z = __float2half(0.f);
    g_hrh[0][(size_t)row * 128 + t] = z;
    g_hrl[0][(size_t)row * 128 + t] = z;
    int bb = row >> 9, nn = row & 511;
    g_hTh[0][(size_t)(bb * 128 + t) * 512 + nn] = z;
    g_hTl[0][(size_t)(bb * 128 + t) * 512 + nn] = z;
    g_c[row * 128 + t] = 0.f;
}

// ---------------------------------------------------------------------------
// k_ges: Ges = es @ Wes + bbig (4096 x 512, K=128) fp32, runs once
// ---------------------------------------------------------------------------
__global__ void __launch_bounds__(256) k_ges() {
    int m0 = (blockIdx.x >> 2) * 64;
    int n0 = (blockIdx.x & 3) * 128;

    __shared__ __align__(16) float As[16][68];
    __shared__ __align__(16) float Bs[16][132];

    int tid = threadIdx.x;
    int ty = tid >> 4, tx = tid & 15;
    int ar = tid >> 2, ac = (tid & 3) * 4;
    int br = tid >> 5, bc = (tid & 31) * 4;

    float acc[4][8] = {};

    for (int k0 = 0; k0 < 128; k0 += 16) {
        float4 av = *(const float4*)&g_es[(size_t)(m0 + ar) * 128 + k0 + ac];
        float4 bv0 = *(const float4*)&g_Wes[(size_t)(k0 + br) * 512 + n0 + bc];
        float4 bv1 = *(const float4*)&g_Wes[(size_t)(k0 + br + 8) * 512 + n0 + bc];
        As[ac + 0][ar] = av.x; As[ac + 1][ar] = av.y;
        As[ac + 2][ar] = av.z; As[ac + 3][ar] = av.w;
        *(float4*)&Bs[br][bc] = bv0;
        *(float4*)&Bs[br + 8][bc] = bv1;
        __syncthreads();
#pragma unroll
        for (int kk = 0; kk < 16; kk++) {
            float4 a4 = *(const float4*)&As[kk][ty * 4];
            float4 b0 = *(const float4*)&Bs[kk][tx * 8];
            float4 b1 = *(const float4*)&Bs[kk][tx * 8 + 4];
            float av4[4] = { a4.x, a4.y, a4.z, a4.w };
            float bv8[8] = { b0.x, b0.y, b0.z, b0.w, b1.x, b1.y, b1.z, b1.w };
#pragma unroll
            for (int i = 0; i < 4; i++)
#pragma unroll
                for (int jq = 0; jq < 8; jq++) acc[i][jq] += av4[i] * bv8[jq];
        }
        __syncthreads();
    }

    float bb[8];
#pragma unroll
    for (int q = 0; q < 8; q++) bb[q] = g_bbig[n0 + tx * 8 + q];
#pragma unroll
    for (int r = 0; r < 4; r++) {
        int rr = m0 + ty * 4 + r;
        float* dst = &g_Ges[(size_t)rr * 512 + n0 + tx * 8];
#pragma unroll
        for (int q = 0; q < 8; q++) dst[q] = acc[r][q] + bb[q];
    }
}

// ---------------------------------------------------------------------------
// phase gH: H = An @ h, CTA tile 64x64 (8b x 8m x 2n = 128 tiles)
// ---------------------------------------------------------------------------
__device__ __forceinline__ void phase_gH(char* dsm, int hin, int cta, int tid) {
    uint32_t sbase = smem_u32(dsm);
    int wid = tid >> 5, lane = tid & 31;
    int wm = wid >> 2, wn = wid & 3;
    int b  = cta >> 4;
    int m0 = ((cta >> 1) & 7) * 64;
    int n0 = (cta & 1) * 64;

    float acc[2][2][4];
    uint32_t hacc[2][2][2];
#pragma unroll
    for (int i = 0; i < 2; i++)
#pragma unroll
        for (int j = 0; j < 2; j++) {
#pragma unroll
            for (int q = 0; q < 4; q++) acc[i][j][q] = 0.f;
            hacc[i][j][0] = 0u; hacc[i][j][1] = 0u;
        }

    const __half* Ah0 = g_Anh + (size_t)b * 262144 + (size_t)m0 * 512;
    const __half* Al0 = g_Anl + (size_t)b * 262144 + (size_t)m0 * 512;
    const __half* Bh0 = g_hTh[hin] + (size_t)b * 65536 + (size_t)n0 * 512;
    const __half* Bl0 = g_hTl[hin] + (size_t)b * 65536 + (size_t)n0 * 512;

    auto issue = [&](int cc, uint32_t buf) {
        int kc = cc * 64;
#pragma unroll
        for (int i = 0; i < 2; i++) {
            int idx = tid + i * 256, r = idx >> 3, c = idx & 7;
            uint32_t d = buf + r * RS + c * 16;
            size_t off = (size_t)r * 512 + kc + c * 8;
            cpa16(d,            Ah0 + off);
            cpa16(d + GH_T,     Al0 + off);
            cpa16(d + 2 * GH_T, Bh0 + off);
            cpa16(d + 3 * GH_T, Bl0 + off);
        }
    };

    issue(0, sbase);
    CP_COMMIT();

#pragma unroll 1
    for (int cc = 0; cc < 8; cc++) {
        if (cc + 1 < 8) issue(cc + 1, sbase + ((cc + 1) & 1) * STG_SZ);
        CP_COMMIT();
        CP_WAIT1();
        __syncthreads();

        uint32_t buf = sbase + (cc & 1) * STG_SZ;
        uint32_t aH = buf + (uint32_t)(wm * 32 + (lane & 15)) * RS + ((lane >> 4) * 16);
        uint32_t aL = aH + GH_T;
        uint32_t bH = buf + 2 * GH_T
                    + (uint32_t)(wn * 16 + (lane & 7) + ((lane >> 4) & 1) * 8) * RS
                    + (((lane >> 3) & 1) * 16);
        uint32_t bL = bH + GH_T;
#pragma unroll
        for (int ks = 0; ks < 4; ks++) {
            uint32_t ah[2][4], al[2][4], bh[4], bl[4];
            ldsm4(ah[0], aH + ks * 32); ldsm4(ah[1], aH + 16 * RS + ks * 32);
            ldsm4(al[0], aL + ks * 32); ldsm4(al[1], aL + 16 * RS + ks * 32);
            ldsm4(bh, bH + ks * 32);
            ldsm4(bl, bL + ks * 32);
#pragma unroll
            for (int mf = 0; mf < 2; mf++) {
                mmaf(acc[mf][0], ah[mf], &bh[0]); mmaf(acc[mf][1], ah[mf], &bh[2]);
                mmah(hacc[mf][0], al[mf], &bh[0]); mmah(hacc[mf][1], al[mf], &bh[2]);
                mmah(hacc[mf][0], ah[mf], &bl[0]); mmah(hacc[mf][1], ah[mf], &bl[2]);
            }
        }
        __syncthreads();
    }
    CP_WAIT0();

    int rbase = b * 512 + m0 + wm * 32 + (lane >> 2);
    int cbase = n0 + wn * 16 + (lane & 3) * 2;
#pragma unroll
    for (int mf = 0; mf < 2; mf++) {
#pragma unroll
        for (int nf = 0; nf < 2; nf++) {
            int col = cbase + nf * 8;
            float* d = acc[mf][nf];
            hmerge(d, hacc[mf][nf]);
            __half h0, l0, h1, l1;
            int r0 = rbase + mf * 16;
            hsplit(d[0], h0, l0); hsplit(d[1], h1, l1);
            *(__half2*)(g_Hh + (size_t)r0 * 128 + col) = __halves2half2(h0, h1);
            *(__half2*)(g_Hl + (size_t)r0 * 128 + col) = __halves2half2(l0, l1);
            hsplit(d[2], h0, l0); hsplit(d[3], h1, l1);
            *(__half2*)(g_Hh + (size_t)(r0 + 8) * 128 + col) = __halves2half2(h0, h1);
            *(__half2*)(g_Hl + (size_t)(r0 + 8) * 128 + col) = __halves2half2(l0, l1);
        }
    }
}

// ---------------------------------------------------------------------------
// phase gG (barrier-overlapped): gates = Ges + [H | h] @ Wcomb, 128x128 tiles.
// Part 1 (before bar wait): chunks 2,3 = h(t-1)-part (K 128..255).
// Part 2 (after bar wait):  chunks 0,1 = H(t)-part (K 0..127) + epilogue.
// B persistent in smem.
// ---------------------------------------------------------------------------
__device__ __forceinline__ void phase_gG(char* dsm, int hin, int hout, int cta, int tid,
                                         unsigned wait_gen) {
    uint32_t sbase = smem_u32(dsm);
    int wid = tid >> 5, lane = tid & 31;
    int wm = wid >> 2, wn = wid & 3;
    int m0 = (cta >> 2) * 128;
    int n0 = (cta & 3) * 128;

    float acc[4][4][4];
    uint32_t hacc[4][4][2];
#pragma unroll
    for (int i = 0; i < 4; i++)
#pragma unroll
        for (int j = 0; j < 4; j++) {
#pragma unroll
            for (int q = 0; q < 4; q++) acc[i][j][q] = 0.f;
            hacc[i][j][0] = 0u; hacc[i][j][1] = 0u;
        }

    auto issue = [&](int cc, uint32_t buf) {
        int kc = cc * 64;
        const __half* Ahs;
        const __half* Als;
        if (kc < 128) {
            Ahs = g_Hh + (size_t)m0 * 128 + kc;
            Als = g_Hl + (size_t)m0 * 128 + kc;
        } else {
            Ahs = g_hrh[hin] + (size_t)m0 * 128 + (kc - 128);
            Als = g_hrl[hin] + (size_t)m0 * 128 + (kc - 128);
        }
#pragma unroll
        for (int i = 0; i < 4; i++) {
            int idx = tid + i * 256, r = idx >> 3, c = idx & 7;
            uint32_t d = buf + r * RS + c * 16;
            size_t off = (size_t)r * 128 + c * 8;
            cpa16(d,        Ahs + off);
            cpa16(d + GG_T, Als + off);
        }
    };

    uint32_t wtH = sbase + SM_WT
                 + (uint32_t)(wn * 32 + (lane & 7) + ((lane >> 4) & 1) * 8) * WT_RSB
                 + (((lane >> 3) & 1) * 16);
    uint32_t wtL = wtH + WT_SZ;

    auto compute = [&](int cc, uint32_t buf) {
        uint32_t aH = buf + (uint32_t)(wm * 64 + (lane & 15)) * RS + ((lane >> 4) * 16);
        uint32_t aL = aH + GG_T;
        uint32_t kb = (uint32_t)cc * 128;
#pragma unroll
        for (int ks = 0; ks < 4; ks++) {
            uint32_t ah[4][4], al[4][4], bh0[4], bh1[4], bl0[4], bl1[4];
#pragma unroll
            for (int mf = 0; mf < 4; mf++) {
                ldsm4(ah[mf], aH + mf * 16 * RS + ks * 32);
                ldsm4(al[mf], aL + mf * 16 * RS + ks * 32);
            }
            ldsm4(bh0, wtH + kb + ks * 32);
            ldsm4(bh1, wtH + 16 * WT_RSB + kb + ks * 32);
            ldsm4(bl0, wtL + kb + ks * 32);
            ldsm4(bl1, wtL + 16 * WT_RSB + kb + ks * 32);
#pragma unroll
            for (int mf = 0; mf < 4; mf++) {
                mmaf(acc[mf][0], ah[mf], &bh0[0]); mmaf(acc[mf][1], ah[mf], &bh0[2]);
                mmaf(acc[mf][2], ah[mf], &bh1[0]); mmaf(acc[mf][3], ah[mf], &bh1[2]);
                mmah(hacc[mf][0], al[mf], &bh0[0]); mmah(hacc[mf][1], al[mf], &bh0[2]);
                mmah(hacc[mf][2], al[mf], &bh1[0]); mmah(hacc[mf][3], al[mf], &bh1[2]);
                mmah(hacc[mf][0], ah[mf], &bl0[0]); mmah(hacc[mf][1], ah[mf], &bl0[2]);
                mmah(hacc[mf][2], ah[mf], &bl1[0]); mmah(hacc[mf][3], ah[mf], &bl1[2]);
            }
        }
    };

    // ---- part 1: h-part chunks (2,3) — no dependence on this step's H
    issue(2, sbase);            CP_COMMIT();
    issue(3, sbase + STG_SZ);   CP_COMMIT();
    CP_WAIT1();
    __syncthreads();
    compute(2, sbase);
    CP_WAIT0();
    __syncthreads();
    compute(3, sbase + STG_SZ);

    // ---- barrier wait: H(t) now complete grid-wide (also fences stage reuse)
    gbar_wait(wait_gen);

    // ---- part 2: H-part chunks (0,1)
    issue(0, sbase);            CP_COMMIT();
    issue(1, sbase + STG_SZ);   CP_COMMIT();
    CP_WAIT1();
    __syncthreads();
    compute(0, sbase);
    CP_WAIT0();
    __syncthreads();
    compute(1, sbase + STG_SZ);
    __syncthreads();   // all warps done reading stages before cst overwrite

    // stage fp32 gate tile (with corrections merged) in smem
    float* cst = (float*)dsm;   // [128][132]
#pragma unroll
    for (int mf = 0; mf < 4; mf++) {
#pragma unroll
        for (int nf = 0; nf < 4; nf++) {
            int row = wm * 64 + mf * 16 + (lane >> 2);
            int col = wn * 32 + nf * 8 + (lane & 3) * 2;
            float* d = acc[mf][nf];
            hmerge(d, hacc[mf][nf]);
            *(float2*)&cst[row * 132 + col]       = make_float2(d[0], d[1]);
            *(float2*)&cst[(row + 8) * 132 + col] = make_float2(d[2], d[3]);
        }
    }
    __syncthreads();

    // pass 1: gates -> c, h (h in regs)
    float hv16[16];
    int q  = tid & 31;
    int rb = tid >> 5;
    int j  = (n0 >> 2) + q;
    __half* hrho = g_hrh[hout];
    __half* hrlo = g_hrl[hout];
#pragma unroll
    for (int i = 0; i < 16; i++) {
        int r = rb + i * 8;
        int rr = m0 + r;
        float4 pv = *(float4*)&cst[r * 132 + q * 4];
        float4 ge = *(const float4*)&g_Ges[(size_t)rr * 512 + j * 4];
        float iv = sigm(pv.x + ge.x), fv = sigm(pv.y + ge.y);
        float gv = ftanh(pv.z + ge.z), ov = sigm(pv.w + ge.w);
        size_t cidx = (size_t)rr * 128 + j;
        float cc = fv * g_c[cidx] + iv * gv;
        g_c[cidx] = cc;
        float hv = ov * ftanh(cc);
        hv16[i] = hv;
        __half hh, ll;
        hsplit(hv, hh, ll);
        hrho[cidx] = hh;
        hrlo[cidx] = ll;
    }
    __syncthreads();   // cst dead

    // pass 2: smem transpose (32 features x 128 rows)
    __half* trh = (__half*)dsm;            // [32][136]
    __half* trl = (__half*)(dsm + 8704);
#pragma unroll
    for (int i = 0; i < 16; i++) {
        int r = rb + i * 8;
        __half hh, ll;
        hsplit(hv16[i], hh, ll);
        trh[q * 136 + r] = hh;
        trl[q * 136 + r] = ll;
    }
    __syncthreads();

    // pass 3: coalesced hT writes
    __half* hTh = g_hTh[hout];
    __half* hTl = g_hTl[hout];
    int bb = m0 >> 9, nn0 = m0 & 511;
    int jr = tid >> 4, ch = tid & 15;
#pragma unroll
    for (int half = 0; half < 2; half++) {
        int jj = jr + half * 16;
        uint4 vh = *(uint4*)&trh[jj * 136 + ch * 8];
        uint4 vl = *(uint4*)&trl[jj * 136 + ch * 8];
        size_t base = (size_t)(bb * 128 + (n0 >> 2) + jj) * 512 + nn0 + ch * 8;
        *(uint4*)&hTh[base] = vh;
        *(uint4*)&hTl[base] = vl;
    }
    __syncthreads();
}

// ---------------------------------------------------------------------------
// phase out (tensor-core): Xi += h @ Wout + bout ; emit out[:, :, t, :]
// ---------------------------------------------------------------------------
__device__ __forceinline__ void phase_out(char* dsm, int t, int hidx,
                                          const float* __restrict__ bout,
                                          float* __restrict__ out, int cta, int tid) {
    uint32_t sbase = smem_u32(dsm);
    int wid = tid >> 5, lane = tid & 31;
    int mw = wid & 1, nw = wid >> 1;
    int row0 = cta * 32;
    __syncthreads();

    {
        const __half* hh = g_hrh[hidx] + (size_t)row0 * 128;
        const __half* hl = g_hrl[hidx] + (size_t)row0 * 128;
#pragma unroll
        for (int i = 0; i < 2; i++) {
            int idx = tid + i * 256, r = idx >> 4, c = idx & 15;
            cpa16(sbase + OUT_HA  + r * OUT_RSB + c * 16, hh + (size_t)r * 128 + c * 8);
            cpa16(sbase + OUT_HAL + r * OUT_RSB + c * 16, hl + (size_t)r * 128 + c * 8);
        }
#pragma unroll
        for (int i = 0; i < 4; i++) {
            int idx = tid + i * 256, r = idx >> 4, c = idx & 15;
            cpa16(sbase + OUT_WB  + r * OUT_RSB + c * 16, g_WoTh + (size_t)r * 128 + c * 8);
            cpa16(sbase + OUT_WBL + r * OUT_RSB + c * 16, g_WoTl + (size_t)r * 128 + c * 8);
        }
        CP_COMMIT();
    }

    int rA = row0 + mw * 16 + (lane >> 2);
    int cA = nw * 16 + (lane & 3) * 2;
    float2 xi[2][2], bo[2];
#pragma unroll
    for (int nf = 0; nf < 2; nf++) {
        int col = cA + nf * 8;
        xi[nf][0] = *(const float2*)&g_Xi[rA * 64 + col];
        xi[nf][1] = *(const float2*)&g_Xi[(rA + 8) * 64 + col];
        bo[nf] = *(const float2*)&bout[col];
    }

    CP_WAIT0();
    __syncthreads();

    uint32_t aH = sbase + OUT_HA + (uint32_t)(mw * 16 + (lane & 15)) * OUT_RSB + ((lane >> 4) * 16);
    uint32_t aL = aH + (OUT_HAL - OUT_HA);
    uint32_t bH = sbase + OUT_WB
                + (uint32_t)(nw * 16 + (lane & 7) + ((lane >> 4) & 1) * 8) * OUT_RSB
                + (((lane >> 3) & 1) * 16);
    uint32_t bL = bH + (OUT_WBL - OUT_WB);

    float acc[2][4] = {};
    uint32_t hacc[2][2] = {};
#pragma unroll
    for (int ks = 0; ks < 8; ks++) {
        uint32_t ah[4], al[4], bh[4], bl[4];
        ldsm4(ah, aH + ks * 32);
        ldsm4(al, aL + ks * 32);
        ldsm4(bh, bH + ks * 32);
        ldsm4(bl, bL + ks * 32);
        mmaf(acc[0], ah, &bh[0]); mmaf(acc[1], ah, &bh[2]);
        mmah(hacc[0], al, &bh[0]); mmah(hacc[1], al, &bh[2]);
        mmah(hacc[0], ah, &bl[0]); mmah(hacc[1], ah, &bl[2]);
    }

#pragma unroll
    for (int nf = 0; nf < 2; nf++) {
        hmerge(acc[nf], hacc[nf]);
        int col = cA + nf * 8;
        float2 v0 = make_float2(acc[nf][0] + xi[nf][0].x + bo[nf].x,
                                acc[nf][1] + xi[nf][0].y + bo[nf].y);
        float2 v1 = make_float2(acc[nf][2] + xi[nf][1].x + bo[nf].x,
                                acc[nf][3] + xi[nf][1].y + bo[nf].y);
        *(float2*)&g_Xi[rA * 64 + col] = v0;
        *(float2*)&g_Xi[(rA + 8) * 64 + col] = v1;
        *(float2*)&out[(size_t)rA * 4096 + t * 64 + col] = v0;
        *(float2*)&out[(size_t)(rA + 8) * 4096 + t * 64 + col] = v1;
    }
    __syncthreads();
}

// ---------------------------------------------------------------------------
// k_main: persistent kernel, 63 steps. Barrier 1 is split arrive/wait with
// gG's h-part computed in the gap; barrier 2 is a full barrier.
// ---------------------------------------------------------------------------
__global__ void __launch_bounds__(256) k_main(const float* __restrict__ bout,
                                              float* __restrict__ out) {
    extern __shared__ __align__(16) char dsm[];
    int cta = blockIdx.x, tid = threadIdx.x;

    // persistent weight slice for this CTA's gG n-tile
    {
        int n0 = (cta & 3) * 128;
        uint32_t wt = smem_u32(dsm) + SM_WT;
#pragma unroll
        for (int i = 0; i < 16; i++) {
            int idx = tid + i * 256;
            int r = idx >> 5, c = idx & 31;
            cpa16(wt + r * WT_RSB + c * 16,         g_WTh + (size_t)(n0 + r) * 256 + c * 8);
            cpa16(wt + WT_SZ + r * WT_RSB + c * 16, g_WTl + (size_t)(n0 + r) * 256 + c * 8);
        }
        CP_COMMIT();
        CP_WAIT0();
    }
    __syncthreads();

    unsigned gen = 0;
#pragma unroll 1
    for (int t = 1; t < Tc; t++) {
        int hin = (t - 1) & 1, hout = t & 1;
        phase_gH(dsm, hin, cta, tid);
        if (t >= 2) phase_out(dsm, t - 1, hin, bout, out, cta, tid);
        ++gen;
        gbar_arrive(gen);                            // bar1: H complete (this CTA)
        phase_gG(dsm, hin, hout, cta, tid, gen);     // h-part overlaps bar1 wait
        gbar(++gen);                                 // bar2: h(t) complete
    }
    phase_out(dsm, Tc - 1, (Tc - 1) & 1, bout, out, cta, tid);
}

// ---------------------------------------------------------------------------
extern "C" void kernel_launch(void* const* d_in, const int* in_sizes, int n_in,
                              void* d_out, int out_size) {
    const float* X    = (const float*)d_in[0];
    const float* A    = (const float*)d_in[1];
    const float* Wse  = (const float*)d_in[2];
    const float* bse  = (const float*)d_in[3];
    const float* Wpe  = (const float*)d_in[4];
    const float* bpe  = (const float*)d_in[5];
    const float* Wii  = (const float*)d_in[6];
    const float* bii  = (const float*)d_in[7];
    const float* Whi  = (const float*)d_in[8];
    const float* bhi  = (const float*)d_in[9];
    const float* Wif  = (const float*)d_in[10];
    const float* bif_ = (const float*)d_in[11];
    const float* Whf  = (const float*)d_in[12];
    const float* bhf  = (const float*)d_in[13];
    const float* Wig  = (const float*)d_in[14];
    const float* big_ = (const float*)d_in[15];
    const float* Whg  = (const float*)d_in[16];
    const float* bhg  = (const float*)d_in[17];
    const float* Wio  = (const float*)d_in[18];
    const float* bio  = (const float*)d_in[19];
    const float* Who  = (const float*)d_in[20];
    const float* bho  = (const float*)d_in[21];
    const float* Wout = (const float*)d_in[22];
    const float* bout = (const float*)d_in[23];
    float* out = (float*)d_out;

    cudaFuncSetAttribute(k_main, cudaFuncAttributeMaxDynamicSharedMemorySize, SM_TOTAL);

    k_dinv<<<Rc, 128>>>(A);
    k_an<<<2048, 256>>>(A);
    k_prep<<<512, 128>>>(Wii, bii, Whi, bhi, Wif, bif_, Whf, bhf,
                         Wig, big_, Whg, bhg, Wio, bio, Who, bho, Wpe, bpe);
    k_init<<<Rc, 128>>>(X, Wse, bse, Wout, out);
    k_ges<<<256, 256>>>();
    k_main<<<NCTA, 256, SM_TOTAL>>>(bout, out);
}

// round 10
// speedup vs baseline: 1.1088x; 1.0775x over previous
#include <cuda_runtime.h>
#include <cuda_fp16.h>
#include <math.h>
#include <stdint.h>

// Problem constants
#define Bc   8
#define Nc   512
#define Tc   64
#define NINc 64
#define NHc  128
#define Rc   (Bc * Nc)   // 4096 rows
#define NCTA 128

// ---------------- scratch (device globals) ----------------------------------
__device__ float g_dinv[Rc];
__device__ __half g_Anh[Bc * Nc * Nc];          // An fp16 (4 MB)
__device__ float g_es[Rc * NHc];                // static embedding fp32
__device__ float g_Wes[128 * 512];              // Wi[0:128] interleaved fp32
__device__ float g_bbig[512];
__device__ float g_Ges[Rc * 512];               // es @ Wes + bbig (fp32, interleaved)
__device__ __half g_WTh[512 * 256];             // Wcomb^T hi: [n][k]
__device__ __half g_WTl[512 * 256];
__device__ __half g_WoTh[64 * 128];             // Wout^T hi: [n][k]
__device__ __half g_WoTl[64 * 128];
__device__ __half g_Hh[Rc * NHc];               // H = An@h, hi/lo, row-major
__device__ __half g_Hl[Rc * NHc];
__device__ __half g_hrh[2][Rc * NHc];           // h row-major hi/lo (double buffered)
__device__ __half g_hrl[2][Rc * NHc];
__device__ __half g_hTh[2][Bc * NHc * Nc];      // h transposed per batch [b][j][n]
__device__ __half g_hTl[2][Bc * NHc * Nc];
__device__ float g_c[Rc * NHc];                 // cell state
__device__ float g_Xi[Rc * NINc];               // running output accumulator
__device__ unsigned g_count;                    // grid barrier arrive counter
__device__ unsigned g_sense;                    // grid barrier generation

// ---------------- helpers ----------------------------------------------------
__device__ __forceinline__ uint32_t smem_u32(const void* p) {
    uint32_t a;
    asm("{ .reg .u64 t; cvta.to.shared.u64 t, %1; cvt.u32.u64 %0, t; }" : "=r"(a) : "l"(p));
    return a;
}
// fast sigmoid / tanh via MUFU paths
__device__ __forceinline__ float sigm(float x) {
    return __fdividef(1.f, 1.f + __expf(-x));
}
__device__ __forceinline__ float ftanh(float x) {
    float e = __expf(2.f * x);
    return 1.f - __fdividef(2.f, e + 1.f);
}
__device__ __forceinline__ void hsplit(float v, __half& hi, __half& lo) {
    hi = __float2half_rn(v);
    lo = __float2half_rn(v - __half2float(hi));
}
__device__ __forceinline__ void cpa16(uint32_t dst, const void* src) {
    asm volatile("cp.async.cg.shared.global [%0], [%1], 16;" :: "r"(dst), "l"(src) : "memory");
}
#define CP_COMMIT() asm volatile("cp.async.commit_group;" ::: "memory")
#define CP_WAIT1()  asm volatile("cp.async.wait_group 1;" ::: "memory")
#define CP_WAIT0()  asm volatile("cp.async.wait_group 0;" ::: "memory")

__device__ __forceinline__ void ldsm4(uint32_t* r, uint32_t a) {
    asm volatile("ldmatrix.sync.aligned.m8n8.x4.shared.b16 {%0,%1,%2,%3}, [%4];"
        : "=r"(r[0]), "=r"(r[1]), "=r"(r[2]), "=r"(r[3]) : "r"(a));
}
// main pass: fp16 operands, fp32 accumulator
__device__ __forceinline__ void mmaf(float* d, const uint32_t* a, const uint32_t* b) {
    asm volatile("mma.sync.aligned.m16n8k16.row.col.f32.f16.f16.f32 "
        "{%0,%1,%2,%3}, {%4,%5,%6,%7}, {%8,%9}, {%0,%1,%2,%3};"
        : "+f"(d[0]), "+f"(d[1]), "+f"(d[2]), "+f"(d[3])
        : "r"(a[0]), "r"(a[1]), "r"(a[2]), "r"(a[3]), "r"(b[0]), "r"(b[1]));
}
// correction pass: fp16 accumulator
__device__ __forceinline__ void mmah(uint32_t* d, const uint32_t* a, const uint32_t* b) {
    asm volatile("mma.sync.aligned.m16n8k16.row.col.f16.f16.f16.f16 "
        "{%0,%1}, {%2,%3,%4,%5}, {%6,%7}, {%0,%1};"
        : "+r"(d[0]), "+r"(d[1])
        : "r"(a[0]), "r"(a[1]), "r"(a[2]), "r"(a[3]), "r"(b[0]), "r"(b[1]));
}
__device__ __forceinline__ void hmerge(float* d, const uint32_t* h) {
    __half2 q0 = *(const __half2*)&h[0];
    __half2 q1 = *(const __half2*)&h[1];
    d[0] += __half2float(q0.x); d[1] += __half2float(q0.y);
    d[2] += __half2float(q1.x); d[3] += __half2float(q1.y);
}

// grid-wide sense barrier, split into arrive / wait halves
__device__ __forceinline__ void gbar_arrive(unsigned gen) {
    __syncthreads();
    if (threadIdx.x == 0) {
        unsigned prev;
        asm volatile("atom.release.gpu.add.u32 %0, [%1], %2;"
                     : "=r"(prev) : "l"(&g_count), "r"(1u) : "memory");
        if (prev == NCTA - 1) {
            g_count = 0u;
            asm volatile("st.release.gpu.u32 [%0], %1;" :: "l"(&g_sense), "r"(gen) : "memory");
        }
    }
}
__device__ __forceinline__ void gbar_wait(unsigned gen) {
    if (threadIdx.x == 0) {
        unsigned s;
        do {
            asm volatile("ld.acquire.gpu.u32 %0, [%1];" : "=r"(s) : "l"(&g_sense) : "memory");
        } while (s < gen);
    }
    __syncthreads();
}
__device__ __forceinline__ void gbar(unsigned gen) {
    gbar_arrive(gen);
    gbar_wait(gen);
}

#define RS 144          // stage tile row stride (72 halves)
#define GH_T   9216     // gH tile: 64 rows x RS
#define GH_STG 27648    // gH stage: Ah | Bh | Bl
#define GG_T   18432    // gG tile: 128 rows x RS
#define GG_STG 36864    // gG stage: Ah | Al
#define SM_WT    82944  // after 3 gH stages (3 x 27648)
#define WT_RSB   528
#define WT_SZ    67584
#define SM_TOTAL (SM_WT + 2 * WT_SZ)   // 218112
// out-phase stage offsets (within stage region)
#define OUT_RSB  272
#define OUT_HA   0
#define OUT_HAL  8704
#define OUT_WB   17408
#define OUT_WBL  34816

// ---------------------------------------------------------------------------
__global__ void k_dinv(const float* __restrict__ A) {
    int row = blockIdx.x;
    const float* arow = A + (size_t)row * Nc;
    float s = 0.f;
    for (int j = threadIdx.x; j < Nc; j += blockDim.x) s += arow[j];
    __shared__ float sh[128];
    sh[threadIdx.x] = s;
    __syncthreads();
    for (int off = 64; off > 0; off >>= 1) {
        if (threadIdx.x < off) sh[threadIdx.x] += sh[threadIdx.x + off];
        __syncthreads();
    }
    if (threadIdx.x == 0) {
        float d = sh[0];
        g_dinv[row] = (d > 0.f) ? rsqrtf(d) : 0.f;
    }
}

__global__ void k_an(const float* __restrict__ A) {
    int idx = blockIdx.x * blockDim.x + threadIdx.x;
    int e = idx * 4;
    int b   = e >> 18;
    int rem = e & 262143;
    int i   = rem >> 9;
    int j   = rem & 511;
    float4 a = *(const float4*)(A + (size_t)e);
    float di = g_dinv[b * 512 + i];
    const float* dj = g_dinv + b * 512 + j;
    __half2* ph = (__half2*)(g_Anh + (size_t)e);
    ph[0] = __halves2half2(__float2half_rn(a.x * di * dj[0]),
                           __float2half_rn(a.y * di * dj[1]));
    ph[1] = __halves2half2(__float2half_rn(a.z * di * dj[2]),
                           __float2half_rn(a.w * di * dj[3]));
}

// ---------------------------------------------------------------------------
__global__ void k_prep(const float* __restrict__ Wii, const float* __restrict__ bii,
                       const float* __restrict__ Whi, const float* __restrict__ bhi,
                       const float* __restrict__ Wif, const float* __restrict__ bif_,
                       const float* __restrict__ Whf, const float* __restrict__ bhf,
                       const float* __restrict__ Wig, const float* __restrict__ big_,
                       const float* __restrict__ Whg, const float* __restrict__ bhg,
                       const float* __restrict__ Wio, const float* __restrict__ bio,
                       const float* __restrict__ Who, const float* __restrict__ bho,
                       const float* __restrict__ Wpe, const float* __restrict__ bpe) {
    int n = blockIdx.x;
    int g = n & 3;
    int j = n >> 2;
    int t = threadIdx.x;
    const float* Wi = (g == 0) ? Wii : (g == 1) ? Wif : (g == 2) ? Wig : Wio;
    const float* Wh = (g == 0) ? Whi : (g == 1) ? Whf : (g == 2) ? Whg : Who;
    const float* bi = (g == 0) ? bii : (g == 1) ? bif_ : (g == 2) ? big_ : bio;
    const float* bh = (g == 0) ? bhi : (g == 1) ? bhf : (g == 2) ? bhg : bho;

    __shared__ float wcol[128];
    wcol[t] = Wi[(128 + t) * 128 + j];
    __syncthreads();

    g_Wes[t * 512 + n] = Wi[t * 128 + j];

    float acc = 0.f;
    const float* wpet = Wpe + t * 128;
#pragma unroll 8
    for (int m = 0; m < 128; m++) acc += wpet[m] * wcol[m];

    __half hh, ll;
    hsplit(acc, hh, ll);
    g_WTh[n * 256 + t] = hh;
    g_WTl[n * 256 + t] = ll;
    float whv = Wh[t * 128 + j];
    hsplit(whv, hh, ll);
    g_WTh[n * 256 + 128 + t] = hh;
    g_WTl[n * 256 + 128 + t] = ll;

    if (t == 0) {
        float ba = bi[j] + bh[j];
        for (int m = 0; m < 128; m++) ba += bpe[m] * wcol[m];
        g_bbig[n] = ba;
    }
}

// ---------------------------------------------------------------------------
// k_init: es = X0@Wse + bse ; zero h & c ; Xi = X0 ; out t=0 ; barrier reset ;
//         WoutT hi/lo
// ---------------------------------------------------------------------------
__global__ void k_init(const float* __restrict__ X, const float* __restrict__ Wse,
                       const float* __restrict__ bse, const float* __restrict__ Wout,
                       float* __restrict__ out) {
    int row = blockIdx.x;
    int t = threadIdx.x;
    if (row == 0 && t == 0) { g_count = 0u; g_sense = 0u; }
    if (row < 64) {
        __half hh, ll;
        hsplit(Wout[t * 64 + row], hh, ll);
        g_WoTh[row * 128 + t] = hh;
        g_WoTl[row * 128 + t] = ll;
    }
    __shared__ float x0[64];
    if (t < 64) {
        float v = X[(size_t)row * 4096 + t];
        x0[t] = v;
        g_Xi[row * 64 + t] = v;
        out[(size_t)row * 4096 + t] = v;
    }
    __syncthreads();
    float acc = bse[t];
#pragma unroll 8
    for (int k = 0; k < 64; k++) acc += x0[k] * Wse[k * 128 + t];
    g_es[row * 128 + t] = acc;

    __half z = __float2half(0.f);
    g_hrh[0][(size_t)row * 128 + t] = z;
    g_hrl[0][(size_t)row * 128 + t] = z;
    int bb = row >> 9, nn = row & 511;
    g_hTh[0][(size_t)(bb * 128 + t) * 512 + nn] = z;
    g_hTl[0][(size_t)(bb * 128 + t) * 512 + nn] = z;
    g_c[row * 128 + t] = 0.f;
}

// ---------------------------------------------------------------------------
// k_ges: Ges = es @ Wes + bbig (4096 x 512, K=128) fp32, runs once
// ---------------------------------------------------------------------------
__global__ void __launch_bounds__(256) k_ges() {
    int m0 = (blockIdx.x >> 2) * 64;
    int n0 = (blockIdx.x & 3) * 128;

    __shared__ __align__(16) float As[16][68];
    __shared__ __align__(16) float Bs[16][132];

    int tid = threadIdx.x;
    int ty = tid >> 4, tx = tid & 15;
    int ar = tid >> 2, ac = (tid & 3) * 4;
    int br = tid >> 5, bc = (tid & 31) * 4;

    float acc[4][8] = {};

    for (int k0 = 0; k0 < 128; k0 += 16) {
        float4 av = *(const float4*)&g_es[(size_t)(m0 + ar) * 128 + k0 + ac];
        float4 bv0 = *(const float4*)&g_Wes[(size_t)(k0 + br) * 512 + n0 + bc];
        float4 bv1 = *(const float4*)&g_Wes[(size_t)(k0 + br + 8) * 512 + n0 + bc];
        As[ac + 0][ar] = av.x; As[ac + 1][ar] = av.y;
        As[ac + 2][ar] = av.z; As[ac + 3][ar] = av.w;
        *(float4*)&Bs[br][bc] = bv0;
        *(float4*)&Bs[br + 8][bc] = bv1;
        __syncthreads();
#pragma unroll
        for (int kk = 0; kk < 16; kk++) {
            float4 a4 = *(const float4*)&As[kk][ty * 4];
            float4 b0 = *(const float4*)&Bs[kk][tx * 8];
            float4 b1 = *(const float4*)&Bs[kk][tx * 8 + 4];
            float av4[4] = { a4.x, a4.y, a4.z, a4.w };
            float bv8[8] = { b0.x, b0.y, b0.z, b0.w, b1.x, b1.y, b1.z, b1.w };
#pragma unroll
            for (int i = 0; i < 4; i++)
#pragma unroll
                for (int jq = 0; jq < 8; jq++) acc[i][jq] += av4[i] * bv8[jq];
        }
        __syncthreads();
    }

    float bb[8];
#pragma unroll
    for (int q = 0; q < 8; q++) bb[q] = g_bbig[n0 + tx * 8 + q];
#pragma unroll
    for (int r = 0; r < 4; r++) {
        int rr = m0 + ty * 4 + r;
        float* dst = &g_Ges[(size_t)rr * 512 + n0 + tx * 8];
#pragma unroll
        for (int q = 0; q < 8; q++) dst[q] = acc[r][q] + bb[q];
    }
}

// ---------------------------------------------------------------------------
// phase gH: H = An @ h, CTA tile 64x64 (8b x 8m x 2n = 128 tiles)
// An fp16-only; corrections: Ah·Bl via fp16 acc. 3-stage pipeline.
// ---------------------------------------------------------------------------
__device__ __forceinline__ void phase_gH(char* dsm, int hin, int cta, int tid) {
    uint32_t sbase = smem_u32(dsm);
    int wid = tid >> 5, lane = tid & 31;
    int wm = wid >> 2, wn = wid & 3;
    int b  = cta >> 4;
    int m0 = ((cta >> 1) & 7) * 64;
    int n0 = (cta & 1) * 64;

    float acc[2][2][4];
    uint32_t hacc[2][2][2];
#pragma unroll
    for (int i = 0; i < 2; i++)
#pragma unroll
        for (int j = 0; j < 2; j++) {
#pragma unroll
            for (int q = 0; q < 4; q++) acc[i][j][q] = 0.f;
            hacc[i][j][0] = 0u; hacc[i][j][1] = 0u;
        }

    const __half* Ah0 = g_Anh + (size_t)b * 262144 + (size_t)m0 * 512;
    const __half* Bh0 = g_hTh[hin] + (size_t)b * 65536 + (size_t)n0 * 512;
    const __half* Bl0 = g_hTl[hin] + (size_t)b * 65536 + (size_t)n0 * 512;

    auto stg = [&](int cc) -> uint32_t { return sbase + (uint32_t)(cc % 3) * GH_STG; };

    auto issue = [&](int cc) {
        uint32_t buf = stg(cc);
        int kc = cc * 64;
#pragma unroll
        for (int i = 0; i < 2; i++) {
            int idx = tid + i * 256, r = idx >> 3, c = idx & 7;
            uint32_t d = buf + r * RS + c * 16;
            size_t off = (size_t)r * 512 + kc + c * 8;
            cpa16(d,            Ah0 + off);
            cpa16(d + GH_T,     Bh0 + off);
            cpa16(d + 2 * GH_T, Bl0 + off);
        }
    };

    issue(0); CP_COMMIT();
    issue(1); CP_COMMIT();

#pragma unroll 1
    for (int cc = 0; cc < 8; cc++) {
        CP_WAIT1();
        __syncthreads();

        uint32_t buf = stg(cc);
        uint32_t aH = buf + (uint32_t)(wm * 32 + (lane & 15)) * RS + ((lane >> 4) * 16);
        uint32_t bH = buf + GH_T
                    + (uint32_t)(wn * 16 + (lane & 7) + ((lane >> 4) & 1) * 8) * RS
                    + (((lane >> 3) & 1) * 16);
        uint32_t bL = bH + GH_T;
#pragma unroll
        for (int ks = 0; ks < 4; ks++) {
            uint32_t ah[2][4], bh[4], bl[4];
            ldsm4(ah[0], aH + ks * 32); ldsm4(ah[1], aH + 16 * RS + ks * 32);
            ldsm4(bh, bH + ks * 32);
            ldsm4(bl, bL + ks * 32);
#pragma unroll
            for (int mf = 0; mf < 2; mf++) {
                mmaf(acc[mf][0], ah[mf], &bh[0]); mmaf(acc[mf][1], ah[mf], &bh[2]);
                mmah(hacc[mf][0], ah[mf], &bl[0]); mmah(hacc[mf][1], ah[mf], &bl[2]);
            }
        }
        __syncthreads();
        if (cc + 2 < 8) { issue(cc + 2); CP_COMMIT(); }
    }
    CP_WAIT0();

    int rbase = b * 512 + m0 + wm * 32 + (lane >> 2);
    int cbase = n0 + wn * 16 + (lane & 3) * 2;
#pragma unroll
    for (int mf = 0; mf < 2; mf++) {
#pragma unroll
        for (int nf = 0; nf < 2; nf++) {
            int col = cbase + nf * 8;
            float* d = acc[mf][nf];
            hmerge(d, hacc[mf][nf]);
            __half h0, l0, h1, l1;
            int r0 = rbase + mf * 16;
            hsplit(d[0], h0, l0); hsplit(d[1], h1, l1);
            *(__half2*)(g_Hh + (size_t)r0 * 128 + col) = __halves2half2(h0, h1);
            *(__half2*)(g_Hl + (size_t)r0 * 128 + col) = __halves2half2(l0, l1);
            hsplit(d[2], h0, l0); hsplit(d[3], h1, l1);
            *(__half2*)(g_Hh + (size_t)(r0 + 8) * 128 + col) = __halves2half2(h0, h1);
            *(__half2*)(g_Hl + (size_t)(r0 + 8) * 128 + col) = __halves2half2(l0, l1);
        }
    }
}

// ---------------------------------------------------------------------------
// phase gG (barrier-overlapped): gates = Ges + [H | h] @ Wcomb, 128x128 tiles.
// Part 1 (before bar wait): chunks 2,3 = h(t-1)-part.  Part 2: chunks 0,1 + epi.
// ---------------------------------------------------------------------------
__device__ __forceinline__ void phase_gG(char* dsm, int hin, int hout, int cta, int tid,
                                         unsigned wait_gen) {
    uint32_t sbase = smem_u32(dsm);
    int wid = tid >> 5, lane = tid & 31;
    int wm = wid >> 2, wn = wid & 3;
    int m0 = (cta >> 2) * 128;
    int n0 = (cta & 3) * 128;

    float acc[4][4][4];
    uint32_t hacc[4][4][2];
#pragma unroll
    for (int i = 0; i < 4; i++)
#pragma unroll
        for (int j = 0; j < 4; j++) {
#pragma unroll
            for (int q = 0; q < 4; q++) acc[i][j][q] = 0.f;
            hacc[i][j][0] = 0u; hacc[i][j][1] = 0u;
        }

    auto issue = [&](int cc, uint32_t buf) {
        int kc = cc * 64;
        const __half* Ahs;
        const __half* Als;
        if (kc < 128) {
            Ahs = g_Hh + (size_t)m0 * 128 + kc;
            Als = g_Hl + (size_t)m0 * 128 + kc;
        } else {
            Ahs = g_hrh[hin] + (size_t)m0 * 128 + (kc - 128);
            Als = g_hrl[hin] + (size_t)m0 * 128 + (kc - 128);
        }
#pragma unroll
        for (int i = 0; i < 4; i++) {
            int idx = tid + i * 256, r = idx >> 3, c = idx & 7;
            uint32_t d = buf + r * RS + c * 16;
            size_t off = (size_t)r * 128 + c * 8;
            cpa16(d,        Ahs + off);
            cpa16(d + GG_T, Als + off);
        }
    };

    uint32_t wtH = sbase + SM_WT
                 + (uint32_t)(wn * 32 + (lane & 7) + ((lane >> 4) & 1) * 8) * WT_RSB
                 + (((lane >> 3) & 1) * 16);
    uint32_t wtL = wtH + WT_SZ;

    auto compute = [&](int cc, uint32_t buf) {
        uint32_t aH = buf + (uint32_t)(wm * 64 + (lane & 15)) * RS + ((lane >> 4) * 16);
        uint32_t aL = aH + GG_T;
        uint32_t kb = (uint32_t)cc * 128;
#pragma unroll
        for (int ks = 0; ks < 4; ks++) {
            uint32_t ah[4][4], al[4][4], bh0[4], bh1[4], bl0[4], bl1[4];
#pragma unroll
            for (int mf = 0; mf < 4; mf++) {
                ldsm4(ah[mf], aH + mf * 16 * RS + ks * 32);
                ldsm4(al[mf], aL + mf * 16 * RS + ks * 32);
            }
            ldsm4(bh0, wtH + kb + ks * 32);
            ldsm4(bh1, wtH + 16 * WT_RSB + kb + ks * 32);
            ldsm4(bl0, wtL + kb + ks * 32);
            ldsm4(bl1, wtL + 16 * WT_RSB + kb + ks * 32);
#pragma unroll
            for (int mf = 0; mf < 4; mf++) {
                mmaf(acc[mf][0], ah[mf], &bh0[0]); mmaf(acc[mf][1], ah[mf], &bh0[2]);
                mmaf(acc[mf][2], ah[mf], &bh1[0]); mmaf(acc[mf][3], ah[mf], &bh1[2]);
                mmah(hacc[mf][0], al[mf], &bh0[0]); mmah(hacc[mf][1], al[mf], &bh0[2]);
                mmah(hacc[mf][2], al[mf], &bh1[0]); mmah(hacc[mf][3], al[mf], &bh1[2]);
                mmah(hacc[mf][0], ah[mf], &bl0[0]); mmah(hacc[mf][1], ah[mf], &bl0[2]);
                mmah(hacc[mf][2], ah[mf], &bl1[0]); mmah(hacc[mf][3], ah[mf], &bl1[2]);
            }
        }
    };

    // ---- part 1: h-part chunks (2,3) — no dependence on this step's H
    issue(2, sbase);            CP_COMMIT();
    issue(3, sbase + GG_STG);   CP_COMMIT();
    CP_WAIT1();
    __syncthreads();
    compute(2, sbase);
    CP_WAIT0();
    __syncthreads();
    compute(3, sbase + GG_STG);

    // ---- barrier wait: H(t) complete grid-wide
    gbar_wait(wait_gen);

    // ---- part 2: H-part chunks (0,1)
    issue(0, sbase);            CP_COMMIT();
    issue(1, sbase + GG_STG);   CP_COMMIT();
    CP_WAIT1();
    __syncthreads();
    compute(0, sbase);
    CP_WAIT0();
    __syncthreads();
    compute(1, sbase + GG_STG);
    __syncthreads();

    // stage fp32 gate tile (with corrections merged) in smem
    float* cst = (float*)dsm;   // [128][132]
#pragma unroll
    for (int mf = 0; mf < 4; mf++) {
#pragma unroll
        for (int nf = 0; nf < 4; nf++) {
            int row = wm * 64 + mf * 16 + (lane >> 2);
            int col = wn * 32 + nf * 8 + (lane & 3) * 2;
            float* d = acc[mf][nf];
            hmerge(d, hacc[mf][nf]);
            *(float2*)&cst[row * 132 + col]       = make_float2(d[0], d[1]);
            *(float2*)&cst[(row + 8) * 132 + col] = make_float2(d[2], d[3]);
        }
    }
    __syncthreads();

    // pass 1: gates -> c, h (h in regs)
    float hv16[16];
    int q  = tid & 31;
    int rb = tid >> 5;
    int j  = (n0 >> 2) + q;
    __half* hrho = g_hrh[hout];
    __half* hrlo = g_hrl[hout];
#pragma unroll
    for (int i = 0; i < 16; i++) {
        int r = rb + i * 8;
        int rr = m0 + r;
        float4 pv = *(float4*)&cst[r * 132 + q * 4];
        float4 ge = *(const float4*)&g_Ges[(size_t)rr * 512 + j * 4];
        float iv = sigm(pv.x + ge.x), fv = sigm(pv.y + ge.y);
        float gv = ftanh(pv.z + ge.z), ov = sigm(pv.w + ge.w);
        size_t cidx = (size_t)rr * 128 + j;
        float cc = fv * g_c[cidx] + iv * gv;
        g_c[cidx] = cc;
        float hv = ov * ftanh(cc);
        hv16[i] = hv;
        __half hh, ll;
        hsplit(hv, hh, ll);
        hrho[cidx] = hh;
        hrlo[cidx] = ll;
    }
    __syncthreads();   // cst dead

    // pass 2: smem transpose (32 features x 128 rows)
    __half* trh = (__half*)dsm;            // [32][136]
    __half* trl = (__half*)(dsm + 8704);
#pragma unroll
    for (int i = 0; i < 16; i++) {
        int r = rb + i * 8;
        __half hh, ll;
        hsplit(hv16[i], hh, ll);
        trh[q * 136 + r] = hh;
        trl[q * 136 + r] = ll;
    }
    __syncthreads();

    // pass 3: coalesced hT writes
    __half* hTh = g_hTh[hout];
    __half* hTl = g_hTl[hout];
    int bb = m0 >> 9, nn0 = m0 & 511;
    int jr = tid >> 4, ch = tid & 15;
#pragma unroll
    for (int half = 0; half < 2; half++) {
        int jj = jr + half * 16;
        uint4 vh = *(uint4*)&trh[jj * 136 + ch * 8];
        uint4 vl = *(uint4*)&trl[jj * 136 + ch * 8];
        size_t base = (size_t)(bb * 128 + (n0 >> 2) + jj) * 512 + nn0 + ch * 8;
        *(uint4*)&hTh[base] = vh;
        *(uint4*)&hTl[base] = vl;
    }
    __syncthreads();
}

// ---------------------------------------------------------------------------
// phase out (tensor-core): Xi += h @ Wout + bout ; emit out[:, :, t, :]
// ---------------------------------------------------------------------------
__device__ __forceinline__ void phase_out(char* dsm, int t, int hidx,
                                          const float* __restrict__ bout,
                                          float* __restrict__ out, int cta, int tid) {
    uint32_t sbase = smem_u32(dsm);
    int wid = tid >> 5, lane = tid & 31;
    int mw = wid & 1, nw = wid >> 1;
    int row0 = cta * 32;
    __syncthreads();

    {
        const __half* hh = g_hrh[hidx] + (size_t)row0 * 128;
        const __half* hl = g_hrl[hidx] + (size_t)row0 * 128;
#pragma unroll
        for (int i = 0; i < 2; i++) {
            int idx = tid + i * 256, r = idx >> 4, c = idx & 15;
            cpa16(sbase + OUT_HA  + r * OUT_RSB + c * 16, hh + (size_t)r * 128 + c * 8);
            cpa16(sbase + OUT_HAL + r * OUT_RSB + c * 16, hl + (size_t)r * 128 + c * 8);
        }
#pragma unroll
        for (int i = 0; i < 4; i++) {
            int idx = tid + i * 256, r = idx >> 4, c = idx & 15;
            cpa16(sbase + OUT_WB  + r * OUT_RSB + c * 16, g_WoTh + (size_t)r * 128 + c * 8);
            cpa16(sbase + OUT_WBL + r * OUT_RSB + c * 16, g_WoTl + (size_t)r * 128 + c * 8);
        }
        CP_COMMIT();
    }

    int rA = row0 + mw * 16 + (lane >> 2);
    int cA = nw * 16 + (lane & 3) * 2;
    float2 xi[2][2], bo[2];
#pragma unroll
    for (int nf = 0; nf < 2; nf++) {
        int col = cA + nf * 8;
        xi[nf][0] = *(const float2*)&g_Xi[rA * 64 + col];
        xi[nf][1] = *(const float2*)&g_Xi[(rA + 8) * 64 + col];
        bo[nf] = *(const float2*)&bout[col];
    }

    CP_WAIT0();
    __syncthreads();

    uint32_t aH = sbase + OUT_HA + (uint32_t)(mw * 16 + (lane & 15)) * OUT_RSB + ((lane >> 4) * 16);
    uint32_t aL = aH + (OUT_HAL - OUT_HA);
    uint32_t bH = sbase + OUT_WB
                + (uint32_t)(nw * 16 + (lane & 7) + ((lane >> 4) & 1) * 8) * OUT_RSB
                + (((lane >> 3) & 1) * 16);
    uint32_t bL = bH + (OUT_WBL - OUT_WB);

    float acc[2][4] = {};
    uint32_t hacc[2][2] = {};
#pragma unroll
    for (int ks = 0; ks < 8; ks++) {
        uint32_t ah[4], al[4], bh[4], bl[4];
        ldsm4(ah, aH + ks * 32);
        ldsm4(al, aL + ks * 32);
        ldsm4(bh, bH + ks * 32);
        ldsm4(bl, bL + ks * 32);
        mmaf(acc[0], ah, &bh[0]); mmaf(acc[1], ah, &bh[2]);
        mmah(hacc[0], al, &bh[0]); mmah(hacc[1], al, &bh[2]);
        mmah(hacc[0], ah, &bl[0]); mmah(hacc[1], ah, &bl[2]);
    }

#pragma unroll
    for (int nf = 0; nf < 2; nf++) {
        hmerge(acc[nf], hacc[nf]);
        int col = cA + nf * 8;
        float2 v0 = make_float2(acc[nf][0] + xi[nf][0].x + bo[nf].x,
                                acc[nf][1] + xi[nf][0].y + bo[nf].y);
        float2 v1 = make_float2(acc[nf][2] + xi[nf][1].x + bo[nf].x,
                                acc[nf][3] + xi[nf][1].y + bo[nf].y);
        *(float2*)&g_Xi[rA * 64 + col] = v0;
        *(float2*)&g_Xi[(rA + 8) * 64 + col] = v1;
        *(float2*)&out[(size_t)rA * 4096 + t * 64 + col] = v0;
        *(float2*)&out[(size_t)(rA + 8) * 4096 + t * 64 + col] = v1;
    }
    __syncthreads();
}

// ---------------------------------------------------------------------------
// k_main: persistent kernel, 63 steps.
// gH -> arrive -> out(t-1) -> gG(h-part, wait, H-part) -> bar2
// ---------------------------------------------------------------------------
__global__ void __launch_bounds__(256) k_main(const float* __restrict__ bout,
                                              float* __restrict__ out) {
    extern __shared__ __align__(16) char dsm[];
    int cta = blockIdx.x, tid = threadIdx.x;

    // persistent weight slice for this CTA's gG n-tile
    {
        int n0 = (cta & 3) * 128;
        uint32_t wt = smem_u32(dsm) + SM_WT;
#pragma unroll
        for (int i = 0; i < 16; i++) {
            int idx = tid + i * 256;
            int r = idx >> 5, c = idx & 31;
            cpa16(wt + r * WT_RSB + c * 16,         g_WTh + (size_t)(n0 + r) * 256 + c * 8);
            cpa16(wt + WT_SZ + r * WT_RSB + c * 16, g_WTl + (size_t)(n0 + r) * 256 + c * 8);
        }
        CP_COMMIT();
        CP_WAIT0();
    }
    __syncthreads();

    unsigned gen = 0;
#pragma unroll 1
    for (int t = 1; t < Tc; t++) {
        int hin = (t - 1) & 1, hout = t & 1;
        phase_gH(dsm, hin, cta, tid);
        ++gen;
        gbar_arrive(gen);                            // bar1: this CTA's H done
        if (t >= 2) phase_out(dsm, t - 1, hin, bout, out, cta, tid);
        phase_gG(dsm, hin, hout, cta, tid, gen);     // h-part + out overlap bar1 wait
        gbar(++gen);                                 // bar2: h(t) complete
    }
    phase_out(dsm, Tc - 1, (Tc - 1) & 1, bout, out, cta, tid);
}

// ---------------------------------------------------------------------------
extern "C" void kernel_launch(void* const* d_in, const int* in_sizes, int n_in,
                              void* d_out, int out_size) {
    const float* X    = (const float*)d_in[0];
    const float* A    = (const float*)d_in[1];
    const float* Wse  = (const float*)d_in[2];
    const float* bse  = (const float*)d_in[3];
    const float* Wpe  = (const float*)d_in[4];
    const float* bpe  = (const float*)d_in[5];
    const float* Wii  = (const float*)d_in[6];
    const float* bii  = (const float*)d_in[7];
    const float* Whi  = (const float*)d_in[8];
    const float* bhi  = (const float*)d_in[9];
    const float* Wif  = (const float*)d_in[10];
    const float* bif_ = (const float*)d_in[11];
    const float* Whf  = (const float*)d_in[12];
    const float* bhf  = (const float*)d_in[13];
    const float* Wig  = (const float*)d_in[14];
    const float* big_ = (const float*)d_in[15];
    const float* Whg  = (const float*)d_in[16];
    const float* bhg  = (const float*)d_in[17];
    const float* Wio  = (const float*)d_in[18];
    const float* bio  = (const float*)d_in[19];
    const float* Who  = (const float*)d_in[20];
    const float* bho  = (const float*)d_in[21];
    const float* Wout = (const float*)d_in[22];
    const float* bout = (const float*)d_in[23];
    float* out = (float*)d_out;

    cudaFuncSetAttribute(k_main, cudaFuncAttributeMaxDynamicSharedMemorySize, SM_TOTAL);

    k_dinv<<<Rc, 128>>>(A);
    k_an<<<2048, 256>>>(A);
    k_prep<<<512, 128>>>(Wii, bii, Whi, bhi, Wif, bif_, Whf, bhf,
                         Wig, big_, Whg, bhg, Wio, bio, Who, bho, Wpe, bpe);
    k_init<<<Rc, 128>>>(X, Wse, bse, Wout, out);
    k_ges<<<256, 256>>>();
    k_main<<<NCTA, 256, SM_TOTAL>>>(bout, out);
}

// round 11
// speedup vs baseline: 1.2382x; 1.1167x over previous
#include <cuda_runtime.h>
#include <cuda_fp16.h>
#include <math.h>
#include <stdint.h>

// Problem constants
#define Bc   8
#define Nc   512
#define Tc   64
#define NINc 64
#define NHc  128
#define Rc   (Bc * Nc)   // 4096 rows
#define NCTA 128

// ---------------- scratch (device globals) ----------------------------------
__device__ float g_dinv[Rc];
__device__ __half g_Anh[Bc * Nc * Nc];          // An fp16 (4 MB)
__device__ float g_es[Rc * NHc];                // static embedding fp32
__device__ float g_Wes[128 * 512];              // Wi[0:128] interleaved fp32
__device__ float g_bbig[512];
__device__ float g_Ges[Rc * 512];               // es @ Wes + bbig (fp32, interleaved)
__device__ __half g_WTh[512 * 256];             // Wcomb^T hi: [n][k]
__device__ __half g_WTl[512 * 256];
__device__ __half g_WoTh[64 * 128];             // Wout^T hi: [n][k]
__device__ __half g_WoTl[64 * 128];
__device__ __half g_Hh[Rc * NHc];               // H = An@h, fp16, row-major
__device__ __half g_hrh[2][Rc * NHc];           // h row-major hi/lo (double buffered)
__device__ __half g_hrl[2][Rc * NHc];
__device__ __half g_hTh[2][Bc * NHc * Nc];      // h transposed per batch [b][j][n]
__device__ __half g_hTl[2][Bc * NHc * Nc];
__device__ float g_c[Rc * NHc];                 // cell state
__device__ float g_Xi[Rc * NINc];               // running output accumulator
__device__ unsigned g_count;                    // grid barrier arrive counter
__device__ unsigned g_sense;                    // grid barrier generation

// ---------------- helpers ----------------------------------------------------
__device__ __forceinline__ uint32_t smem_u32(const void* p) {
    uint32_t a;
    asm("{ .reg .u64 t; cvta.to.shared.u64 t, %1; cvt.u32.u64 %0, t; }" : "=r"(a) : "l"(p));
    return a;
}
// fast sigmoid / tanh via MUFU paths
__device__ __forceinline__ float sigm(float x) {
    return __fdividef(1.f, 1.f + __expf(-x));
}
__device__ __forceinline__ float ftanh(float x) {
    float e = __expf(2.f * x);
    return 1.f - __fdividef(2.f, e + 1.f);
}
__device__ __forceinline__ void hsplit(float v, __half& hi, __half& lo) {
    hi = __float2half_rn(v);
    lo = __float2half_rn(v - __half2float(hi));
}
__device__ __forceinline__ void cpa16(uint32_t dst, const void* src) {
    asm volatile("cp.async.cg.shared.global [%0], [%1], 16;" :: "r"(dst), "l"(src) : "memory");
}
#define CP_COMMIT() asm volatile("cp.async.commit_group;" ::: "memory")
#define CP_WAIT1()  asm volatile("cp.async.wait_group 1;" ::: "memory")
#define CP_WAIT0()  asm volatile("cp.async.wait_group 0;" ::: "memory")

__device__ __forceinline__ void ldsm4(uint32_t* r, uint32_t a) {
    asm volatile("ldmatrix.sync.aligned.m8n8.x4.shared.b16 {%0,%1,%2,%3}, [%4];"
        : "=r"(r[0]), "=r"(r[1]), "=r"(r[2]), "=r"(r[3]) : "r"(a));
}
// main pass: fp16 operands, fp32 accumulator
__device__ __forceinline__ void mmaf(float* d, const uint32_t* a, const uint32_t* b) {
    asm volatile("mma.sync.aligned.m16n8k16.row.col.f32.f16.f16.f32 "
        "{%0,%1,%2,%3}, {%4,%5,%6,%7}, {%8,%9}, {%0,%1,%2,%3};"
        : "+f"(d[0]), "+f"(d[1]), "+f"(d[2]), "+f"(d[3])
        : "r"(a[0]), "r"(a[1]), "r"(a[2]), "r"(a[3]), "r"(b[0]), "r"(b[1]));
}
// correction pass: fp16 accumulator
__device__ __forceinline__ void mmah(uint32_t* d, const uint32_t* a, const uint32_t* b) {
    asm volatile("mma.sync.aligned.m16n8k16.row.col.f16.f16.f16.f16 "
        "{%0,%1}, {%2,%3,%4,%5}, {%6,%7}, {%0,%1};"
        : "+r"(d[0]), "+r"(d[1])
        : "r"(a[0]), "r"(a[1]), "r"(a[2]), "r"(a[3]), "r"(b[0]), "r"(b[1]));
}
__device__ __forceinline__ void hmerge(float* d, const uint32_t* h) {
    __half2 q0 = *(const __half2*)&h[0];
    __half2 q1 = *(const __half2*)&h[1];
    d[0] += __half2float(q0.x); d[1] += __half2float(q0.y);
    d[2] += __half2float(q1.x); d[3] += __half2float(q1.y);
}

// grid-wide sense barrier, split into arrive / wait halves
__device__ __forceinline__ void gbar_arrive(unsigned gen) {
    __syncthreads();
    if (threadIdx.x == 0) {
        unsigned prev;
        asm volatile("atom.release.gpu.add.u32 %0, [%1], %2;"
                     : "=r"(prev) : "l"(&g_count), "r"(1u) : "memory");
        if (prev == NCTA - 1) {
            g_count = 0u;
            asm volatile("st.release.gpu.u32 [%0], %1;" :: "l"(&g_sense), "r"(gen) : "memory");
        }
    }
}
__device__ __forceinline__ void gbar_wait(unsigned gen) {
    if (threadIdx.x == 0) {
        unsigned s;
        do {
            asm volatile("ld.acquire.gpu.u32 %0, [%1];" : "=r"(s) : "l"(&g_sense) : "memory");
        } while (s < gen);
    }
    __syncthreads();
}
__device__ __forceinline__ void gbar(unsigned gen) {
    gbar_arrive(gen);
    gbar_wait(gen);
}

#define RS 144          // stage tile row stride (72 halves)
#define GH_T   9216     // gH tile: 64 rows x RS
#define GH_STG 27648    // gH stage: Ah | Bh | Bl
#define GG_T   18432    // gG tile: 128 rows x RS
#define GG_STG 18432    // gG stage: Ah only
#define SM_WT    82944  // after 3 gH stages (3 x 27648)
#define WT_RSB   528
#define WT_SZ    67584
#define SM_TOTAL (SM_WT + 2 * WT_SZ)   // 218112
// out-phase stage offsets (within stage region)
#define OUT_RSB  272
#define OUT_HA   0
#define OUT_HAL  8704
#define OUT_WB   17408
#define OUT_WBL  34816

// ---------------------------------------------------------------------------
__global__ void k_dinv(const float* __restrict__ A) {
    int row = blockIdx.x;
    const float* arow = A + (size_t)row * Nc;
    float s = 0.f;
    for (int j = threadIdx.x; j < Nc; j += blockDim.x) s += arow[j];
    __shared__ float sh[128];
    sh[threadIdx.x] = s;
    __syncthreads();
    for (int off = 64; off > 0; off >>= 1) {
        if (threadIdx.x < off) sh[threadIdx.x] += sh[threadIdx.x + off];
        __syncthreads();
    }
    if (threadIdx.x == 0) {
        float d = sh[0];
        g_dinv[row] = (d > 0.f) ? rsqrtf(d) : 0.f;
    }
}

__global__ void k_an(const float* __restrict__ A) {
    int idx = blockIdx.x * blockDim.x + threadIdx.x;
    int e = idx * 4;
    int b   = e >> 18;
    int rem = e & 262143;
    int i   = rem >> 9;
    int j   = rem & 511;
    float4 a = *(const float4*)(A + (size_t)e);
    float di = g_dinv[b * 512 + i];
    const float* dj = g_dinv + b * 512 + j;
    __half2* ph = (__half2*)(g_Anh + (size_t)e);
    ph[0] = __halves2half2(__float2half_rn(a.x * di * dj[0]),
                           __float2half_rn(a.y * di * dj[1]));
    ph[1] = __halves2half2(__float2half_rn(a.z * di * dj[2]),
                           __float2half_rn(a.w * di * dj[3]));
}

// ---------------------------------------------------------------------------
__global__ void k_prep(const float* __restrict__ Wii, const float* __restrict__ bii,
                       const float* __restrict__ Whi, const float* __restrict__ bhi,
                       const float* __restrict__ Wif, const float* __restrict__ bif_,
                       const float* __restrict__ Whf, const float* __restrict__ bhf,
                       const float* __restrict__ Wig, const float* __restrict__ big_,
                       const float* __restrict__ Whg, const float* __restrict__ bhg,
                       const float* __restrict__ Wio, const float* __restrict__ bio,
                       const float* __restrict__ Who, const float* __restrict__ bho,
                       const float* __restrict__ Wpe, const float* __restrict__ bpe) {
    int n = blockIdx.x;
    int g = n & 3;
    int j = n >> 2;
    int t = threadIdx.x;
    const float* Wi = (g == 0) ? Wii : (g == 1) ? Wif : (g == 2) ? Wig : Wio;
    const float* Wh = (g == 0) ? Whi : (g == 1) ? Whf : (g == 2) ? Whg : Who;
    const float* bi = (g == 0) ? bii : (g == 1) ? bif_ : (g == 2) ? big_ : bio;
    const float* bh = (g == 0) ? bhi : (g == 1) ? bhf : (g == 2) ? bhg : bho;

    __shared__ float wcol[128];
    wcol[t] = Wi[(128 + t) * 128 + j];
    __syncthreads();

    g_Wes[t * 512 + n] = Wi[t * 128 + j];

    float acc = 0.f;
    const float* wpet = Wpe + t * 128;
#pragma unroll 8
    for (int m = 0; m < 128; m++) acc += wpet[m] * wcol[m];

    __half hh, ll;
    hsplit(acc, hh, ll);
    g_WTh[n * 256 + t] = hh;
    g_WTl[n * 256 + t] = ll;
    float whv = Wh[t * 128 + j];
    hsplit(whv, hh, ll);
    g_WTh[n * 256 + 128 + t] = hh;
    g_WTl[n * 256 + 128 + t] = ll;

    if (t == 0) {
        float ba = bi[j] + bh[j];
        for (int m = 0; m < 128; m++) ba += bpe[m] * wcol[m];
        g_bbig[n] = ba;
    }
}

// ---------------------------------------------------------------------------
// k_init: es = X0@Wse + bse ; zero h & c ; Xi = X0 ; out t=0 ; barrier reset ;
//         WoutT hi/lo
// ---------------------------------------------------------------------------
__global__ void k_init(const float* __restrict__ X, const float* __restrict__ Wse,
                       const float* __restrict__ bse, const float* __restrict__ Wout,
                       float* __restrict__ out) {
    int row = blockIdx.x;
    int t = threadIdx.x;
    if (row == 0 && t == 0) { g_count = 0u; g_sense = 0u; }
    if (row < 64) {
        __half hh, ll;
        hsplit(Wout[t * 64 + row], hh, ll);
        g_WoTh[row * 128 + t] = hh;
        g_WoTl[row * 128 + t] = ll;
    }
    __shared__ float x0[64];
    if (t < 64) {
        float v = X[(size_t)row * 4096 + t];
        x0[t] = v;
        g_Xi[row * 64 + t] = v;
        out[(size_t)row * 4096 + t] = v;
    }
    __syncthreads();
    float acc = bse[t];
#pragma unroll 8
    for (int k = 0; k < 64; k++) acc += x0[k] * Wse[k * 128 + t];
    g_es[row * 128 + t] = acc;

    __half z = __float2half(0.f);
    g_hrh[0][(size_t)row * 128 + t] = z;
    g_hrl[0][(size_t)row * 128 + t] = z;
    int bb = row >> 9, nn = row & 511;
    g_hTh[0][(size_t)(bb * 128 + t) * 512 + nn] = z;
    g_hTl[0][(size_t)(bb * 128 + t) * 512 + nn] = z;
    g_c[row * 128 + t] = 0.f;
}

// ---------------------------------------------------------------------------
// k_ges: Ges = es @ Wes + bbig (4096 x 512, K=128) fp32, runs once
// ---------------------------------------------------------------------------
__global__ void __launch_bounds__(256) k_ges() {
    int m0 = (blockIdx.x >> 2) * 64;
    int n0 = (blockIdx.x & 3) * 128;

    __shared__ __align__(16) float As[16][68];
    __shared__ __align__(16) float Bs[16][132];

    int tid = threadIdx.x;
    int ty = tid >> 4, tx = tid & 15;
    int ar = tid >> 2, ac = (tid & 3) * 4;
    int br = tid >> 5, bc = (tid & 31) * 4;

    float acc[4][8] = {};

    for (int k0 = 0; k0 < 128; k0 += 16) {
        float4 av = *(const float4*)&g_es[(size_t)(m0 + ar) * 128 + k0 + ac];
        float4 bv0 = *(const float4*)&g_Wes[(size_t)(k0 + br) * 512 + n0 + bc];
        float4 bv1 = *(const float4*)&g_Wes[(size_t)(k0 + br + 8) * 512 + n0 + bc];
        As[ac + 0][ar] = av.x; As[ac + 1][ar] = av.y;
        As[ac + 2][ar] = av.z; As[ac + 3][ar] = av.w;
        *(float4*)&Bs[br][bc] = bv0;
        *(float4*)&Bs[br + 8][bc] = bv1;
        __syncthreads();
#pragma unroll
        for (int kk = 0; kk < 16; kk++) {
            float4 a4 = *(const float4*)&As[kk][ty * 4];
            float4 b0 = *(const float4*)&Bs[kk][tx * 8];
            float4 b1 = *(const float4*)&Bs[kk][tx * 8 + 4];
            float av4[4] = { a4.x, a4.y, a4.z, a4.w };
            float bv8[8] = { b0.x, b0.y, b0.z, b0.w, b1.x, b1.y, b1.z, b1.w };
#pragma unroll
            for (int i = 0; i < 4; i++)
#pragma unroll
                for (int jq = 0; jq < 8; jq++) acc[i][jq] += av4[i] * bv8[jq];
        }
        __syncthreads();
    }

    float bb[8];
#pragma unroll
    for (int q = 0; q < 8; q++) bb[q] = g_bbig[n0 + tx * 8 + q];
#pragma unroll
    for (int r = 0; r < 4; r++) {
        int rr = m0 + ty * 4 + r;
        float* dst = &g_Ges[(size_t)rr * 512 + n0 + tx * 8];
#pragma unroll
        for (int q = 0; q < 8; q++) dst[q] = acc[r][q] + bb[q];
    }
}

// ---------------------------------------------------------------------------
// phase gH: H = An @ h, CTA tile 64x64 (8b x 8m x 2n = 128 tiles)
// An fp16-only; correction: Ah·Bl via fp16 acc. 3-stage pipeline.
// ---------------------------------------------------------------------------
__device__ __forceinline__ void phase_gH(char* dsm, int hin, int cta, int tid) {
    uint32_t sbase = smem_u32(dsm);
    int wid = tid >> 5, lane = tid & 31;
    int wm = wid >> 2, wn = wid & 3;
    int b  = cta >> 4;
    int m0 = ((cta >> 1) & 7) * 64;
    int n0 = (cta & 1) * 64;

    float acc[2][2][4];
    uint32_t hacc[2][2][2];
#pragma unroll
    for (int i = 0; i < 2; i++)
#pragma unroll
        for (int j = 0; j < 2; j++) {
#pragma unroll
            for (int q = 0; q < 4; q++) acc[i][j][q] = 0.f;
            hacc[i][j][0] = 0u; hacc[i][j][1] = 0u;
        }

    const __half* Ah0 = g_Anh + (size_t)b * 262144 + (size_t)m0 * 512;
    const __half* Bh0 = g_hTh[hin] + (size_t)b * 65536 + (size_t)n0 * 512;
    const __half* Bl0 = g_hTl[hin] + (size_t)b * 65536 + (size_t)n0 * 512;

    auto stg = [&](int cc) -> uint32_t { return sbase + (uint32_t)(cc % 3) * GH_STG; };

    auto issue = [&](int cc) {
        uint32_t buf = stg(cc);
        int kc = cc * 64;
#pragma unroll
        for (int i = 0; i < 2; i++) {
            int idx = tid + i * 256, r = idx >> 3, c = idx & 7;
            uint32_t d = buf + r * RS + c * 16;
            size_t off = (size_t)r * 512 + kc + c * 8;
            cpa16(d,            Ah0 + off);
            cpa16(d + GH_T,     Bh0 + off);
            cpa16(d + 2 * GH_T, Bl0 + off);
        }
    };

    issue(0); CP_COMMIT();
    issue(1); CP_COMMIT();

#pragma unroll 1
    for (int cc = 0; cc < 8; cc++) {
        CP_WAIT1();
        __syncthreads();

        uint32_t buf = stg(cc);
        uint32_t aH = buf + (uint32_t)(wm * 32 + (lane & 15)) * RS + ((lane >> 4) * 16);
        uint32_t bH = buf + GH_T
                    + (uint32_t)(wn * 16 + (lane & 7) + ((lane >> 4) & 1) * 8) * RS
                    + (((lane >> 3) & 1) * 16);
        uint32_t bL = bH + GH_T;
#pragma unroll
        for (int ks = 0; ks < 4; ks++) {
            uint32_t ah[2][4], bh[4], bl[4];
            ldsm4(ah[0], aH + ks * 32); ldsm4(ah[1], aH + 16 * RS + ks * 32);
            ldsm4(bh, bH + ks * 32);
            ldsm4(bl, bL + ks * 32);
#pragma unroll
            for (int mf = 0; mf < 2; mf++) {
                mmaf(acc[mf][0], ah[mf], &bh[0]); mmaf(acc[mf][1], ah[mf], &bh[2]);
                mmah(hacc[mf][0], ah[mf], &bl[0]); mmah(hacc[mf][1], ah[mf], &bl[2]);
            }
        }
        __syncthreads();
        if (cc + 2 < 8) { issue(cc + 2); CP_COMMIT(); }
    }
    CP_WAIT0();

    // epilogue: H fp16 only
    int rbase = b * 512 + m0 + wm * 32 + (lane >> 2);
    int cbase = n0 + wn * 16 + (lane & 3) * 2;
#pragma unroll
    for (int mf = 0; mf < 2; mf++) {
#pragma unroll
        for (int nf = 0; nf < 2; nf++) {
            int col = cbase + nf * 8;
            float* d = acc[mf][nf];
            hmerge(d, hacc[mf][nf]);
            int r0 = rbase + mf * 16;
            *(__half2*)(g_Hh + (size_t)r0 * 128 + col) =
                __halves2half2(__float2half_rn(d[0]), __float2half_rn(d[1]));
            *(__half2*)(g_Hh + (size_t)(r0 + 8) * 128 + col) =
                __halves2half2(__float2half_rn(d[2]), __float2half_rn(d[3]));
        }
    }
}

// ---------------------------------------------------------------------------
// phase gG (barrier-overlapped): gates = Ges + [H | h] @ Wcomb, 128x128 tiles.
// A is fp16-only (no lo corrections); weight-lo corrections kept.
// Part 1 (before bar wait): chunks 2,3 = h(t-1)-part.  Part 2: chunks 0,1 + epi.
// ---------------------------------------------------------------------------
__device__ __forceinline__ void phase_gG(char* dsm, int hin, int hout, int cta, int tid,
                                         unsigned wait_gen) {
    uint32_t sbase = smem_u32(dsm);
    int wid = tid >> 5, lane = tid & 31;
    int wm = wid >> 2, wn = wid & 3;
    int m0 = (cta >> 2) * 128;
    int n0 = (cta & 3) * 128;

    float acc[4][4][4];
    uint32_t hacc[4][4][2];
#pragma unroll
    for (int i = 0; i < 4; i++)
#pragma unroll
        for (int j = 0; j < 4; j++) {
#pragma unroll
            for (int q = 0; q < 4; q++) acc[i][j][q] = 0.f;
            hacc[i][j][0] = 0u; hacc[i][j][1] = 0u;
        }

    auto issue = [&](int cc, uint32_t buf) {
        int kc = cc * 64;
        const __half* Ahs = (kc < 128)
            ? g_Hh + (size_t)m0 * 128 + kc
            : g_hrh[hin] + (size_t)m0 * 128 + (kc - 128);
#pragma unroll
        for (int i = 0; i < 4; i++) {
            int idx = tid + i * 256, r = idx >> 3, c = idx & 7;
            cpa16(buf + r * RS + c * 16, Ahs + (size_t)r * 128 + c * 8);
        }
    };

    uint32_t wtH = sbase + SM_WT
                 + (uint32_t)(wn * 32 + (lane & 7) + ((lane >> 4) & 1) * 8) * WT_RSB
                 + (((lane >> 3) & 1) * 16);
    uint32_t wtL = wtH + WT_SZ;

    auto compute = [&](int cc, uint32_t buf) {
        uint32_t aH = buf + (uint32_t)(wm * 64 + (lane & 15)) * RS + ((lane >> 4) * 16);
        uint32_t kb = (uint32_t)cc * 128;
#pragma unroll
        for (int ks = 0; ks < 4; ks++) {
            uint32_t ah[4][4], bh0[4], bh1[4], bl0[4], bl1[4];
#pragma unroll
            for (int mf = 0; mf < 4; mf++)
                ldsm4(ah[mf], aH + mf * 16 * RS + ks * 32);
            ldsm4(bh0, wtH + kb + ks * 32);
            ldsm4(bh1, wtH + 16 * WT_RSB + kb + ks * 32);
            ldsm4(bl0, wtL + kb + ks * 32);
            ldsm4(bl1, wtL + 16 * WT_RSB + kb + ks * 32);
#pragma unroll
            for (int mf = 0; mf < 4; mf++) {
                mmaf(acc[mf][0], ah[mf], &bh0[0]); mmaf(acc[mf][1], ah[mf], &bh0[2]);
                mmaf(acc[mf][2], ah[mf], &bh1[0]); mmaf(acc[mf][3], ah[mf], &bh1[2]);
                mmah(hacc[mf][0], ah[mf], &bl0[0]); mmah(hacc[mf][1], ah[mf], &bl0[2]);
                mmah(hacc[mf][2], ah[mf], &bl1[0]); mmah(hacc[mf][3], ah[mf], &bl1[2]);
            }
        }
    };

    // ---- part 1: h-part chunks (2,3) — no dependence on this step's H
    issue(2, sbase);            CP_COMMIT();
    issue(3, sbase + GG_STG);   CP_COMMIT();
    CP_WAIT1();
    __syncthreads();
    compute(2, sbase);
    CP_WAIT0();
    __syncthreads();
    compute(3, sbase + GG_STG);

    // ---- barrier wait: H(t) complete grid-wide
    gbar_wait(wait_gen);

    // ---- part 2: H-part chunks (0,1)
    issue(0, sbase);            CP_COMMIT();
    issue(1, sbase + GG_STG);   CP_COMMIT();
    CP_WAIT1();
    __syncthreads();
    compute(0, sbase);
    CP_WAIT0();
    __syncthreads();
    compute(1, sbase + GG_STG);
    __syncthreads();

    // stage fp32 gate tile (with corrections merged) in smem
    float* cst = (float*)dsm;   // [128][132]
#pragma unroll
    for (int mf = 0; mf < 4; mf++) {
#pragma unroll
        for (int nf = 0; nf < 4; nf++) {
            int row = wm * 64 + mf * 16 + (lane >> 2);
            int col = wn * 32 + nf * 8 + (lane & 3) * 2;
            float* d = acc[mf][nf];
            hmerge(d, hacc[mf][nf]);
            *(float2*)&cst[row * 132 + col]       = make_float2(d[0], d[1]);
            *(float2*)&cst[(row + 8) * 132 + col] = make_float2(d[2], d[3]);
        }
    }
    __syncthreads();

    // pass 1: gates -> c, h (h in regs)
    float hv16[16];
    int q  = tid & 31;
    int rb = tid >> 5;
    int j  = (n0 >> 2) + q;
    __half* hrho = g_hrh[hout];
    __half* hrlo = g_hrl[hout];
#pragma unroll
    for (int i = 0; i < 16; i++) {
        int r = rb + i * 8;
        int rr = m0 + r;
        float4 pv = *(float4*)&cst[r * 132 + q * 4];
        float4 ge = *(const float4*)&g_Ges[(size_t)rr * 512 + j * 4];
        float iv = sigm(pv.x + ge.x), fv = sigm(pv.y + ge.y);
        float gv = ftanh(pv.z + ge.z), ov = sigm(pv.w + ge.w);
        size_t cidx = (size_t)rr * 128 + j;
        float cc = fv * g_c[cidx] + iv * gv;
        g_c[cidx] = cc;
        float hv = ov * ftanh(cc);
        hv16[i] = hv;
        __half hh, ll;
        hsplit(hv, hh, ll);
        hrho[cidx] = hh;
        hrlo[cidx] = ll;
    }
    __syncthreads();   // cst dead

    // pass 2: smem transpose (32 features x 128 rows)
    __half* trh = (__half*)dsm;            // [32][136]
    __half* trl = (__half*)(dsm + 8704);
#pragma unroll
    for (int i = 0; i < 16; i++) {
        int r = rb + i * 8;
        __half hh, ll;
        hsplit(hv16[i], hh, ll);
        trh[q * 136 + r] = hh;
        trl[q * 136 + r] = ll;
    }
    __syncthreads();

    // pass 3: coalesced hT writes
    __half* hTh = g_hTh[hout];
    __half* hTl = g_hTl[hout];
    int bb = m0 >> 9, nn0 = m0 & 511;
    int jr = tid >> 4, ch = tid & 15;
#pragma unroll
    for (int half = 0; half < 2; half++) {
        int jj = jr + half * 16;
        uint4 vh = *(uint4*)&trh[jj * 136 + ch * 8];
        uint4 vl = *(uint4*)&trl[jj * 136 + ch * 8];
        size_t base = (size_t)(bb * 128 + (n0 >> 2) + jj) * 512 + nn0 + ch * 8;
        *(uint4*)&hTh[base] = vh;
        *(uint4*)&hTl[base] = vl;
    }
    __syncthreads();
}

// ---------------------------------------------------------------------------
// phase out (tensor-core): Xi += h @ Wout + bout ; emit out[:, :, t, :]
// ---------------------------------------------------------------------------
__device__ __forceinline__ void phase_out(char* dsm, int t, int hidx,
                                          const float* __restrict__ bout,
                                          float* __restrict__ out, int cta, int tid) {
    uint32_t sbase = smem_u32(dsm);
    int wid = tid >> 5, lane = tid & 31;
    int mw = wid & 1, nw = wid >> 1;
    int row0 = cta * 32;
    __syncthreads();

    {
        const __half* hh = g_hrh[hidx] + (size_t)row0 * 128;
        const __half* hl = g_hrl[hidx] + (size_t)row0 * 128;
#pragma unroll
        for (int i = 0; i < 2; i++) {
            int idx = tid + i * 256, r = idx >> 4, c = idx & 15;
            cpa16(sbase + OUT_HA  + r * OUT_RSB + c * 16, hh + (size_t)r * 128 + c * 8);
            cpa16(sbase + OUT_HAL + r * OUT_RSB + c * 16, hl + (size_t)r * 128 + c * 8);
        }
#pragma unroll
        for (int i = 0; i < 4; i++) {
            int idx = tid + i * 256, r = idx >> 4, c = idx & 15;
            cpa16(sbase + OUT_WB  + r * OUT_RSB + c * 16, g_WoTh + (size_t)r * 128 + c * 8);
            cpa16(sbase + OUT_WBL + r * OUT_RSB + c * 16, g_WoTl + (size_t)r * 128 + c * 8);
        }
        CP_COMMIT();
    }

    int rA = row0 + mw * 16 + (lane >> 2);
    int cA = nw * 16 + (lane & 3) * 2;
    float2 xi[2][2], bo[2];
#pragma unroll
    for (int nf = 0; nf < 2; nf++) {
        int col = cA + nf * 8;
        xi[nf][0] = *(const float2*)&g_Xi[rA * 64 + col];
        xi[nf][1] = *(const float2*)&g_Xi[(rA + 8) * 64 + col];
        bo[nf] = *(const float2*)&bout[col];
    }

    CP_WAIT0();
    __syncthreads();

    uint32_t aH = sbase + OUT_HA + (uint32_t)(mw * 16 + (lane & 15)) * OUT_RSB + ((lane >> 4) * 16);
    uint32_t aL = aH + (OUT_HAL - OUT_HA);
    uint32_t bH = sbase + OUT_WB
                + (uint32_t)(nw * 16 + (lane & 7) + ((lane >> 4) & 1) * 8) * OUT_RSB
                + (((lane >> 3) & 1) * 16);
    uint32_t bL = bH + (OUT_WBL - OUT_WB);

    float acc[2][4] = {};
    uint32_t hacc[2][2] = {};
#pragma unroll
    for (int ks = 0; ks < 8; ks++) {
        uint32_t ah[4], al[4], bh[4], bl[4];
        ldsm4(ah, aH + ks * 32);
        ldsm4(al, aL + ks * 32);
        ldsm4(bh, bH + ks * 32);
        ldsm4(bl, bL + ks * 32);
        mmaf(acc[0], ah, &bh[0]); mmaf(acc[1], ah, &bh[2]);
        mmah(hacc[0], al, &bh[0]); mmah(hacc[1], al, &bh[2]);
        mmah(hacc[0], ah, &bl[0]); mmah(hacc[1], ah, &bl[2]);
    }

#pragma unroll
    for (int nf = 0; nf < 2; nf++) {
        hmerge(acc[nf], hacc[nf]);
        int col = cA + nf * 8;
        float2 v0 = make_float2(acc[nf][0] + xi[nf][0].x + bo[nf].x,
                                acc[nf][1] + xi[nf][0].y + bo[nf].y);
        float2 v1 = make_float2(acc[nf][2] + xi[nf][1].x + bo[nf].x,
                                acc[nf][3] + xi[nf][1].y + bo[nf].y);
        *(float2*)&g_Xi[rA * 64 + col] = v0;
        *(float2*)&g_Xi[(rA + 8) * 64 + col] = v1;
        *(float2*)&out[(size_t)rA * 4096 + t * 64 + col] = v0;
        *(float2*)&out[(size_t)(rA + 8) * 4096 + t * 64 + col] = v1;
    }
    __syncthreads();
}

// ---------------------------------------------------------------------------
// k_main: persistent kernel, 63 steps.
// gH -> arrive -> out(t-1) -> gG(h-part, wait, H-part) -> bar2
// ---------------------------------------------------------------------------
__global__ void __launch_bounds__(256) k_main(const float* __restrict__ bout,
                                              float* __restrict__ out) {
    extern __shared__ __align__(16) char dsm[];
    int cta = blockIdx.x, tid = threadIdx.x;

    // persistent weight slice for this CTA's gG n-tile
    {
        int n0 = (cta & 3) * 128;
        uint32_t wt = smem_u32(dsm) + SM_WT;
#pragma unroll
        for (int i = 0; i < 16; i++) {
            int idx = tid + i * 256;
            int r = idx >> 5, c = idx & 31;
            cpa16(wt + r * WT_RSB + c * 16,         g_WTh + (size_t)(n0 + r) * 256 + c * 8);
            cpa16(wt + WT_SZ + r * WT_RSB + c * 16, g_WTl + (size_t)(n0 + r) * 256 + c * 8);
        }
        CP_COMMIT();
        CP_WAIT0();
    }
    __syncthreads();

    unsigned gen = 0;
#pragma unroll 1
    for (int t = 1; t < Tc; t++) {
        int hin = (t - 1) & 1, hout = t & 1;
        phase_gH(dsm, hin, cta, tid);
        ++gen;
        gbar_arrive(gen);                            // bar1: this CTA's H done
        if (t >= 2) phase_out(dsm, t - 1, hin, bout, out, cta, tid);
        phase_gG(dsm, hin, hout, cta, tid, gen);     // h-part + out overlap bar1 wait
        gbar(++gen);                                 // bar2: h(t) complete
    }
    phase_out(dsm, Tc - 1, (Tc - 1) & 1, bout, out, cta, tid);
}

// ---------------------------------------------------------------------------
extern "C" void kernel_launch(void* const* d_in, const int* in_sizes, int n_in,
                              void* d_out, int out_size) {
    const float* X    = (const float*)d_in[0];
    const float* A    = (const float*)d_in[1];
    const float* Wse  = (const float*)d_in[2];
    const float* bse  = (const float*)d_in[3];
    const float* Wpe  = (const float*)d_in[4];
    const float* bpe  = (const float*)d_in[5];
    const float* Wii  = (const float*)d_in[6];
    const float* bii  = (const float*)d_in[7];
    const float* Whi  = (const float*)d_in[8];
    const float* bhi  = (const float*)d_in[9];
    const float* Wif  = (const float*)d_in[10];
    const float* bif_ = (const float*)d_in[11];
    const float* Whf  = (const float*)d_in[12];
    const float* bhf  = (const float*)d_in[13];
    const float* Wig  = (const float*)d_in[14];
    const float* big_ = (const float*)d_in[15];
    const float* Whg  = (const float*)d_in[16];
    const float* bhg  = (const float*)d_in[17];
    const float* Wio  = (const float*)d_in[18];
    const float* bio  = (const float*)d_in[19];
    const float* Who  = (const float*)d_in[20];
    const float* bho  = (const float*)d_in[21];
    const float* Wout = (const float*)d_in[22];
    const float* bout = (const float*)d_in[23];
    float* out = (float*)d_out;

    cudaFuncSetAttribute(k_main, cudaFuncAttributeMaxDynamicSharedMemorySize, SM_TOTAL);

    k_dinv<<<Rc, 128>>>(A);
    k_an<<<2048, 256>>>(A);
    k_prep<<<512, 128>>>(Wii, bii, Whi, bhi, Wif, bif_, Whf, bhf,
                         Wig, big_, Whg, bhg, Wio, bio, Who, bho, Wpe, bpe);
    k_init<<<Rc, 128>>>(X, Wse, bse, Wout, out);
    k_ges<<<256, 256>>>();
    k_main<<<NCTA, 256, SM_TOTAL>>>(bout, out);
}

// round 12
// speedup vs baseline: 1.3729x; 1.1088x over previous
#include <cuda_runtime.h>
#include <cuda_fp16.h>
#include <math.h>
#include <stdint.h>

// Problem constants
#define Bc   8
#define Nc   512
#define Tc   64
#define NINc 64
#define NHc  128
#define Rc   (Bc * Nc)   // 4096 rows
#define NCTA 128

// ---------------- scratch (device globals) ----------------------------------
__device__ float g_dinv[Rc];
__device__ __half g_Anh[Bc * Nc * Nc];          // An fp16 (4 MB)
__device__ float g_es[Rc * NHc];                // static embedding fp32
__device__ float g_Wes[128 * 512];              // Wi[0:128] interleaved fp32
__device__ float g_bbig[512];
__device__ float g_Ges[Rc * 512];               // es @ Wes + bbig (fp32, interleaved)
__device__ __half g_WTh[512 * 256];             // Wcomb^T hi: [n][k]
__device__ __half g_WTl[512 * 256];             // Wcomb^T lo (weight corr kept)
__device__ __half g_WoTh[64 * 128];             // Wout^T hi: [n][k]
__device__ __half g_WoTl[64 * 128];             // Wout^T lo (weight corr kept)
__device__ __half g_Hh[Rc * NHc];               // H = An@h, fp16, row-major
__device__ __half g_hrh[2][Rc * NHc];           // h row-major fp16 (double buffered)
__device__ __half g_hTh[2][Bc * NHc * Nc];      // h transposed per batch [b][j][n]
__device__ float g_c[Rc * NHc];                 // cell state
__device__ float g_Xi[Rc * NINc];               // running output accumulator
__device__ unsigned g_count;                    // grid barrier arrive counter
__device__ unsigned g_sense;                    // grid barrier generation

// ---------------- helpers ----------------------------------------------------
__device__ __forceinline__ uint32_t smem_u32(const void* p) {
    uint32_t a;
    asm("{ .reg .u64 t; cvta.to.shared.u64 t, %1; cvt.u32.u64 %0, t; }" : "=r"(a) : "l"(p));
    return a;
}
// fast sigmoid / tanh via MUFU paths
__device__ __forceinline__ float sigm(float x) {
    return __fdividef(1.f, 1.f + __expf(-x));
}
__device__ __forceinline__ float ftanh(float x) {
    float e = __expf(2.f * x);
    return 1.f - __fdividef(2.f, e + 1.f);
}
__device__ __forceinline__ void hsplit(float v, __half& hi, __half& lo) {
    hi = __float2half_rn(v);
    lo = __float2half_rn(v - __half2float(hi));
}
__device__ __forceinline__ void cpa16(uint32_t dst, const void* src) {
    asm volatile("cp.async.cg.shared.global [%0], [%1], 16;" :: "r"(dst), "l"(src) : "memory");
}
#define CP_COMMIT() asm volatile("cp.async.commit_group;" ::: "memory")
#define CP_WAIT1()  asm volatile("cp.async.wait_group 1;" ::: "memory")
#define CP_WAIT0()  asm volatile("cp.async.wait_group 0;" ::: "memory")

__device__ __forceinline__ void ldsm4(uint32_t* r, uint32_t a) {
    asm volatile("ldmatrix.sync.aligned.m8n8.x4.shared.b16 {%0,%1,%2,%3}, [%4];"
        : "=r"(r[0]), "=r"(r[1]), "=r"(r[2]), "=r"(r[3]) : "r"(a));
}
// main pass: fp16 operands, fp32 accumulator
__device__ __forceinline__ void mmaf(float* d, const uint32_t* a, const uint32_t* b) {
    asm volatile("mma.sync.aligned.m16n8k16.row.col.f32.f16.f16.f32 "
        "{%0,%1,%2,%3}, {%4,%5,%6,%7}, {%8,%9}, {%0,%1,%2,%3};"
        : "+f"(d[0]), "+f"(d[1]), "+f"(d[2]), "+f"(d[3])
        : "r"(a[0]), "r"(a[1]), "r"(a[2]), "r"(a[3]), "r"(b[0]), "r"(b[1]));
}
// correction pass: fp16 accumulator
__device__ __forceinline__ void mmah(uint32_t* d, const uint32_t* a, const uint32_t* b) {
    asm volatile("mma.sync.aligned.m16n8k16.row.col.f16.f16.f16.f16 "
        "{%0,%1}, {%2,%3,%4,%5}, {%6,%7}, {%0,%1};"
        : "+r"(d[0]), "+r"(d[1])
        : "r"(a[0]), "r"(a[1]), "r"(a[2]), "r"(a[3]), "r"(b[0]), "r"(b[1]));
}
__device__ __forceinline__ void hmerge(float* d, const uint32_t* h) {
    __half2 q0 = *(const __half2*)&h[0];
    __half2 q1 = *(const __half2*)&h[1];
    d[0] += __half2float(q0.x); d[1] += __half2float(q0.y);
    d[2] += __half2float(q1.x); d[3] += __half2float(q1.y);
}

// grid-wide sense barrier, split into arrive / wait halves
__device__ __forceinline__ void gbar_arrive(unsigned gen) {
    __syncthreads();
    if (threadIdx.x == 0) {
        unsigned prev;
        asm volatile("atom.release.gpu.add.u32 %0, [%1], %2;"
                     : "=r"(prev) : "l"(&g_count), "r"(1u) : "memory");
        if (prev == NCTA - 1) {
            g_count = 0u;
            asm volatile("st.release.gpu.u32 [%0], %1;" :: "l"(&g_sense), "r"(gen) : "memory");
        }
    }
}
__device__ __forceinline__ void gbar_wait(unsigned gen) {
    if (threadIdx.x == 0) {
        unsigned s;
        do {
            asm volatile("ld.acquire.gpu.u32 %0, [%1];" : "=r"(s) : "l"(&g_sense) : "memory");
        } while (s < gen);
    }
    __syncthreads();
}
__device__ __forceinline__ void gbar(unsigned gen) {
    gbar_arrive(gen);
    gbar_wait(gen);
}

#define RS 144          // stage tile row stride (72 halves)
#define GH_T   9216     // gH tile: 64 rows x RS
#define GH_STG 18432    // gH stage: Ah | Bh
#define GG_T   18432    // gG tile: 128 rows x RS
#define GG_STG 18432    // gG stage: Ah only
#define SM_WT    82944
#define WT_RSB   528
#define WT_SZ    67584
#define SM_TOTAL (SM_WT + 2 * WT_SZ)   // 218112
// out-phase stage offsets (within stage region)
#define OUT_RSB  272
#define OUT_HA   0
#define OUT_WB   8704
#define OUT_WBL  26112

// ---------------------------------------------------------------------------
__global__ void k_dinv(const float* __restrict__ A) {
    int row = blockIdx.x;
    const float* arow = A + (size_t)row * Nc;
    float s = 0.f;
    for (int j = threadIdx.x; j < Nc; j += blockDim.x) s += arow[j];
    __shared__ float sh[128];
    sh[threadIdx.x] = s;
    __syncthreads();
    for (int off = 64; off > 0; off >>= 1) {
        if (threadIdx.x < off) sh[threadIdx.x] += sh[threadIdx.x + off];
        __syncthreads();
    }
    if (threadIdx.x == 0) {
        float d = sh[0];
        g_dinv[row] = (d > 0.f) ? rsqrtf(d) : 0.f;
    }
}

__global__ void k_an(const float* __restrict__ A) {
    int idx = blockIdx.x * blockDim.x + threadIdx.x;
    int e = idx * 4;
    int b   = e >> 18;
    int rem = e & 262143;
    int i   = rem >> 9;
    int j   = rem & 511;
    float4 a = *(const float4*)(A + (size_t)e);
    float di = g_dinv[b * 512 + i];
    const float* dj = g_dinv + b * 512 + j;
    __half2* ph = (__half2*)(g_Anh + (size_t)e);
    ph[0] = __halves2half2(__float2half_rn(a.x * di * dj[0]),
                           __float2half_rn(a.y * di * dj[1]));
    ph[1] = __halves2half2(__float2half_rn(a.z * di * dj[2]),
                           __float2half_rn(a.w * di * dj[3]));
}

// ---------------------------------------------------------------------------
__global__ void k_prep(const float* __restrict__ Wii, const float* __restrict__ bii,
                       const float* __restrict__ Whi, const float* __restrict__ bhi,
                       const float* __restrict__ Wif, const float* __restrict__ bif_,
                       const float* __restrict__ Whf, const float* __restrict__ bhf,
                       const float* __restrict__ Wig, const float* __restrict__ big_,
                       const float* __restrict__ Whg, const float* __restrict__ bhg,
                       const float* __restrict__ Wio, const float* __restrict__ bio,
                       const float* __restrict__ Who, const float* __restrict__ bho,
                       const float* __restrict__ Wpe, const float* __restrict__ bpe) {
    int n = blockIdx.x;
    int g = n & 3;
    int j = n >> 2;
    int t = threadIdx.x;
    const float* Wi = (g == 0) ? Wii : (g == 1) ? Wif : (g == 2) ? Wig : Wio;
    const float* Wh = (g == 0) ? Whi : (g == 1) ? Whf : (g == 2) ? Whg : Who;
    const float* bi = (g == 0) ? bii : (g == 1) ? bif_ : (g == 2) ? big_ : bio;
    const float* bh = (g == 0) ? bhi : (g == 1) ? bhf : (g == 2) ? bhg : bho;

    __shared__ float wcol[128];
    wcol[t] = Wi[(128 + t) * 128 + j];
    __syncthreads();

    g_Wes[t * 512 + n] = Wi[t * 128 + j];

    float acc = 0.f;
    const float* wpet = Wpe + t * 128;
#pragma unroll 8
    for (int m = 0; m < 128; m++) acc += wpet[m] * wcol[m];

    __half hh, ll;
    hsplit(acc, hh, ll);
    g_WTh[n * 256 + t] = hh;
    g_WTl[n * 256 + t] = ll;
    float whv = Wh[t * 128 + j];
    hsplit(whv, hh, ll);
    g_WTh[n * 256 + 128 + t] = hh;
    g_WTl[n * 256 + 128 + t] = ll;

    if (t == 0) {
        float ba = bi[j] + bh[j];
        for (int m = 0; m < 128; m++) ba += bpe[m] * wcol[m];
        g_bbig[n] = ba;
    }
}

// ---------------------------------------------------------------------------
// k_init: es = X0@Wse + bse ; zero h & c ; Xi = X0 ; out t=0 ; barrier reset ;
//         WoutT hi/lo
// ---------------------------------------------------------------------------
__global__ void k_init(const float* __restrict__ X, const float* __restrict__ Wse,
                       const float* __restrict__ bse, const float* __restrict__ Wout,
                       float* __restrict__ out) {
    int row = blockIdx.x;
    int t = threadIdx.x;
    if (row == 0 && t == 0) { g_count = 0u; g_sense = 0u; }
    if (row < 64) {
        __half hh, ll;
        hsplit(Wout[t * 64 + row], hh, ll);
        g_WoTh[row * 128 + t] = hh;
        g_WoTl[row * 128 + t] = ll;
    }
    __shared__ float x0[64];
    if (t < 64) {
        float v = X[(size_t)row * 4096 + t];
        x0[t] = v;
        g_Xi[row * 64 + t] = v;
        out[(size_t)row * 4096 + t] = v;
    }
    __syncthreads();
    float acc = bse[t];
#pragma unroll 8
    for (int k = 0; k < 64; k++) acc += x0[k] * Wse[k * 128 + t];
    g_es[row * 128 + t] = acc;

    __half z = __float2half(0.f);
    g_hrh[0][(size_t)row * 128 + t] = z;
    int bb = row >> 9, nn = row & 511;
    g_hTh[0][(size_t)(bb * 128 + t) * 512 + nn] = z;
    g_c[row * 128 + t] = 0.f;
}

// ---------------------------------------------------------------------------
// k_ges: Ges = es @ Wes + bbig (4096 x 512, K=128) fp32, runs once
// ---------------------------------------------------------------------------
__global__ void __launch_bounds__(256) k_ges() {
    int m0 = (blockIdx.x >> 2) * 64;
    int n0 = (blockIdx.x & 3) * 128;

    __shared__ __align__(16) float As[16][68];
    __shared__ __align__(16) float Bs[16][132];

    int tid = threadIdx.x;
    int ty = tid >> 4, tx = tid & 15;
    int ar = tid >> 2, ac = (tid & 3) * 4;
    int br = tid >> 5, bc = (tid & 31) * 4;

    float acc[4][8] = {};

    for (int k0 = 0; k0 < 128; k0 += 16) {
        float4 av = *(const float4*)&g_es[(size_t)(m0 + ar) * 128 + k0 + ac];
        float4 bv0 = *(const float4*)&g_Wes[(size_t)(k0 + br) * 512 + n0 + bc];
        float4 bv1 = *(const float4*)&g_Wes[(size_t)(k0 + br + 8) * 512 + n0 + bc];
        As[ac + 0][ar] = av.x; As[ac + 1][ar] = av.y;
        As[ac + 2][ar] = av.z; As[ac + 3][ar] = av.w;
        *(float4*)&Bs[br][bc] = bv0;
        *(float4*)&Bs[br + 8][bc] = bv1;
        __syncthreads();
#pragma unroll
        for (int kk = 0; kk < 16; kk++) {
            float4 a4 = *(const float4*)&As[kk][ty * 4];
            float4 b0 = *(const float4*)&Bs[kk][tx * 8];
            float4 b1 = *(const float4*)&Bs[kk][tx * 8 + 4];
            float av4[4] = { a4.x, a4.y, a4.z, a4.w };
            float bv8[8] = { b0.x, b0.y, b0.z, b0.w, b1.x, b1.y, b1.z, b1.w };
#pragma unroll
            for (int i = 0; i < 4; i++)
#pragma unroll
                for (int jq = 0; jq < 8; jq++) acc[i][jq] += av4[i] * bv8[jq];
        }
        __syncthreads();
    }

    float bb[8];
#pragma unroll
    for (int q = 0; q < 8; q++) bb[q] = g_bbig[n0 + tx * 8 + q];
#pragma unroll
    for (int r = 0; r < 4; r++) {
        int rr = m0 + ty * 4 + r;
        float* dst = &g_Ges[(size_t)rr * 512 + n0 + tx * 8];
#pragma unroll
        for (int q = 0; q < 8; q++) dst[q] = acc[r][q] + bb[q];
    }
}

// ---------------------------------------------------------------------------
// phase gH: H = An @ h, CTA tile 64x64 (8b x 8m x 2n = 128 tiles)
// Pure fp16 operands (An, hT), fp32 acc. 3-stage pipeline, 2 streams.
// ---------------------------------------------------------------------------
__device__ __forceinline__ void phase_gH(char* dsm, int hin, int cta, int tid) {
    uint32_t sbase = smem_u32(dsm);
    int wid = tid >> 5, lane = tid & 31;
    int wm = wid >> 2, wn = wid & 3;
    int b  = cta >> 4;
    int m0 = ((cta >> 1) & 7) * 64;
    int n0 = (cta & 1) * 64;

    float acc[2][2][4];
#pragma unroll
    for (int i = 0; i < 2; i++)
#pragma unroll
        for (int j = 0; j < 2; j++)
#pragma unroll
            for (int q = 0; q < 4; q++) acc[i][j][q] = 0.f;

    const __half* Ah0 = g_Anh + (size_t)b * 262144 + (size_t)m0 * 512;
    const __half* Bh0 = g_hTh[hin] + (size_t)b * 65536 + (size_t)n0 * 512;

    auto stg = [&](int cc) -> uint32_t { return sbase + (uint32_t)(cc % 3) * GH_STG; };

    auto issue = [&](int cc) {
        uint32_t buf = stg(cc);
        int kc = cc * 64;
#pragma unroll
        for (int i = 0; i < 2; i++) {
            int idx = tid + i * 256, r = idx >> 3, c = idx & 7;
            uint32_t d = buf + r * RS + c * 16;
            size_t off = (size_t)r * 512 + kc + c * 8;
            cpa16(d,        Ah0 + off);
            cpa16(d + GH_T, Bh0 + off);
        }
    };

    issue(0); CP_COMMIT();
    issue(1); CP_COMMIT();

#pragma unroll 1
    for (int cc = 0; cc < 8; cc++) {
        CP_WAIT1();
        __syncthreads();

        uint32_t buf = stg(cc);
        uint32_t aH = buf + (uint32_t)(wm * 32 + (lane & 15)) * RS + ((lane >> 4) * 16);
        uint32_t bH = buf + GH_T
                    + (uint32_t)(wn * 16 + (lane & 7) + ((lane >> 4) & 1) * 8) * RS
                    + (((lane >> 3) & 1) * 16);
#pragma unroll
        for (int ks = 0; ks < 4; ks++) {
            uint32_t ah[2][4], bh[4];
            ldsm4(ah[0], aH + ks * 32); ldsm4(ah[1], aH + 16 * RS + ks * 32);
            ldsm4(bh, bH + ks * 32);
#pragma unroll
            for (int mf = 0; mf < 2; mf++) {
                mmaf(acc[mf][0], ah[mf], &bh[0]); mmaf(acc[mf][1], ah[mf], &bh[2]);
            }
        }
        __syncthreads();
        if (cc + 2 < 8) { issue(cc + 2); CP_COMMIT(); }
    }
    CP_WAIT0();

    // epilogue: H fp16
    int rbase = b * 512 + m0 + wm * 32 + (lane >> 2);
    int cbase = n0 + wn * 16 + (lane & 3) * 2;
#pragma unroll
    for (int mf = 0; mf < 2; mf++) {
#pragma unroll
        for (int nf = 0; nf < 2; nf++) {
            int col = cbase + nf * 8;
            float* d = acc[mf][nf];
            int r0 = rbase + mf * 16;
            *(__half2*)(g_Hh + (size_t)r0 * 128 + col) =
                __halves2half2(__float2half_rn(d[0]), __float2half_rn(d[1]));
            *(__half2*)(g_Hh + (size_t)(r0 + 8) * 128 + col) =
                __halves2half2(__float2half_rn(d[2]), __float2half_rn(d[3]));
        }
    }
}

// ---------------------------------------------------------------------------
// phase gG (barrier-overlapped): gates = Ges + [H | h] @ Wcomb, 128x128 tiles.
// A fp16-only; weight-lo corrections kept.
// Part 1 (before bar wait): chunks 2,3 = h(t-1)-part.  Part 2: chunks 0,1 + epi.
// ---------------------------------------------------------------------------
__device__ __forceinline__ void phase_gG(char* dsm, int hin, int hout, int cta, int tid,
                                         unsigned wait_gen) {
    uint32_t sbase = smem_u32(dsm);
    int wid = tid >> 5, lane = tid & 31;
    int wm = wid >> 2, wn = wid & 3;
    int m0 = (cta >> 2) * 128;
    int n0 = (cta & 3) * 128;

    float acc[4][4][4];
    uint32_t hacc[4][4][2];
#pragma unroll
    for (int i = 0; i < 4; i++)
#pragma unroll
        for (int j = 0; j < 4; j++) {
#pragma unroll
            for (int q = 0; q < 4; q++) acc[i][j][q] = 0.f;
            hacc[i][j][0] = 0u; hacc[i][j][1] = 0u;
        }

    auto issue = [&](int cc, uint32_t buf) {
        int kc = cc * 64;
        const __half* Ahs = (kc < 128)
            ? g_Hh + (size_t)m0 * 128 + kc
            : g_hrh[hin] + (size_t)m0 * 128 + (kc - 128);
#pragma unroll
        for (int i = 0; i < 4; i++) {
            int idx = tid + i * 256, r = idx >> 3, c = idx & 7;
            cpa16(buf + r * RS + c * 16, Ahs + (size_t)r * 128 + c * 8);
        }
    };

    uint32_t wtH = sbase + SM_WT
                 + (uint32_t)(wn * 32 + (lane & 7) + ((lane >> 4) & 1) * 8) * WT_RSB
                 + (((lane >> 3) & 1) * 16);
    uint32_t wtL = wtH + WT_SZ;

    auto compute = [&](int cc, uint32_t buf) {
        uint32_t aH = buf + (uint32_t)(wm * 64 + (lane & 15)) * RS + ((lane >> 4) * 16);
        uint32_t kb = (uint32_t)cc * 128;
#pragma unroll
        for (int ks = 0; ks < 4; ks++) {
            uint32_t ah[4][4], bh0[4], bh1[4], bl0[4], bl1[4];
#pragma unroll
            for (int mf = 0; mf < 4; mf++)
                ldsm4(ah[mf], aH + mf * 16 * RS + ks * 32);
            ldsm4(bh0, wtH + kb + ks * 32);
            ldsm4(bh1, wtH + 16 * WT_RSB + kb + ks * 32);
            ldsm4(bl0, wtL + kb + ks * 32);
            ldsm4(bl1, wtL + 16 * WT_RSB + kb + ks * 32);
#pragma unroll
            for (int mf = 0; mf < 4; mf++) {
                mmaf(acc[mf][0], ah[mf], &bh0[0]); mmaf(acc[mf][1], ah[mf], &bh0[2]);
                mmaf(acc[mf][2], ah[mf], &bh1[0]); mmaf(acc[mf][3], ah[mf], &bh1[2]);
                mmah(hacc[mf][0], ah[mf], &bl0[0]); mmah(hacc[mf][1], ah[mf], &bl0[2]);
                mmah(hacc[mf][2], ah[mf], &bl1[0]); mmah(hacc[mf][3], ah[mf], &bl1[2]);
            }
        }
    };

    // ---- part 1: h-part chunks (2,3) — no dependence on this step's H
    issue(2, sbase);            CP_COMMIT();
    issue(3, sbase + GG_STG);   CP_COMMIT();
    CP_WAIT1();
    __syncthreads();
    compute(2, sbase);
    CP_WAIT0();
    __syncthreads();
    compute(3, sbase + GG_STG);

    // ---- barrier wait: H(t) complete grid-wide
    gbar_wait(wait_gen);

    // ---- part 2: H-part chunks (0,1)
    issue(0, sbase);            CP_COMMIT();
    issue(1, sbase + GG_STG);   CP_COMMIT();
    CP_WAIT1();
    __syncthreads();
    compute(0, sbase);
    CP_WAIT0();
    __syncthreads();
    compute(1, sbase + GG_STG);
    __syncthreads();

    // stage fp32 gate tile (with weight corrections merged) in smem
    float* cst = (float*)dsm;   // [128][132]
#pragma unroll
    for (int mf = 0; mf < 4; mf++) {
#pragma unroll
        for (int nf = 0; nf < 4; nf++) {
            int row = wm * 64 + mf * 16 + (lane >> 2);
            int col = wn * 32 + nf * 8 + (lane & 3) * 2;
            float* d = acc[mf][nf];
            hmerge(d, hacc[mf][nf]);
            *(float2*)&cst[row * 132 + col]       = make_float2(d[0], d[1]);
            *(float2*)&cst[(row + 8) * 132 + col] = make_float2(d[2], d[3]);
        }
    }
    __syncthreads();

    // pass 1: gates -> c, h (h in regs, fp16)
    float hv16[16];
    int q  = tid & 31;
    int rb = tid >> 5;
    int j  = (n0 >> 2) + q;
    __half* hrho = g_hrh[hout];
#pragma unroll
    for (int i = 0; i < 16; i++) {
        int r = rb + i * 8;
        int rr = m0 + r;
        float4 pv = *(float4*)&cst[r * 132 + q * 4];
        float4 ge = *(const float4*)&g_Ges[(size_t)rr * 512 + j * 4];
        float iv = sigm(pv.x + ge.x), fv = sigm(pv.y + ge.y);
        float gv = ftanh(pv.z + ge.z), ov = sigm(pv.w + ge.w);
        size_t cidx = (size_t)rr * 128 + j;
        float cc = fv * g_c[cidx] + iv * gv;
        g_c[cidx] = cc;
        float hv = ov * ftanh(cc);
        hv16[i] = hv;
        hrho[cidx] = __float2half_rn(hv);
    }
    __syncthreads();   // cst dead

    // pass 2: smem transpose (32 features x 128 rows)
    __half* trh = (__half*)dsm;            // [32][136]
#pragma unroll
    for (int i = 0; i < 16; i++) {
        int r = rb + i * 8;
        trh[q * 136 + r] = __float2half_rn(hv16[i]);
    }
    __syncthreads();

    // pass 3: coalesced hT writes
    __half* hTh = g_hTh[hout];
    int bb = m0 >> 9, nn0 = m0 & 511;
    int jr = tid >> 4, ch = tid & 15;
#pragma unroll
    for (int half = 0; half < 2; half++) {
        int jj = jr + half * 16;
        uint4 vh = *(uint4*)&trh[jj * 136 + ch * 8];
        size_t base = (size_t)(bb * 128 + (n0 >> 2) + jj) * 512 + nn0 + ch * 8;
        *(uint4*)&hTh[base] = vh;
    }
    __syncthreads();
}

// ---------------------------------------------------------------------------
// phase out (tensor-core): Xi += h @ Wout + bout ; emit out[:, :, t, :]
// h fp16-only; Wout-lo correction kept.
// ---------------------------------------------------------------------------
__device__ __forceinline__ void phase_out(char* dsm, int t, int hidx,
                                          const float* __restrict__ bout,
                                          float* __restrict__ out, int cta, int tid) {
    uint32_t sbase = smem_u32(dsm);
    int wid = tid >> 5, lane = tid & 31;
    int mw = wid & 1, nw = wid >> 1;
    int row0 = cta * 32;
    __syncthreads();

    {
        const __half* hh = g_hrh[hidx] + (size_t)row0 * 128;
#pragma unroll
        for (int i = 0; i < 2; i++) {
            int idx = tid + i * 256, r = idx >> 4, c = idx & 15;
            cpa16(sbase + OUT_HA + r * OUT_RSB + c * 16, hh + (size_t)r * 128 + c * 8);
        }
#pragma unroll
        for (int i = 0; i < 4; i++) {
            int idx = tid + i * 256, r = idx >> 4, c = idx & 15;
            cpa16(sbase + OUT_WB  + r * OUT_RSB + c * 16, g_WoTh + (size_t)r * 128 + c * 8);
            cpa16(sbase + OUT_WBL + r * OUT_RSB + c * 16, g_WoTl + (size_t)r * 128 + c * 8);
        }
        CP_COMMIT();
    }

    int rA = row0 + mw * 16 + (lane >> 2);
    int cA = nw * 16 + (lane & 3) * 2;
    float2 xi[2][2], bo[2];
#pragma unroll
    for (int nf = 0; nf < 2; nf++) {
        int col = cA + nf * 8;
        xi[nf][0] = *(const float2*)&g_Xi[rA * 64 + col];
        xi[nf][1] = *(const float2*)&g_Xi[(rA + 8) * 64 + col];
        bo[nf] = *(const float2*)&bout[col];
    }

    CP_WAIT0();
    __syncthreads();

    uint32_t aH = sbase + OUT_HA + (uint32_t)(mw * 16 + (lane & 15)) * OUT_RSB + ((lane >> 4) * 16);
    uint32_t bH = sbase + OUT_WB
                + (uint32_t)(nw * 16 + (lane & 7) + ((lane >> 4) & 1) * 8) * OUT_RSB
                + (((lane >> 3) & 1) * 16);
    uint32_t bL = bH + (OUT_WBL - OUT_WB);

    float acc[2][4] = {};
    uint32_t hacc[2][2] = {};
#pragma unroll
    for (int ks = 0; ks < 8; ks++) {
        uint32_t ah[4], bh[4], bl[4];
        ldsm4(ah, aH + ks * 32);
        ldsm4(bh, bH + ks * 32);
        ldsm4(bl, bL + ks * 32);
        mmaf(acc[0], ah, &bh[0]); mmaf(acc[1], ah, &bh[2]);
        mmah(hacc[0], ah, &bl[0]); mmah(hacc[1], ah, &bl[2]);
    }

#pragma unroll
    for (int nf = 0; nf < 2; nf++) {
        hmerge(acc[nf], hacc[nf]);
        int col = cA + nf * 8;
        float2 v0 = make_float2(acc[nf][0] + xi[nf][0].x + bo[nf].x,
                                acc[nf][1] + xi[nf][0].y + bo[nf].y);
        float2 v1 = make_float2(acc[nf][2] + xi[nf][1].x + bo[nf].x,
                                acc[nf][3] + xi[nf][1].y + bo[nf].y);
        *(float2*)&g_Xi[rA * 64 + col] = v0;
        *(float2*)&g_Xi[(rA + 8) * 64 + col] = v1;
        *(float2*)&out[(size_t)rA * 4096 + t * 64 + col] = v0;
        *(float2*)&out[(size_t)(rA + 8) * 4096 + t * 64 + col] = v1;
    }
    __syncthreads();
}

// ---------------------------------------------------------------------------
// k_main: persistent kernel, 63 steps.
// gH -> arrive -> out(t-1) -> gG(h-part, wait, H-part) -> bar2
// ---------------------------------------------------------------------------
__global__ void __launch_bounds__(256) k_main(const float* __restrict__ bout,
                                              float* __restrict__ out) {
    extern __shared__ __align__(16) char dsm[];
    int cta = blockIdx.x, tid = threadIdx.x;

    // persistent weight slice for this CTA's gG n-tile
    {
        int n0 = (cta & 3) * 128;
        uint32_t wt = smem_u32(dsm) + SM_WT;
#pragma unroll
        for (int i = 0; i < 16; i++) {
            int idx = tid + i * 256;
            int r = idx >> 5, c = idx & 31;
            cpa16(wt + r * WT_RSB + c * 16,         g_WTh + (size_t)(n0 + r) * 256 + c * 8);
            cpa16(wt + WT_SZ + r * WT_RSB + c * 16, g_WTl + (size_t)(n0 + r) * 256 + c * 8);
        }
        CP_COMMIT();
        CP_WAIT0();
    }
    __syncthreads();

    unsigned gen = 0;
#pragma unroll 1
    for (int t = 1; t < Tc; t++) {
        int hin = (t - 1) & 1, hout = t & 1;
        phase_gH(dsm, hin, cta, tid);
        ++gen;
        gbar_arrive(gen);                            // bar1: this CTA's H done
        if (t >= 2) phase_out(dsm, t - 1, hin, bout, out, cta, tid);
        phase_gG(dsm, hin, hout, cta, tid, gen);     // h-part + out overlap bar1 wait
        gbar(++gen);                                 // bar2: h(t) complete
    }
    phase_out(dsm, Tc - 1, (Tc - 1) & 1, bout, out, cta, tid);
}

// ---------------------------------------------------------------------------
extern "C" void kernel_launch(void* const* d_in, const int* in_sizes, int n_in,
                              void* d_out, int out_size) {
    const float* X    = (const float*)d_in[0];
    const float* A    = (const float*)d_in[1];
    const float* Wse  = (const float*)d_in[2];
    const float* bse  = (const float*)d_in[3];
    const float* Wpe  = (const float*)d_in[4];
    const float* bpe  = (const float*)d_in[5];
    const float* Wii  = (const float*)d_in[6];
    const float* bii  = (const float*)d_in[7];
    const float* Whi  = (const float*)d_in[8];
    const float* bhi  = (const float*)d_in[9];
    const float* Wif  = (const float*)d_in[10];
    const float* bif_ = (const float*)d_in[11];
    const float* Whf  = (const float*)d_in[12];
    const float* bhf  = (const float*)d_in[13];
    const float* Wig  = (const float*)d_in[14];
    const float* big_ = (const float*)d_in[15];
    const float* Whg  = (const float*)d_in[16];
    const float* bhg  = (const float*)d_in[17];
    const float* Wio  = (const float*)d_in[18];
    const float* bio  = (const float*)d_in[19];
    const float* Who  = (const float*)d_in[20];
    const float* bho  = (const float*)d_in[21];
    const float* Wout = (const float*)d_in[22];
    const float* bout = (const float*)d_in[23];
    float* out = (float*)d_out;

    cudaFuncSetAttribute(k_main, cudaFuncAttributeMaxDynamicSharedMemorySize, SM_TOTAL);

    k_dinv<<<Rc, 128>>>(A);
    k_an<<<2048, 256>>>(A);
    k_prep<<<512, 128>>>(Wii, bii, Whi, bhi, Wif, bif_, Whf, bhf,
                         Wig, big_, Whg, bhg, Wio, bio, Who, bho, Wpe, bpe);
    k_init<<<Rc, 128>>>(X, Wse, bse, Wout, out);
    k_ges<<<256, 256>>>();
    k_main<<<NCTA, 256, SM_TOTAL>>>(bout, out);
}

// round 13
// speedup vs baseline: 1.4647x; 1.0668x over previous
#include <cuda_runtime.h>
#include <cuda_fp16.h>
#include <math.h>
#include <stdint.h>

// Problem constants
#define Bc   8
#define Nc   512
#define Tc   64
#define NINc 64
#define NHc  128
#define Rc   (Bc * Nc)   // 4096 rows
#define NCTA 128

// ---------------- scratch (device globals) ----------------------------------
__device__ float g_dinv[Rc];
__device__ __half g_Anh[Bc * Nc * Nc];          // An fp16 (4 MB)
__device__ float g_es[Rc * NHc];                // static embedding fp32
__device__ float g_Wes[128 * 512];              // Wi[0:128] interleaved fp32
__device__ float g_bbig[512];
__device__ float g_Ges[Rc * 512];               // es @ Wes + bbig (fp32, interleaved)
__device__ __half g_WTh[512 * 256];             // Wcomb^T hi: [n][k]
__device__ __half g_WTl[512 * 256];             // Wcomb^T lo (weight corr kept)
__device__ __half g_WoTh[64 * 128];             // Wout^T hi: [n][k]
__device__ __half g_WoTl[64 * 128];             // Wout^T lo (weight corr kept)
__device__ __half g_Hh[Rc * NHc];               // H = An@h, fp16, row-major
__device__ __half g_hrh[2][Rc * NHc];           // h row-major fp16 (double buffered)
__device__ __half g_hTh[2][Bc * NHc * Nc];      // h transposed per batch [b][j][n]
__device__ float g_c[Rc * NHc];                 // cell state
__device__ float g_Xi[Rc * NINc];               // running output accumulator
__device__ unsigned g_count;                    // grid barrier arrive counter
__device__ unsigned g_sense;                    // grid barrier generation

// ---------------- helpers ----------------------------------------------------
__device__ __forceinline__ uint32_t smem_u32(const void* p) {
    uint32_t a;
    asm("{ .reg .u64 t; cvta.to.shared.u64 t, %1; cvt.u32.u64 %0, t; }" : "=r"(a) : "l"(p));
    return a;
}
__device__ __forceinline__ float sigm(float x) {
    return __fdividef(1.f, 1.f + __expf(-x));
}
__device__ __forceinline__ float ftanh(float x) {
    float e = __expf(2.f * x);
    return 1.f - __fdividef(2.f, e + 1.f);
}
__device__ __forceinline__ void hsplit(float v, __half& hi, __half& lo) {
    hi = __float2half_rn(v);
    lo = __float2half_rn(v - __half2float(hi));
}
__device__ __forceinline__ void cpa16(uint32_t dst, const void* src) {
    asm volatile("cp.async.cg.shared.global [%0], [%1], 16;" :: "r"(dst), "l"(src) : "memory");
}
#define CP_COMMIT() asm volatile("cp.async.commit_group;" ::: "memory")
#define CP_WAIT2()  asm volatile("cp.async.wait_group 2;" ::: "memory")
#define CP_WAIT1()  asm volatile("cp.async.wait_group 1;" ::: "memory")
#define CP_WAIT0()  asm volatile("cp.async.wait_group 0;" ::: "memory")

__device__ __forceinline__ void ldsm4(uint32_t* r, uint32_t a) {
    asm volatile("ldmatrix.sync.aligned.m8n8.x4.shared.b16 {%0,%1,%2,%3}, [%4];"
        : "=r"(r[0]), "=r"(r[1]), "=r"(r[2]), "=r"(r[3]) : "r"(a));
}
__device__ __forceinline__ void mmaf(float* d, const uint32_t* a, const uint32_t* b) {
    asm volatile("mma.sync.aligned.m16n8k16.row.col.f32.f16.f16.f32 "
        "{%0,%1,%2,%3}, {%4,%5,%6,%7}, {%8,%9}, {%0,%1,%2,%3};"
        : "+f"(d[0]), "+f"(d[1]), "+f"(d[2]), "+f"(d[3])
        : "r"(a[0]), "r"(a[1]), "r"(a[2]), "r"(a[3]), "r"(b[0]), "r"(b[1]));
}
__device__ __forceinline__ void mmah(uint32_t* d, const uint32_t* a, const uint32_t* b) {
    asm volatile("mma.sync.aligned.m16n8k16.row.col.f16.f16.f16.f16 "
        "{%0,%1}, {%2,%3,%4,%5}, {%6,%7}, {%0,%1};"
        : "+r"(d[0]), "+r"(d[1])
        : "r"(a[0]), "r"(a[1]), "r"(a[2]), "r"(a[3]), "r"(b[0]), "r"(b[1]));
}
__device__ __forceinline__ void hmerge(float* d, const uint32_t* h) {
    __half2 q0 = *(const __half2*)&h[0];
    __half2 q1 = *(const __half2*)&h[1];
    d[0] += __half2float(q0.x); d[1] += __half2float(q0.y);
    d[2] += __half2float(q1.x); d[3] += __half2float(q1.y);
}

// grid-wide sense barrier, split into arrive / wait halves
__device__ __forceinline__ void gbar_arrive(unsigned gen) {
    __syncthreads();
    if (threadIdx.x == 0) {
        unsigned prev;
        asm volatile("atom.release.gpu.add.u32 %0, [%1], %2;"
                     : "=r"(prev) : "l"(&g_count), "r"(1u) : "memory");
        if (prev == NCTA - 1) {
            g_count = 0u;
            asm volatile("st.release.gpu.u32 [%0], %1;" :: "l"(&g_sense), "r"(gen) : "memory");
        }
    }
}
__device__ __forceinline__ void gbar_wait(unsigned gen) {
    if (threadIdx.x == 0) {
        unsigned s;
        do {
            asm volatile("ld.acquire.gpu.u32 %0, [%1];" : "=r"(s) : "l"(&g_sense) : "memory");
        } while (s < gen);
    }
    __syncthreads();
}

#define RS 144          // stage tile row stride (72 halves)
#define GH_T   9216     // gH tile: 64 rows x RS
#define STG    18432    // unified stage size (gH: Ah|Bh ; gG: Ah 128 rows)
#define SM_WT    55296  // after 3 stages
#define WT_RSB   528
#define WT_SZ    67584
#define SM_WOT   190464 // SM_WT + 2*WT_SZ
#define WOT_SZ   17408  // 64 rows x 272
#define OUT_RSB  272
#define SM_TOTAL 225280 // SM_WOT + 2*WOT_SZ

// ---------------------------------------------------------------------------
__global__ void k_dinv(const float* __restrict__ A) {
    int row = blockIdx.x;
    const float* arow = A + (size_t)row * Nc;
    float s = 0.f;
    for (int j = threadIdx.x; j < Nc; j += blockDim.x) s += arow[j];
    __shared__ float sh[128];
    sh[threadIdx.x] = s;
    __syncthreads();
    for (int off = 64; off > 0; off >>= 1) {
        if (threadIdx.x < off) sh[threadIdx.x] += sh[threadIdx.x + off];
        __syncthreads();
    }
    if (threadIdx.x == 0) {
        float d = sh[0];
        g_dinv[row] = (d > 0.f) ? rsqrtf(d) : 0.f;
    }
}

__global__ void k_an(const float* __restrict__ A) {
    int idx = blockIdx.x * blockDim.x + threadIdx.x;
    int e = idx * 4;
    int b   = e >> 18;
    int rem = e & 262143;
    int i   = rem >> 9;
    int j   = rem & 511;
    float4 a = *(const float4*)(A + (size_t)e);
    float di = g_dinv[b * 512 + i];
    const float* dj = g_dinv + b * 512 + j;
    __half2* ph = (__half2*)(g_Anh + (size_t)e);
    ph[0] = __halves2half2(__float2half_rn(a.x * di * dj[0]),
                           __float2half_rn(a.y * di * dj[1]));
    ph[1] = __halves2half2(__float2half_rn(a.z * di * dj[2]),
                           __float2half_rn(a.w * di * dj[3]));
}

// ---------------------------------------------------------------------------
__global__ void k_prep(const float* __restrict__ Wii, const float* __restrict__ bii,
                       const float* __restrict__ Whi, const float* __restrict__ bhi,
                       const float* __restrict__ Wif, const float* __restrict__ bif_,
                       const float* __restrict__ Whf, const float* __restrict__ bhf,
                       const float* __restrict__ Wig, const float* __restrict__ big_,
                       const float* __restrict__ Whg, const float* __restrict__ bhg,
                       const float* __restrict__ Wio, const float* __restrict__ bio,
                       const float* __restrict__ Who, const float* __restrict__ bho,
                       const float* __restrict__ Wpe, const float* __restrict__ bpe) {
    int n = blockIdx.x;
    int g = n & 3;
    int j = n >> 2;
    int t = threadIdx.x;
    const float* Wi = (g == 0) ? Wii : (g == 1) ? Wif : (g == 2) ? Wig : Wio;
    const float* Wh = (g == 0) ? Whi : (g == 1) ? Whf : (g == 2) ? Whg : Who;
    const float* bi = (g == 0) ? bii : (g == 1) ? bif_ : (g == 2) ? big_ : bio;
    const float* bh = (g == 0) ? bhi : (g == 1) ? bhf : (g == 2) ? bhg : bho;

    __shared__ float wcol[128];
    wcol[t] = Wi[(128 + t) * 128 + j];
    __syncthreads();

    g_Wes[t * 512 + n] = Wi[t * 128 + j];

    float acc = 0.f;
    const float* wpet = Wpe + t * 128;
#pragma unroll 8
    for (int m = 0; m < 128; m++) acc += wpet[m] * wcol[m];

    __half hh, ll;
    hsplit(acc, hh, ll);
    g_WTh[n * 256 + t] = hh;
    g_WTl[n * 256 + t] = ll;
    float whv = Wh[t * 128 + j];
    hsplit(whv, hh, ll);
    g_WTh[n * 256 + 128 + t] = hh;
    g_WTl[n * 256 + 128 + t] = ll;

    if (t == 0) {
        float ba = bi[j] + bh[j];
        for (int m = 0; m < 128; m++) ba += bpe[m] * wcol[m];
        g_bbig[n] = ba;
    }
}

// ---------------------------------------------------------------------------
__global__ void k_init(const float* __restrict__ X, const float* __restrict__ Wse,
                       const float* __restrict__ bse, const float* __restrict__ Wout,
                       float* __restrict__ out) {
    int row = blockIdx.x;
    int t = threadIdx.x;
    if (row == 0 && t == 0) { g_count = 0u; g_sense = 0u; }
    if (row < 64) {
        __half hh, ll;
        hsplit(Wout[t * 64 + row], hh, ll);
        g_WoTh[row * 128 + t] = hh;
        g_WoTl[row * 128 + t] = ll;
    }
    __shared__ float x0[64];
    if (t < 64) {
        float v = X[(size_t)row * 4096 + t];
        x0[t] = v;
        g_Xi[row * 64 + t] = v;
        out[(size_t)row * 4096 + t] = v;
    }
    __syncthreads();
    float acc = bse[t];
#pragma unroll 8
    for (int k = 0; k < 64; k++) acc += x0[k] * Wse[k * 128 + t];
    g_es[row * 128 + t] = acc;

    __half z = __float2half(0.f);
    g_hrh[0][(size_t)row * 128 + t] = z;
    int bb = row >> 9, nn = row & 511;
    g_hTh[0][(size_t)(bb * 128 + t) * 512 + nn] = z;
    g_c[row * 128 + t] = 0.f;
}

// ---------------------------------------------------------------------------
// k_ges: Ges = es @ Wes + bbig (4096 x 512, K=128) fp32, runs once
// ---------------------------------------------------------------------------
__global__ void __launch_bounds__(256) k_ges() {
    int m0 = (blockIdx.x >> 2) * 64;
    int n0 = (blockIdx.x & 3) * 128;

    __shared__ __align__(16) float As[16][68];
    __shared__ __align__(16) float Bs[16][132];

    int tid = threadIdx.x;
    int ty = tid >> 4, tx = tid & 15;
    int ar = tid >> 2, ac = (tid & 3) * 4;
    int br = tid >> 5, bc = (tid & 31) * 4;

    float acc[4][8] = {};

    for (int k0 = 0; k0 < 128; k0 += 16) {
        float4 av = *(const float4*)&g_es[(size_t)(m0 + ar) * 128 + k0 + ac];
        float4 bv0 = *(const float4*)&g_Wes[(size_t)(k0 + br) * 512 + n0 + bc];
        float4 bv1 = *(const float4*)&g_Wes[(size_t)(k0 + br + 8) * 512 + n0 + bc];
        As[ac + 0][ar] = av.x; As[ac + 1][ar] = av.y;
        As[ac + 2][ar] = av.z; As[ac + 3][ar] = av.w;
        *(float4*)&Bs[br][bc] = bv0;
        *(float4*)&Bs[br + 8][bc] = bv1;
        __syncthreads();
#pragma unroll
        for (int kk = 0; kk < 16; kk++) {
            float4 a4 = *(const float4*)&As[kk][ty * 4];
            float4 b0 = *(const float4*)&Bs[kk][tx * 8];
            float4 b1 = *(const float4*)&Bs[kk][tx * 8 + 4];
            float av4[4] = { a4.x, a4.y, a4.z, a4.w };
            float bv8[8] = { b0.x, b0.y, b0.z, b0.w, b1.x, b1.y, b1.z, b1.w };
#pragma unroll
            for (int i = 0; i < 4; i++)
#pragma unroll
                for (int jq = 0; jq < 8; jq++) acc[i][jq] += av4[i] * bv8[jq];
        }
        __syncthreads();
    }

    float bb[8];
#pragma unroll
    for (int q = 0; q < 8; q++) bb[q] = g_bbig[n0 + tx * 8 + q];
#pragma unroll
    for (int r = 0; r < 4; r++) {
        int rr = m0 + ty * 4 + r;
        float* dst = &g_Ges[(size_t)rr * 512 + n0 + tx * 8];
#pragma unroll
        for (int q = 0; q < 8; q++) dst[q] = acc[r][q] + bb[q];
    }
}

// ---------------------------------------------------------------------------
// phase gH: H = An @ h, CTA tile 64x64 (8b x 8m x 2n = 128 tiles)
// An loads for chunks 0,1 issued BEFORE the bar2 wait (An independent of h);
// hT loads after. 3-stage pipeline.
// ---------------------------------------------------------------------------
__device__ __forceinline__ void phase_gH(char* dsm, int hin, int cta, int tid,
                                         unsigned wait_gen) {
    uint32_t sbase = smem_u32(dsm);
    int wid = tid >> 5, lane = tid & 31;
    int wm = wid >> 2, wn = wid & 3;
    int b  = cta >> 4;
    int m0 = ((cta >> 1) & 7) * 64;
    int n0 = (cta & 1) * 64;

    float acc[2][2][4];
#pragma unroll
    for (int i = 0; i < 2; i++)
#pragma unroll
        for (int j = 0; j < 2; j++)
#pragma unroll
            for (int q = 0; q < 4; q++) acc[i][j][q] = 0.f;

    const __half* Ah0 = g_Anh + (size_t)b * 262144 + (size_t)m0 * 512;
    const __half* Bh0 = g_hTh[hin] + (size_t)b * 65536 + (size_t)n0 * 512;

    auto stg = [&](int cc) -> uint32_t { return sbase + (uint32_t)(cc % 3) * STG; };

    auto issueA = [&](int cc) {
        uint32_t buf = stg(cc);
        int kc = cc * 64;
#pragma unroll
        for (int i = 0; i < 2; i++) {
            int idx = tid + i * 256, r = idx >> 3, c = idx & 7;
            cpa16(buf + r * RS + c * 16, Ah0 + (size_t)r * 512 + kc + c * 8);
        }
    };
    auto issueB = [&](int cc) {
        uint32_t buf = stg(cc);
        int kc = cc * 64;
#pragma unroll
        for (int i = 0; i < 2; i++) {
            int idx = tid + i * 256, r = idx >> 3, c = idx & 7;
            cpa16(buf + GH_T + r * RS + c * 16, Bh0 + (size_t)r * 512 + kc + c * 8);
        }
    };
    auto issue = [&](int cc) {
        uint32_t buf = stg(cc);
        int kc = cc * 64;
#pragma unroll
        for (int i = 0; i < 2; i++) {
            int idx = tid + i * 256, r = idx >> 3, c = idx & 7;
            uint32_t d = buf + r * RS + c * 16;
            size_t off = (size_t)r * 512 + kc + c * 8;
            cpa16(d,        Ah0 + off);
            cpa16(d + GH_T, Bh0 + off);
        }
    };

    // An for chunks 0,1 prefetched across the bar2 wait
    issueA(0); CP_COMMIT();
    issueA(1); CP_COMMIT();
    gbar_wait(wait_gen);          // h(t-1) complete grid-wide
    issueB(0); CP_COMMIT();
    issueB(1); CP_COMMIT();

#pragma unroll 1
    for (int cc = 0; cc < 8; cc++) {
        CP_WAIT1();
        __syncthreads();

        uint32_t buf = stg(cc);
        uint32_t aH = buf + (uint32_t)(wm * 32 + (lane & 15)) * RS + ((lane >> 4) * 16);
        uint32_t bH = buf + GH_T
                    + (uint32_t)(wn * 16 + (lane & 7) + ((lane >> 4) & 1) * 8) * RS
                    + (((lane >> 3) & 1) * 16);
#pragma unroll
        for (int ks = 0; ks < 4; ks++) {
            uint32_t ah[2][4], bh[4];
            ldsm4(ah[0], aH + ks * 32); ldsm4(ah[1], aH + 16 * RS + ks * 32);
            ldsm4(bh, bH + ks * 32);
#pragma unroll
            for (int mf = 0; mf < 2; mf++) {
                mmaf(acc[mf][0], ah[mf], &bh[0]); mmaf(acc[mf][1], ah[mf], &bh[2]);
            }
        }
        __syncthreads();
        if (cc + 2 < 8) { issue(cc + 2); CP_COMMIT(); }
    }
    CP_WAIT0();

    // epilogue: H fp16
    int rbase = b * 512 + m0 + wm * 32 + (lane >> 2);
    int cbase = n0 + wn * 16 + (lane & 3) * 2;
#pragma unroll
    for (int mf = 0; mf < 2; mf++) {
#pragma unroll
        for (int nf = 0; nf < 2; nf++) {
            int col = cbase + nf * 8;
            float* d = acc[mf][nf];
            int r0 = rbase + mf * 16;
            *(__half2*)(g_Hh + (size_t)r0 * 128 + col) =
                __halves2half2(__float2half_rn(d[0]), __float2half_rn(d[1]));
            *(__half2*)(g_Hh + (size_t)(r0 + 8) * 128 + col) =
                __halves2half2(__float2half_rn(d[2]), __float2half_rn(d[3]));
        }
    }
}

// ---------------------------------------------------------------------------
// phase gG (barrier-overlapped, 3-stage): gates = Ges + [H | h] @ Wcomb.
// Order: c2 -> bar wait -> issue c0,c1 -> c3 (loads fly) -> c0 -> c1 -> epi.
// Epilogue staged in two 64-row halves (fp32) to fit the stage region.
// ---------------------------------------------------------------------------
__device__ __forceinline__ void phase_gG(char* dsm, int hin, int hout, int cta, int tid,
                                         unsigned wait_gen) {
    uint32_t sbase = smem_u32(dsm);
    int wid = tid >> 5, lane = tid & 31;
    int wm = wid >> 2, wn = wid & 3;
    int m0 = (cta >> 2) * 128;
    int n0 = (cta & 3) * 128;

    float acc[4][4][4];
    uint32_t hacc[4][4][2];
#pragma unroll
    for (int i = 0; i < 4; i++)
#pragma unroll
        for (int j = 0; j < 4; j++) {
#pragma unroll
            for (int q = 0; q < 4; q++) acc[i][j][q] = 0.f;
            hacc[i][j][0] = 0u; hacc[i][j][1] = 0u;
        }

    auto issue = [&](int cc, uint32_t buf) {
        int kc = cc * 64;
        const __half* Ahs = (kc < 128)
            ? g_Hh + (size_t)m0 * 128 + kc
            : g_hrh[hin] + (size_t)m0 * 128 + (kc - 128);
#pragma unroll
        for (int i = 0; i < 4; i++) {
            int idx = tid + i * 256, r = idx >> 3, c = idx & 7;
            cpa16(buf + r * RS + c * 16, Ahs + (size_t)r * 128 + c * 8);
        }
    };

    uint32_t wtH = sbase + SM_WT
                 + (uint32_t)(wn * 32 + (lane & 7) + ((lane >> 4) & 1) * 8) * WT_RSB
                 + (((lane >> 3) & 1) * 16);
    uint32_t wtL = wtH + WT_SZ;

    auto compute = [&](int cc, uint32_t buf) {
        uint32_t aH = buf + (uint32_t)(wm * 64 + (lane & 15)) * RS + ((lane >> 4) * 16);
        uint32_t kb = (uint32_t)cc * 128;
#pragma unroll
        for (int ks = 0; ks < 4; ks++) {
            uint32_t ah[4][4], bh0[4], bh1[4], bl0[4], bl1[4];
#pragma unroll
            for (int mf = 0; mf < 4; mf++)
                ldsm4(ah[mf], aH + mf * 16 * RS + ks * 32);
            ldsm4(bh0, wtH + kb + ks * 32);
            ldsm4(bh1, wtH + 16 * WT_RSB + kb + ks * 32);
            ldsm4(bl0, wtL + kb + ks * 32);
            ldsm4(bl1, wtL + 16 * WT_RSB + kb + ks * 32);
#pragma unroll
            for (int mf = 0; mf < 4; mf++) {
                mmaf(acc[mf][0], ah[mf], &bh0[0]); mmaf(acc[mf][1], ah[mf], &bh0[2]);
                mmaf(acc[mf][2], ah[mf], &bh1[0]); mmaf(acc[mf][3], ah[mf], &bh1[2]);
                mmah(hacc[mf][0], ah[mf], &bl0[0]); mmah(hacc[mf][1], ah[mf], &bl0[2]);
                mmah(hacc[mf][2], ah[mf], &bl1[0]); mmah(hacc[mf][3], ah[mf], &bl1[2]);
            }
        }
    };

    uint32_t s0 = sbase, s1 = sbase + STG, s2 = sbase + 2 * STG;

    // part 1: h-part chunk 2 (chunk 3 loading)
    issue(2, s0); CP_COMMIT();
    issue(3, s1); CP_COMMIT();
    CP_WAIT1();
    __syncthreads();
    compute(2, s0);

    // barrier wait: H(t) complete grid-wide (contains __syncthreads)
    gbar_wait(wait_gen);

    // issue H-part loads, compute chunk 3 while they fly
    issue(0, s2); CP_COMMIT();
    issue(1, s0); CP_COMMIT();
    CP_WAIT2();
    __syncthreads();
    compute(3, s1);
    CP_WAIT1();
    __syncthreads();
    compute(0, s2);
    CP_WAIT0();
    __syncthreads();
    compute(1, s0);

    // merge weight corrections once
#pragma unroll
    for (int mf = 0; mf < 4; mf++)
#pragma unroll
        for (int nf = 0; nf < 4; nf++) hmerge(acc[mf][nf], hacc[mf][nf]);

    // epilogue: two 64-row halves; fused gate math + row-major h + transpose
    float* cst = (float*)dsm;                 // [64][132] = 33792
    __half* trh = (__half*)(dsm + 33792);     // [32][136] = 8704
    int q  = tid & 31;
    int rb = tid >> 5;
    int j  = (n0 >> 2) + q;
    __half* hrho = g_hrh[hout];
#pragma unroll
    for (int half = 0; half < 2; half++) {
        __syncthreads();
        if (wm == half) {
#pragma unroll
            for (int mf = 0; mf < 4; mf++) {
#pragma unroll
                for (int nf = 0; nf < 4; nf++) {
                    int row = mf * 16 + (lane >> 2);
                    int col = wn * 32 + nf * 8 + (lane & 3) * 2;
                    float* d = acc[mf][nf];
                    *(float2*)&cst[row * 132 + col]       = make_float2(d[0], d[1]);
                    *(float2*)&cst[(row + 8) * 132 + col] = make_float2(d[2], d[3]);
                }
            }
        }
        __syncthreads();
#pragma unroll
        for (int i = 0; i < 8; i++) {
            int rl = rb + i * 8;
            int r  = half * 64 + rl;
            int rr = m0 + r;
            float4 pv = *(float4*)&cst[rl * 132 + q * 4];
            float4 ge = *(const float4*)&g_Ges[(size_t)rr * 512 + j * 4];
            float iv = sigm(pv.x + ge.x), fv = sigm(pv.y + ge.y);
            float gv = ftanh(pv.z + ge.z), ov = sigm(pv.w + ge.w);
            size_t cidx = (size_t)rr * 128 + j;
            float cc = fv * g_c[cidx] + iv * gv;
            g_c[cidx] = cc;
            float hv = ov * ftanh(cc);
            __half hh = __float2half_rn(hv);
            hrho[cidx] = hh;
            trh[q * 136 + r] = hh;
        }
    }
    __syncthreads();

    // coalesced hT writes
    __half* hTh = g_hTh[hout];
    int bb = m0 >> 9, nn0 = m0 & 511;
    int jr = tid >> 4, ch = tid & 15;
#pragma unroll
    for (int half = 0; half < 2; half++) {
        int jj = jr + half * 16;
        uint4 vh = *(uint4*)&trh[jj * 136 + ch * 8];
        size_t base = (size_t)(bb * 128 + (n0 >> 2) + jj) * 512 + nn0 + ch * 8;
        *(uint4*)&hTh[base] = vh;
    }
    __syncthreads();
}

// ---------------------------------------------------------------------------
// phase out: Xi += h @ Wout + bout ; emit out[:, :, t, :]
// WoT hi/lo persistent in smem (loaded once); only h (8.5 KB) loaded per call.
// ---------------------------------------------------------------------------
__device__ __forceinline__ void phase_out(char* dsm, int t, int hidx,
                                          const float* __restrict__ bout,
                                          float* __restrict__ out, int cta, int tid) {
    uint32_t sbase = smem_u32(dsm);
    int wid = tid >> 5, lane = tid & 31;
    int mw = wid & 1, nw = wid >> 1;
    int row0 = cta * 32;
    __syncthreads();

    {
        const __half* hh = g_hrh[hidx] + (size_t)row0 * 128;
#pragma unroll
        for (int i = 0; i < 2; i++) {
            int idx = tid + i * 256, r = idx >> 4, c = idx & 15;
            cpa16(sbase + r * OUT_RSB + c * 16, hh + (size_t)r * 128 + c * 8);
        }
        CP_COMMIT();
    }

    int rA = row0 + mw * 16 + (lane >> 2);
    int cA = nw * 16 + (lane & 3) * 2;
    float2 xi[2][2], bo[2];
#pragma unroll
    for (int nf = 0; nf < 2; nf++) {
        int col = cA + nf * 8;
        xi[nf][0] = *(const float2*)&g_Xi[rA * 64 + col];
        xi[nf][1] = *(const float2*)&g_Xi[(rA + 8) * 64 + col];
        bo[nf] = *(const float2*)&bout[col];
    }

    CP_WAIT0();
    __syncthreads();

    uint32_t aH = sbase + (uint32_t)(mw * 16 + (lane & 15)) * OUT_RSB + ((lane >> 4) * 16);
    uint32_t bH = sbase + SM_WOT
                + (uint32_t)(nw * 16 + (lane & 7) + ((lane >> 4) & 1) * 8) * OUT_RSB
                + (((lane >> 3) & 1) * 16);
    uint32_t bL = bH + WOT_SZ;

    float acc[2][4] = {};
    uint32_t hacc[2][2] = {};
#pragma unroll
    for (int ks = 0; ks < 8; ks++) {
        uint32_t ah[4], bh[4], bl[4];
        ldsm4(ah, aH + ks * 32);
        ldsm4(bh, bH + ks * 32);
        ldsm4(bl, bL + ks * 32);
        mmaf(acc[0], ah, &bh[0]); mmaf(acc[1], ah, &bh[2]);
        mmah(hacc[0], ah, &bl[0]); mmah(hacc[1], ah, &bl[2]);
    }

#pragma unroll
    for (int nf = 0; nf < 2; nf++) {
        hmerge(acc[nf], hacc[nf]);
        int col = cA + nf * 8;
        float2 v0 = make_float2(acc[nf][0] + xi[nf][0].x + bo[nf].x,
                                acc[nf][1] + xi[nf][0].y + bo[nf].y);
        float2 v1 = make_float2(acc[nf][2] + xi[nf][1].x + bo[nf].x,
                                acc[nf][3] + xi[nf][1].y + bo[nf].y);
        *(float2*)&g_Xi[rA * 64 + col] = v0;
        *(float2*)&g_Xi[(rA + 8) * 64 + col] = v1;
        *(float2*)&out[(size_t)rA * 4096 + t * 64 + col] = v0;
        *(float2*)&out[(size_t)(rA + 8) * 4096 + t * 64 + col] = v1;
    }
    __syncthreads();
}

// ---------------------------------------------------------------------------
// k_main: persistent kernel, 63 steps. bar2 is arrive-only; its wait is
// folded into the next step's gH (An prefetched across the wait).
// ---------------------------------------------------------------------------
__global__ void __launch_bounds__(256) k_main(const float* __restrict__ bout,
                                              float* __restrict__ out) {
    extern __shared__ __align__(16) char dsm[];
    int cta = blockIdx.x, tid = threadIdx.x;

    // persistent weight slices: WT (per-CTA n-tile) + WoT (shared)
    {
        int n0 = (cta & 3) * 128;
        uint32_t wt = smem_u32(dsm) + SM_WT;
#pragma unroll
        for (int i = 0; i < 16; i++) {
            int idx = tid + i * 256;
            int r = idx >> 5, c = idx & 31;
            cpa16(wt + r * WT_RSB + c * 16,         g_WTh + (size_t)(n0 + r) * 256 + c * 8);
            cpa16(wt + WT_SZ + r * WT_RSB + c * 16, g_WTl + (size_t)(n0 + r) * 256 + c * 8);
        }
        uint32_t wo = smem_u32(dsm) + SM_WOT;
#pragma unroll
        for (int i = 0; i < 4; i++) {
            int idx = tid + i * 256;
            int r = idx >> 4, c = idx & 15;
            cpa16(wo + r * OUT_RSB + c * 16,          g_WoTh + (size_t)r * 128 + c * 8);
            cpa16(wo + WOT_SZ + r * OUT_RSB + c * 16, g_WoTl + (size_t)r * 128 + c * 8);
        }
        CP_COMMIT();
        CP_WAIT0();
    }
    __syncthreads();

    unsigned gen = 0;
#pragma unroll 1
    for (int t = 1; t < Tc; t++) {
        int hin = (t - 1) & 1, hout = t & 1;
        phase_gH(dsm, hin, cta, tid, gen);           // waits bar2(t-1) after An prefetch
        ++gen;
        gbar_arrive(gen);                            // bar1: this CTA's H done
        if (t >= 2) phase_out(dsm, t - 1, hin, bout, out, cta, tid);
        phase_gG(dsm, hin, hout, cta, tid, gen);     // h-part + out overlap bar1 wait
        ++gen;
        gbar_arrive(gen);                            // bar2: arrive only
    }
    gbar_wait(gen);
    phase_out(dsm, Tc - 1, (Tc - 1) & 1, bout, out, cta, tid);
}

// ---------------------------------------------------------------------------
extern "C" void kernel_launch(void* const* d_in, const int* in_sizes, int n_in,
                              void* d_out, int out_size) {
    const float* X    = (const float*)d_in[0];
    const float* A    = (const float*)d_in[1];
    const float* Wse  = (const float*)d_in[2];
    const float* bse  = (const float*)d_in[3];
    const float* Wpe  = (const float*)d_in[4];
    const float* bpe  = (const float*)d_in[5];
    const float* Wii  = (const float*)d_in[6];
    const float* bii  = (const float*)d_in[7];
    const float* Whi  = (const float*)d_in[8];
    const float* bhi  = (const float*)d_in[9];
    const float* Wif  = (const float*)d_in[10];
    const float* bif_ = (const float*)d_in[11];
    const float* Whf  = (const float*)d_in[12];
    const float* bhf  = (const float*)d_in[13];
    const float* Wig  = (const float*)d_in[14];
    const float* big_ = (const float*)d_in[15];
    const float* Whg  = (const float*)d_in[16];
    const float* bhg  = (const float*)d_in[17];
    const float* Wio  = (const float*)d_in[18];
    const float* bio  = (const float*)d_in[19];
    const float* Who  = (const float*)d_in[20];
    const float* bho  = (const float*)d_in[21];
    const float* Wout = (const float*)d_in[22];
    const float* bout = (const float*)d_in[23];
    float* out = (float*)d_out;

    cudaFuncSetAttribute(k_main, cudaFuncAttributeMaxDynamicSharedMemorySize, SM_TOTAL);

    k_dinv<<<Rc, 128>>>(A);
    k_an<<<2048, 256>>>(A);
    k_prep<<<512, 128>>>(Wii, bii, Whi, bhi, Wif, bif_, Whf, bhf,
                         Wig, big_, Whg, bhg, Wio, bio, Who, bho, Wpe, bpe);
    k_init<<<Rc, 128>>>(X, Wse, bse, Wout, out);
    k_ges<<<256, 256>>>();
    k_main<<<NCTA, 256, SM_TOTAL>>>(bout, out);
}

// round 14
// speedup vs baseline: 1.4714x; 1.0046x over previous
#include <cuda_runtime.h>
#include <cuda_fp16.h>
#include <math.h>
#include <stdint.h>

// Problem constants
#define Bc   8
#define Nc   512
#define Tc   64
#define NINc 64
#define NHc  128
#define Rc   (Bc * Nc)   // 4096 rows
#define NCTA 128

// ---------------- scratch (device globals) ----------------------------------
__device__ float g_dinv[Rc];
__device__ __half g_Anh[Bc * Nc * Nc];          // An fp16 (4 MB)
__device__ float g_es[Rc * NHc];                // static embedding fp32
__device__ float g_Wes[128 * 512];              // Wi[0:128] interleaved fp32
__device__ float g_bbig[512];
__device__ float g_Ges[Rc * 512];               // es @ Wes + bbig (fp32, interleaved)
__device__ __half g_WTh[512 * 256];             // Wcomb^T hi: [n][k]
__device__ __half g_WTl[512 * 256];             // Wcomb^T lo (weight corr kept)
__device__ __half g_WoTh[64 * 128];             // Wout^T hi: [n][k]
__device__ __half g_WoTl[64 * 128];             // Wout^T lo (weight corr kept)
__device__ __half g_Hh[Rc * NHc];               // H = An@h, fp16, row-major
__device__ __half g_hrh[2][Rc * NHc];           // h row-major fp16 (double buffered)
__device__ float g_c[Rc * NHc];                 // cell state
__device__ float g_Xi[Rc * NINc];               // running output accumulator
__device__ unsigned g_count;                    // grid barrier arrive counter
__device__ unsigned g_sense;                    // grid barrier generation

// ---------------- helpers ----------------------------------------------------
__device__ __forceinline__ uint32_t smem_u32(const void* p) {
    uint32_t a;
    asm("{ .reg .u64 t; cvta.to.shared.u64 t, %1; cvt.u32.u64 %0, t; }" : "=r"(a) : "l"(p));
    return a;
}
__device__ __forceinline__ float sigm(float x) {
    return __fdividef(1.f, 1.f + __expf(-x));
}
__device__ __forceinline__ float ftanh(float x) {
    float e = __expf(2.f * x);
    return 1.f - __fdividef(2.f, e + 1.f);
}
__device__ __forceinline__ void hsplit(float v, __half& hi, __half& lo) {
    hi = __float2half_rn(v);
    lo = __float2half_rn(v - __half2float(hi));
}
__device__ __forceinline__ void cpa16(uint32_t dst, const void* src) {
    asm volatile("cp.async.cg.shared.global [%0], [%1], 16;" :: "r"(dst), "l"(src) : "memory");
}
#define CP_COMMIT() asm volatile("cp.async.commit_group;" ::: "memory")
#define CP_WAIT2()  asm volatile("cp.async.wait_group 2;" ::: "memory")
#define CP_WAIT1()  asm volatile("cp.async.wait_group 1;" ::: "memory")
#define CP_WAIT0()  asm volatile("cp.async.wait_group 0;" ::: "memory")

__device__ __forceinline__ void ldsm4(uint32_t* r, uint32_t a) {
    asm volatile("ldmatrix.sync.aligned.m8n8.x4.shared.b16 {%0,%1,%2,%3}, [%4];"
        : "=r"(r[0]), "=r"(r[1]), "=r"(r[2]), "=r"(r[3]) : "r"(a));
}
// transposed ldmatrix: row-major [k][n] tile -> B fragments (consecutive-k pairs)
__device__ __forceinline__ void ldsm4t(uint32_t* r, uint32_t a) {
    asm volatile("ldmatrix.sync.aligned.m8n8.x4.trans.shared.b16 {%0,%1,%2,%3}, [%4];"
        : "=r"(r[0]), "=r"(r[1]), "=r"(r[2]), "=r"(r[3]) : "r"(a));
}
__device__ __forceinline__ void mmaf(float* d, const uint32_t* a, const uint32_t* b) {
    asm volatile("mma.sync.aligned.m16n8k16.row.col.f32.f16.f16.f32 "
        "{%0,%1,%2,%3}, {%4,%5,%6,%7}, {%8,%9}, {%0,%1,%2,%3};"
        : "+f"(d[0]), "+f"(d[1]), "+f"(d[2]), "+f"(d[3])
        : "r"(a[0]), "r"(a[1]), "r"(a[2]), "r"(a[3]), "r"(b[0]), "r"(b[1]));
}
__device__ __forceinline__ void mmah(uint32_t* d, const uint32_t* a, const uint32_t* b) {
    asm volatile("mma.sync.aligned.m16n8k16.row.col.f16.f16.f16.f16 "
        "{%0,%1}, {%2,%3,%4,%5}, {%6,%7}, {%0,%1};"
        : "+r"(d[0]), "+r"(d[1])
        : "r"(a[0]), "r"(a[1]), "r"(a[2]), "r"(a[3]), "r"(b[0]), "r"(b[1]));
}
__device__ __forceinline__ void hmerge(float* d, const uint32_t* h) {
    __half2 q0 = *(const __half2*)&h[0];
    __half2 q1 = *(const __half2*)&h[1];
    d[0] += __half2float(q0.x); d[1] += __half2float(q0.y);
    d[2] += __half2float(q1.x); d[3] += __half2float(q1.y);
}

// grid-wide sense barrier, split into arrive / wait halves
__device__ __forceinline__ void gbar_arrive(unsigned gen) {
    __syncthreads();
    if (threadIdx.x == 0) {
        unsigned prev;
        asm volatile("atom.release.gpu.add.u32 %0, [%1], %2;"
                     : "=r"(prev) : "l"(&g_count), "r"(1u) : "memory");
        if (prev == NCTA - 1) {
            g_count = 0u;
            asm volatile("st.release.gpu.u32 [%0], %1;" :: "l"(&g_sense), "r"(gen) : "memory");
        }
    }
}
__device__ __forceinline__ void gbar_wait(unsigned gen) {
    if (threadIdx.x == 0) {
        unsigned s;
        do {
            asm volatile("ld.acquire.gpu.u32 %0, [%1];" : "=r"(s) : "l"(&g_sense) : "memory");
        } while (s < gen);
    }
    __syncthreads();
}

#define RS 144          // stage tile row stride (72 halves)
#define GH_T   9216     // gH tile: 64 rows x RS
#define STG    18432    // unified stage size (gH: A|B ; gG: Ah 128 rows)
#define SM_WT    55296  // after 3 stages
#define WT_RSB   528
#define WT_SZ    67584
#define SM_WOT   190464 // SM_WT + 2*WT_SZ
#define WOT_SZ   17408  // 64 rows x 272
#define OUT_RSB  272
#define SM_TOTAL 225280 // SM_WOT + 2*WOT_SZ

// ---------------------------------------------------------------------------
__global__ void k_dinv(const float* __restrict__ A) {
    int row = blockIdx.x;
    const float* arow = A + (size_t)row * Nc;
    float s = 0.f;
    for (int j = threadIdx.x; j < Nc; j += blockDim.x) s += arow[j];
    __shared__ float sh[128];
    sh[threadIdx.x] = s;
    __syncthreads();
    for (int off = 64; off > 0; off >>= 1) {
        if (threadIdx.x < off) sh[threadIdx.x] += sh[threadIdx.x + off];
        __syncthreads();
    }
    if (threadIdx.x == 0) {
        float d = sh[0];
        g_dinv[row] = (d > 0.f) ? rsqrtf(d) : 0.f;
    }
}

__global__ void k_an(const float* __restrict__ A) {
    int idx = blockIdx.x * blockDim.x + threadIdx.x;
    int e = idx * 4;
    int b   = e >> 18;
    int rem = e & 262143;
    int i   = rem >> 9;
    int j   = rem & 511;
    float4 a = *(const float4*)(A + (size_t)e);
    float di = g_dinv[b * 512 + i];
    const float* dj = g_dinv + b * 512 + j;
    __half2* ph = (__half2*)(g_Anh + (size_t)e);
    ph[0] = __halves2half2(__float2half_rn(a.x * di * dj[0]),
                           __float2half_rn(a.y * di * dj[1]));
    ph[1] = __halves2half2(__float2half_rn(a.z * di * dj[2]),
                           __float2half_rn(a.w * di * dj[3]));
}

// ---------------------------------------------------------------------------
__global__ void k_prep(const float* __restrict__ Wii, const float* __restrict__ bii,
                       const float* __restrict__ Whi, const float* __restrict__ bhi,
                       const float* __restrict__ Wif, const float* __restrict__ bif_,
                       const float* __restrict__ Whf, const float* __restrict__ bhf,
                       const float* __restrict__ Wig, const float* __restrict__ big_,
                       const float* __restrict__ Whg, const float* __restrict__ bhg,
                       const float* __restrict__ Wio, const float* __restrict__ bio,
                       const float* __restrict__ Who, const float* __restrict__ bho,
                       const float* __restrict__ Wpe, const float* __restrict__ bpe) {
    int n = blockIdx.x;
    int g = n & 3;
    int j = n >> 2;
    int t = threadIdx.x;
    const float* Wi = (g == 0) ? Wii : (g == 1) ? Wif : (g == 2) ? Wig : Wio;
    const float* Wh = (g == 0) ? Whi : (g == 1) ? Whf : (g == 2) ? Whg : Who;
    const float* bi = (g == 0) ? bii : (g == 1) ? bif_ : (g == 2) ? big_ : bio;
    const float* bh = (g == 0) ? bhi : (g == 1) ? bhf : (g == 2) ? bhg : bho;

    __shared__ float wcol[128];
    wcol[t] = Wi[(128 + t) * 128 + j];
    __syncthreads();

    g_Wes[t * 512 + n] = Wi[t * 128 + j];

    float acc = 0.f;
    const float* wpet = Wpe + t * 128;
#pragma unroll 8
    for (int m = 0; m < 128; m++) acc += wpet[m] * wcol[m];

    __half hh, ll;
    hsplit(acc, hh, ll);
    g_WTh[n * 256 + t] = hh;
    g_WTl[n * 256 + t] = ll;
    float whv = Wh[t * 128 + j];
    hsplit(whv, hh, ll);
    g_WTh[n * 256 + 128 + t] = hh;
    g_WTl[n * 256 + 128 + t] = ll;

    if (t == 0) {
        float ba = bi[j] + bh[j];
        for (int m = 0; m < 128; m++) ba += bpe[m] * wcol[m];
        g_bbig[n] = ba;
    }
}

// ---------------------------------------------------------------------------
__global__ void k_init(const float* __restrict__ X, const float* __restrict__ Wse,
                       const float* __restrict__ bse, const float* __restrict__ Wout,
                       float* __restrict__ out) {
    int row = blockIdx.x;
    int t = threadIdx.x;
    if (row == 0 && t == 0) { g_count = 0u; g_sense = 0u; }
    if (row < 64) {
        __half hh, ll;
        hsplit(Wout[t * 64 + row], hh, ll);
        g_WoTh[row * 128 + t] = hh;
        g_WoTl[row * 128 + t] = ll;
    }
    __shared__ float x0[64];
    if (t < 64) {
        float v = X[(size_t)row * 4096 + t];
        x0[t] = v;
        g_Xi[row * 64 + t] = v;
        out[(size_t)row * 4096 + t] = v;
    }
    __syncthreads();
    float acc = bse[t];
#pragma unroll 8
    for (int k = 0; k < 64; k++) acc += x0[k] * Wse[k * 128 + t];
    g_es[row * 128 + t] = acc;

    g_hrh[0][(size_t)row * 128 + t] = __float2half(0.f);
    g_c[row * 128 + t] = 0.f;
}

// ---------------------------------------------------------------------------
// k_ges: Ges = es @ Wes + bbig (4096 x 512, K=128) fp32, runs once
// ---------------------------------------------------------------------------
__global__ void __launch_bounds__(256) k_ges() {
    int m0 = (blockIdx.x >> 2) * 64;
    int n0 = (blockIdx.x & 3) * 128;

    __shared__ __align__(16) float As[16][68];
    __shared__ __align__(16) float Bs[16][132];

    int tid = threadIdx.x;
    int ty = tid >> 4, tx = tid & 15;
    int ar = tid >> 2, ac = (tid & 3) * 4;
    int br = tid >> 5, bc = (tid & 31) * 4;

    float acc[4][8] = {};

    for (int k0 = 0; k0 < 128; k0 += 16) {
        float4 av = *(const float4*)&g_es[(size_t)(m0 + ar) * 128 + k0 + ac];
        float4 bv0 = *(const float4*)&g_Wes[(size_t)(k0 + br) * 512 + n0 + bc];
        float4 bv1 = *(const float4*)&g_Wes[(size_t)(k0 + br + 8) * 512 + n0 + bc];
        As[ac + 0][ar] = av.x; As[ac + 1][ar] = av.y;
        As[ac + 2][ar] = av.z; As[ac + 3][ar] = av.w;
        *(float4*)&Bs[br][bc] = bv0;
        *(float4*)&Bs[br + 8][bc] = bv1;
        __syncthreads();
#pragma unroll
        for (int kk = 0; kk < 16; kk++) {
            float4 a4 = *(const float4*)&As[kk][ty * 4];
            float4 b0 = *(const float4*)&Bs[kk][tx * 8];
            float4 b1 = *(const float4*)&Bs[kk][tx * 8 + 4];
            float av4[4] = { a4.x, a4.y, a4.z, a4.w };
            float bv8[8] = { b0.x, b0.y, b0.z, b0.w, b1.x, b1.y, b1.z, b1.w };
#pragma unroll
            for (int i = 0; i < 4; i++)
#pragma unroll
                for (int jq = 0; jq < 8; jq++) acc[i][jq] += av4[i] * bv8[jq];
        }
        __syncthreads();
    }

    float bb[8];
#pragma unroll
    for (int q = 0; q < 8; q++) bb[q] = g_bbig[n0 + tx * 8 + q];
#pragma unroll
    for (int r = 0; r < 4; r++) {
        int rr = m0 + ty * 4 + r;
        float* dst = &g_Ges[(size_t)rr * 512 + n0 + tx * 8];
#pragma unroll
        for (int q = 0; q < 8; q++) dst[q] = acc[r][q] + bb[q];
    }
}

// ---------------------------------------------------------------------------
// phase gH: H = An @ h, CTA tile 64x64 (8b x 8m x 2n = 128 tiles)
// B loaded ROW-MAJOR from g_hrh (h[node][feature]); fragments via ldmatrix.trans.
// An loads for chunks 0,1 issued BEFORE the bar2 wait. 3-stage pipeline.
// ---------------------------------------------------------------------------
__device__ __forceinline__ void phase_gH(char* dsm, int hin, int cta, int tid,
                                         unsigned wait_gen) {
    uint32_t sbase = smem_u32(dsm);
    int wid = tid >> 5, lane = tid & 31;
    int wm = wid >> 2, wn = wid & 3;
    int b  = cta >> 4;
    int m0 = ((cta >> 1) & 7) * 64;
    int n0 = (cta & 1) * 64;

    float acc[2][2][4];
#pragma unroll
    for (int i = 0; i < 2; i++)
#pragma unroll
        for (int j = 0; j < 2; j++)
#pragma unroll
            for (int q = 0; q < 4; q++) acc[i][j][q] = 0.f;

    const __half* Ah0 = g_Anh + (size_t)b * 262144 + (size_t)m0 * 512;
    const __half* Bh0 = g_hrh[hin] + (size_t)b * 512 * 128 + n0;   // rows = nodes

    auto stg = [&](int cc) -> uint32_t { return sbase + (uint32_t)(cc % 3) * STG; };

    auto issueA = [&](int cc) {
        uint32_t buf = stg(cc);
        int kc = cc * 64;
#pragma unroll
        for (int i = 0; i < 2; i++) {
            int idx = tid + i * 256, r = idx >> 3, c = idx & 7;
            cpa16(buf + r * RS + c * 16, Ah0 + (size_t)r * 512 + kc + c * 8);
        }
    };
    auto issueB = [&](int cc) {
        uint32_t buf = stg(cc);
        int kc = cc * 64;
#pragma unroll
        for (int i = 0; i < 2; i++) {
            int idx = tid + i * 256, r = idx >> 3, c = idx & 7;
            // B tile row r = node kc+r, cols = features n0..n0+63
            cpa16(buf + GH_T + r * RS + c * 16, Bh0 + (size_t)(kc + r) * 128 + c * 8);
        }
    };
    auto issue = [&](int cc) { issueA(cc); issueB(cc); };

    // An for chunks 0,1 prefetched across the bar2 wait
    issueA(0); CP_COMMIT();
    issueA(1); CP_COMMIT();
    gbar_wait(wait_gen);          // h(t-1) complete grid-wide
    issueB(0); CP_COMMIT();
    issueB(1); CP_COMMIT();

    // trans-B lane address: block rows = k, cols = n (within-tile)
    uint32_t bOff = (uint32_t)((lane & 7) + ((lane >> 3) & 1) * 8) * RS
                  + (uint32_t)(wn * 16 + ((lane >> 4) & 1) * 8) * 2;

#pragma unroll 1
    for (int cc = 0; cc < 8; cc++) {
        CP_WAIT1();
        __syncthreads();

        uint32_t buf = stg(cc);
        uint32_t aH = buf + (uint32_t)(wm * 32 + (lane & 15)) * RS + ((lane >> 4) * 16);
        uint32_t bB = buf + GH_T + bOff;
#pragma unroll
        for (int ks = 0; ks < 4; ks++) {
            uint32_t ah[2][4], bh[4];
            ldsm4(ah[0], aH + ks * 32); ldsm4(ah[1], aH + 16 * RS + ks * 32);
            ldsm4t(bh, bB + ks * 16 * RS);
#pragma unroll
            for (int mf = 0; mf < 2; mf++) {
                mmaf(acc[mf][0], ah[mf], &bh[0]); mmaf(acc[mf][1], ah[mf], &bh[2]);
            }
        }
        __syncthreads();
        if (cc + 2 < 8) { issue(cc + 2); CP_COMMIT(); }
    }
    CP_WAIT0();

    // epilogue: H fp16
    int rbase = b * 512 + m0 + wm * 32 + (lane >> 2);
    int cbase = n0 + wn * 16 + (lane & 3) * 2;
#pragma unroll
    for (int mf = 0; mf < 2; mf++) {
#pragma unroll
        for (int nf = 0; nf < 2; nf++) {
            int col = cbase + nf * 8;
            float* d = acc[mf][nf];
            int r0 = rbase + mf * 16;
            *(__half2*)(g_Hh + (size_t)r0 * 128 + col) =
                __halves2half2(__float2half_rn(d[0]), __float2half_rn(d[1]));
            *(__half2*)(g_Hh + (size_t)(r0 + 8) * 128 + col) =
                __halves2half2(__float2half_rn(d[2]), __float2half_rn(d[3]));
        }
    }
}

// ---------------------------------------------------------------------------
// phase gG (barrier-overlapped, 3-stage): gates = Ges + [H | h] @ Wcomb.
// Order: c2 -> bar wait -> issue c0,c1 -> c3 (loads fly) -> c0 -> c1 -> epi.
// Epilogue staged in two 64-row halves (fp32). No transpose (hT eliminated).
// ---------------------------------------------------------------------------
__device__ __forceinline__ void phase_gG(char* dsm, int hin, int hout, int cta, int tid,
                                         unsigned wait_gen) {
    uint32_t sbase = smem_u32(dsm);
    int wid = tid >> 5, lane = tid & 31;
    int wm = wid >> 2, wn = wid & 3;
    int m0 = (cta >> 2) * 128;
    int n0 = (cta & 3) * 128;

    float acc[4][4][4];
    uint32_t hacc[4][4][2];
#pragma unroll
    for (int i = 0; i < 4; i++)
#pragma unroll
        for (int j = 0; j < 4; j++) {
#pragma unroll
            for (int q = 0; q < 4; q++) acc[i][j][q] = 0.f;
            hacc[i][j][0] = 0u; hacc[i][j][1] = 0u;
        }

    auto issue = [&](int cc, uint32_t buf) {
        int kc = cc * 64;
        const __half* Ahs = (kc < 128)
            ? g_Hh + (size_t)m0 * 128 + kc
            : g_hrh[hin] + (size_t)m0 * 128 + (kc - 128);
#pragma unroll
        for (int i = 0; i < 4; i++) {
            int idx = tid + i * 256, r = idx >> 3, c = idx & 7;
            cpa16(buf + r * RS + c * 16, Ahs + (size_t)r * 128 + c * 8);
        }
    };

    uint32_t wtH = sbase + SM_WT
                 + (uint32_t)(wn * 32 + (lane & 7) + ((lane >> 4) & 1) * 8) * WT_RSB
                 + (((lane >> 3) & 1) * 16);
    uint32_t wtL = wtH + WT_SZ;

    auto compute = [&](int cc, uint32_t buf) {
        uint32_t aH = buf + (uint32_t)(wm * 64 + (lane & 15)) * RS + ((lane >> 4) * 16);
        uint32_t kb = (uint32_t)cc * 128;
#pragma unroll
        for (int ks = 0; ks < 4; ks++) {
            uint32_t ah[4][4], bh0[4], bh1[4], bl0[4], bl1[4];
#pragma unroll
            for (int mf = 0; mf < 4; mf++)
                ldsm4(ah[mf], aH + mf * 16 * RS + ks * 32);
            ldsm4(bh0, wtH + kb + ks * 32);
            ldsm4(bh1, wtH + 16 * WT_RSB + kb + ks * 32);
            ldsm4(bl0, wtL + kb + ks * 32);
            ldsm4(bl1, wtL + 16 * WT_RSB + kb + ks * 32);
#pragma unroll
            for (int mf = 0; mf < 4; mf++) {
                mmaf(acc[mf][0], ah[mf], &bh0[0]); mmaf(acc[mf][1], ah[mf], &bh0[2]);
                mmaf(acc[mf][2], ah[mf], &bh1[0]); mmaf(acc[mf][3], ah[mf], &bh1[2]);
                mmah(hacc[mf][0], ah[mf], &bl0[0]); mmah(hacc[mf][1], ah[mf], &bl0[2]);
                mmah(hacc[mf][2], ah[mf], &bl1[0]); mmah(hacc[mf][3], ah[mf], &bl1[2]);
            }
        }
    };

    uint32_t s0 = sbase, s1 = sbase + STG, s2 = sbase + 2 * STG;

    // part 1: h-part chunk 2 (chunk 3 loading)
    issue(2, s0); CP_COMMIT();
    issue(3, s1); CP_COMMIT();
    CP_WAIT1();
    __syncthreads();
    compute(2, s0);

    // barrier wait: H(t) complete grid-wide
    gbar_wait(wait_gen);

    // issue H-part loads, compute chunk 3 while they fly
    issue(0, s2); CP_COMMIT();
    issue(1, s0); CP_COMMIT();
    CP_WAIT2();
    __syncthreads();
    compute(3, s1);
    CP_WAIT1();
    __syncthreads();
    compute(0, s2);
    CP_WAIT0();
    __syncthreads();
    compute(1, s0);

    // merge weight corrections once
#pragma unroll
    for (int mf = 0; mf < 4; mf++)
#pragma unroll
        for (int nf = 0; nf < 4; nf++) hmerge(acc[mf][nf], hacc[mf][nf]);

    // epilogue: two 64-row halves; fused gate math + row-major h writes only
    float* cst = (float*)dsm;                 // [64][132] = 33792
    int q  = tid & 31;
    int rb = tid >> 5;
    int j  = (n0 >> 2) + q;
    __half* hrho = g_hrh[hout];
#pragma unroll
    for (int half = 0; half < 2; half++) {
        __syncthreads();
        if (wm == half) {
#pragma unroll
            for (int mf = 0; mf < 4; mf++) {
#pragma unroll
                for (int nf = 0; nf < 4; nf++) {
                    int row = mf * 16 + (lane >> 2);
                    int col = wn * 32 + nf * 8 + (lane & 3) * 2;
                    float* d = acc[mf][nf];
                    *(float2*)&cst[row * 132 + col]       = make_float2(d[0], d[1]);
                    *(float2*)&cst[(row + 8) * 132 + col] = make_float2(d[2], d[3]);
                }
            }
        }
        __syncthreads();
#pragma unroll
        for (int i = 0; i < 8; i++) {
            int rl = rb + i * 8;
            int r  = half * 64 + rl;
            int rr = m0 + r;
            float4 pv = *(float4*)&cst[rl * 132 + q * 4];
            float4 ge = *(const float4*)&g_Ges[(size_t)rr * 512 + j * 4];
            float iv = sigm(pv.x + ge.x), fv = sigm(pv.y + ge.y);
            float gv = ftanh(pv.z + ge.z), ov = sigm(pv.w + ge.w);
            size_t cidx = (size_t)rr * 128 + j;
            float cc = fv * g_c[cidx] + iv * gv;
            g_c[cidx] = cc;
            float hv = ov * ftanh(cc);
            hrho[cidx] = __float2half_rn(hv);
        }
    }
    __syncthreads();
}

// ---------------------------------------------------------------------------
// phase out: Xi += h @ Wout + bout ; emit out[:, :, t, :]
// WoT hi/lo persistent in smem; only h (8.5 KB) loaded per call.
// ---------------------------------------------------------------------------
__device__ __forceinline__ void phase_out(char* dsm, int t, int hidx,
                                          const float* __restrict__ bout,
                                          float* __restrict__ out, int cta, int tid) {
    uint32_t sbase = smem_u32(dsm);
    int wid = tid >> 5, lane = tid & 31;
    int mw = wid & 1, nw = wid >> 1;
    int row0 = cta * 32;
    __syncthreads();

    {
        const __half* hh = g_hrh[hidx] + (size_t)row0 * 128;
#pragma unroll
        for (int i = 0; i < 2; i++) {
            int idx = tid + i * 256, r = idx >> 4, c = idx & 15;
            cpa16(sbase + r * OUT_RSB + c * 16, hh + (size_t)r * 128 + c * 8);
        }
        CP_COMMIT();
    }

    int rA = row0 + mw * 16 + (lane >> 2);
    int cA = nw * 16 + (lane & 3) * 2;
    float2 xi[2][2], bo[2];
#pragma unroll
    for (int nf = 0; nf < 2; nf++) {
        int col = cA + nf * 8;
        xi[nf][0] = *(const float2*)&g_Xi[rA * 64 + col];
        xi[nf][1] = *(const float2*)&g_Xi[(rA + 8) * 64 + col];
        bo[nf] = *(const float2*)&bout[col];
    }

    CP_WAIT0();
    __syncthreads();

    uint32_t aH = sbase + (uint32_t)(mw * 16 + (lane & 15)) * OUT_RSB + ((lane >> 4) * 16);
    uint32_t bH = sbase + SM_WOT
                + (uint32_t)(nw * 16 + (lane & 7) + ((lane >> 4) & 1) * 8) * OUT_RSB
                + (((lane >> 3) & 1) * 16);
    uint32_t bL = bH + WOT_SZ;

    float acc[2][4] = {};
    uint32_t hacc[2][2] = {};
#pragma unroll
    for (int ks = 0; ks < 8; ks++) {
        uint32_t ah[4], bh[4], bl[4];
        ldsm4(ah, aH + ks * 32);
        ldsm4(bh, bH + ks * 32);
        ldsm4(bl, bL + ks * 32);
        mmaf(acc[0], ah, &bh[0]); mmaf(acc[1], ah, &bh[2]);
        mmah(hacc[0], ah, &bl[0]); mmah(hacc[1], ah, &bl[2]);
    }

#pragma unroll
    for (int nf = 0; nf < 2; nf++) {
        hmerge(acc[nf], hacc[nf]);
        int col = cA + nf * 8;
        float2 v0 = make_float2(acc[nf][0] + xi[nf][0].x + bo[nf].x,
                                acc[nf][1] + xi[nf][0].y + bo[nf].y);
        float2 v1 = make_float2(acc[nf][2] + xi[nf][1].x + bo[nf].x,
                                acc[nf][3] + xi[nf][1].y + bo[nf].y);
        *(float2*)&g_Xi[rA * 64 + col] = v0;
        *(float2*)&g_Xi[(rA + 8) * 64 + col] = v1;
        *(float2*)&out[(size_t)rA * 4096 + t * 64 + col] = v0;
        *(float2*)&out[(size_t)(rA + 8) * 4096 + t * 64 + col] = v1;
    }
    __syncthreads();
}

// ---------------------------------------------------------------------------
// k_main: persistent kernel, 63 steps. bar2 is arrive-only; its wait is
// folded into the next step's gH (An prefetched across the wait).
// ---------------------------------------------------------------------------
__global__ void __launch_bounds__(256) k_main(const float* __restrict__ bout,
                                              float* __restrict__ out) {
    extern __shared__ __align__(16) char dsm[];
    int cta = blockIdx.x, tid = threadIdx.x;

    // persistent weight slices: WT (per-CTA n-tile) + WoT (shared)
    {
        int n0 = (cta & 3) * 128;
        uint32_t wt = smem_u32(dsm) + SM_WT;
#pragma unroll
        for (int i = 0; i < 16; i++) {
            int idx = tid + i * 256;
            int r = idx >> 5, c = idx & 31;
            cpa16(wt + r * WT_RSB + c * 16,         g_WTh + (size_t)(n0 + r) * 256 + c * 8);
            cpa16(wt + WT_SZ + r * WT_RSB + c * 16, g_WTl + (size_t)(n0 + r) * 256 + c * 8);
        }
        uint32_t wo = smem_u32(dsm) + SM_WOT;
#pragma unroll
        for (int i = 0; i < 4; i++) {
            int idx = tid + i * 256;
            int r = idx >> 4, c = idx & 15;
            cpa16(wo + r * OUT_RSB + c * 16,          g_WoTh + (size_t)r * 128 + c * 8);
            cpa16(wo + WOT_SZ + r * OUT_RSB + c * 16, g_WoTl + (size_t)r * 128 + c * 8);
        }
        CP_COMMIT();
        CP_WAIT0();
    }
    __syncthreads();

    unsigned gen = 0;
#pragma unroll 1
    for (int t = 1; t < Tc; t++) {
        int hin = (t - 1) & 1, hout = t & 1;
        phase_gH(dsm, hin, cta, tid, gen);           // waits bar2(t-1) after An prefetch
        ++gen;
        gbar_arrive(gen);                            // bar1: this CTA's H done
        if (t >= 2) phase_out(dsm, t - 1, hin, bout, out, cta, tid);
        phase_gG(dsm, hin, hout, cta, tid, gen);     // h-part + out overlap bar1 wait
        ++gen;
        gbar_arrive(gen);                            // bar2: arrive only
    }
    gbar_wait(gen);
    phase_out(dsm, Tc - 1, (Tc - 1) & 1, bout, out, cta, tid);
}

// ---------------------------------------------------------------------------
extern "C" void kernel_launch(void* const* d_in, const int* in_sizes, int n_in,
                              void* d_out, int out_size) {
    const float* X    = (const float*)d_in[0];
    const float* A    = (const float*)d_in[1];
    const float* Wse  = (const float*)d_in[2];
    const float* bse  = (const float*)d_in[3];
    const float* Wpe  = (const float*)d_in[4];
    const float* bpe  = (const float*)d_in[5];
    const float* Wii  = (const float*)d_in[6];
    const float* bii  = (const float*)d_in[7];
    const float* Whi  = (const float*)d_in[8];
    const float* bhi  = (const float*)d_in[9];
    const float* Wif  = (const float*)d_in[10];
    const float* bif_ = (const float*)d_in[11];
    const float* Whf  = (const float*)d_in[12];
    const float* bhf  = (const float*)d_in[13];
    const float* Wig  = (const float*)d_in[14];
    const float* big_ = (const float*)d_in[15];
    const float* Whg  = (const float*)d_in[16];
    const float* bhg  = (const float*)d_in[17];
    const float* Wio  = (const float*)d_in[18];
    const float* bio  = (const float*)d_in[19];
    const float* Who  = (const float*)d_in[20];
    const float* bho  = (const float*)d_in[21];
    const float* Wout = (const float*)d_in[22];
    const float* bout = (const float*)d_in[23];
    float* out = (float*)d_out;

    cudaFuncSetAttribute(k_main, cudaFuncAttributeMaxDynamicSharedMemorySize, SM_TOTAL);

    k_dinv<<<Rc, 128>>>(A);
    k_an<<<2048, 256>>>(A);
    k_prep<<<512, 128>>>(Wii, bii, Whi, bhi, Wif, bif_, Whf, bhf,
                         Wig, big_, Whg, bhg, Wio, bio, Who, bho, Wpe, bpe);
    k_init<<<Rc, 128>>>(X, Wse, bse, Wout, out);
    k_ges<<<256, 256>>>();
    k_main<<<NCTA, 256, SM_TOTAL>>>(bout, out);
}

// round 15
// speedup vs baseline: 1.6575x; 1.1265x over previous
#include <cuda_runtime.h>
#include <cuda_fp16.h>
#include <math.h>
#include <stdint.h>

// Problem constants
#define Bc   8
#define Nc   512
#define Tc   64
#define NINc 64
#define NHc  128
#define Rc   (Bc * Nc)   // 4096 rows
#define NCTA 128

// ---------------- scratch (device globals) ----------------------------------
__device__ float g_dinv[Rc];
__device__ __half g_Anh[Bc * Nc * Nc];          // An fp16 (4 MB)
__device__ float g_es[Rc * NHc];                // static embedding fp32
__device__ float g_Wes[128 * 512];              // Wi[0:128] interleaved fp32
__device__ float g_bbig[512];
__device__ float g_Ges[Rc * 512];               // es @ Wes + bbig (fp32, interleaved)
__device__ __half g_WTh[512 * 256];             // Wcomb^T fp16: [n][k]
__device__ __half g_WoTh[64 * 128];             // Wout^T hi: [n][k]
__device__ __half g_WoTl[64 * 128];             // Wout^T lo (kept: output path)
__device__ __half g_Hh[Rc * NHc];               // H = An@h, fp16, row-major
__device__ __half g_hrh[2][Rc * NHc];           // h row-major fp16 (double buffered)
__device__ float g_c[Rc * NHc];                 // cell state
__device__ float g_Xi[Rc * NINc];               // running output accumulator
__device__ unsigned g_count;                    // grid barrier arrive counter
__device__ unsigned g_sense;                    // grid barrier generation

// ---------------- helpers ----------------------------------------------------
__device__ __forceinline__ uint32_t smem_u32(const void* p) {
    uint32_t a;
    asm("{ .reg .u64 t; cvta.to.shared.u64 t, %1; cvt.u32.u64 %0, t; }" : "=r"(a) : "l"(p));
    return a;
}
__device__ __forceinline__ float sigm(float x) {
    return __fdividef(1.f, 1.f + __expf(-x));
}
__device__ __forceinline__ float ftanh(float x) {
    float e = __expf(2.f * x);
    return 1.f - __fdividef(2.f, e + 1.f);
}
__device__ __forceinline__ void hsplit(float v, __half& hi, __half& lo) {
    hi = __float2half_rn(v);
    lo = __float2half_rn(v - __half2float(hi));
}
__device__ __forceinline__ void cpa16(uint32_t dst, const void* src) {
    asm volatile("cp.async.cg.shared.global [%0], [%1], 16;" :: "r"(dst), "l"(src) : "memory");
}
#define CP_COMMIT() asm volatile("cp.async.commit_group;" ::: "memory")
#define CP_WAIT2()  asm volatile("cp.async.wait_group 2;" ::: "memory")
#define CP_WAIT1()  asm volatile("cp.async.wait_group 1;" ::: "memory")
#define CP_WAIT0()  asm volatile("cp.async.wait_group 0;" ::: "memory")

__device__ __forceinline__ void ldsm4(uint32_t* r, uint32_t a) {
    asm volatile("ldmatrix.sync.aligned.m8n8.x4.shared.b16 {%0,%1,%2,%3}, [%4];"
        : "=r"(r[0]), "=r"(r[1]), "=r"(r[2]), "=r"(r[3]) : "r"(a));
}
// transposed ldmatrix: row-major [k][n] tile -> B fragments
__device__ __forceinline__ void ldsm4t(uint32_t* r, uint32_t a) {
    asm volatile("ldmatrix.sync.aligned.m8n8.x4.trans.shared.b16 {%0,%1,%2,%3}, [%4];"
        : "=r"(r[0]), "=r"(r[1]), "=r"(r[2]), "=r"(r[3]) : "r"(a));
}
__device__ __forceinline__ void mmaf(float* d, const uint32_t* a, const uint32_t* b) {
    asm volatile("mma.sync.aligned.m16n8k16.row.col.f32.f16.f16.f32 "
        "{%0,%1,%2,%3}, {%4,%5,%6,%7}, {%8,%9}, {%0,%1,%2,%3};"
        : "+f"(d[0]), "+f"(d[1]), "+f"(d[2]), "+f"(d[3])
        : "r"(a[0]), "r"(a[1]), "r"(a[2]), "r"(a[3]), "r"(b[0]), "r"(b[1]));
}
__device__ __forceinline__ void mmah(uint32_t* d, const uint32_t* a, const uint32_t* b) {
    asm volatile("mma.sync.aligned.m16n8k16.row.col.f16.f16.f16.f16 "
        "{%0,%1}, {%2,%3,%4,%5}, {%6,%7}, {%0,%1};"
        : "+r"(d[0]), "+r"(d[1])
        : "r"(a[0]), "r"(a[1]), "r"(a[2]), "r"(a[3]), "r"(b[0]), "r"(b[1]));
}
__device__ __forceinline__ void hmerge(float* d, const uint32_t* h) {
    __half2 q0 = *(const __half2*)&h[0];
    __half2 q1 = *(const __half2*)&h[1];
    d[0] += __half2float(q0.x); d[1] += __half2float(q0.y);
    d[2] += __half2float(q1.x); d[3] += __half2float(q1.y);
}

// grid-wide sense barrier, split into arrive / wait halves
__device__ __forceinline__ void gbar_arrive(unsigned gen) {
    __syncthreads();
    if (threadIdx.x == 0) {
        unsigned prev;
        asm volatile("atom.release.gpu.add.u32 %0, [%1], %2;"
                     : "=r"(prev) : "l"(&g_count), "r"(1u) : "memory");
        if (prev == NCTA - 1) {
            g_count = 0u;
            asm volatile("st.release.gpu.u32 [%0], %1;" :: "l"(&g_sense), "r"(gen) : "memory");
        }
    }
}
__device__ __forceinline__ void gbar_wait(unsigned gen) {
    if (threadIdx.x == 0) {
        unsigned s;
        do {
            asm volatile("ld.acquire.gpu.u32 %0, [%1];" : "=r"(s) : "l"(&g_sense) : "memory");
        } while (s < gen);
    }
    __syncthreads();
}

#define RS 144          // stage tile row stride (72 halves)
#define GH_T   9216     // gH tile: 64 rows x RS
#define STG    18432    // unified stage size
#define SM_WT    55296  // after 3 stages
#define WT_RSB   528
#define WT_SZ    67584
#define SM_WOT   122880 // SM_WT + WT_SZ
#define WOT_SZ   17408
#define OUT_RSB  272
#define SM_TOTAL 157696 // SM_WOT + 2*WOT_SZ

// ---------------------------------------------------------------------------
__global__ void k_dinv(const float* __restrict__ A) {
    int row = blockIdx.x;
    const float* arow = A + (size_t)row * Nc;
    float s = 0.f;
    for (int j = threadIdx.x; j < Nc; j += blockDim.x) s += arow[j];
    __shared__ float sh[128];
    sh[threadIdx.x] = s;
    __syncthreads();
    for (int off = 64; off > 0; off >>= 1) {
        if (threadIdx.x < off) sh[threadIdx.x] += sh[threadIdx.x + off];
        __syncthreads();
    }
    if (threadIdx.x == 0) {
        float d = sh[0];
        g_dinv[row] = (d > 0.f) ? rsqrtf(d) : 0.f;
    }
}

__global__ void k_an(const float* __restrict__ A) {
    int idx = blockIdx.x * blockDim.x + threadIdx.x;
    int e = idx * 4;
    int b   = e >> 18;
    int rem = e & 262143;
    int i   = rem >> 9;
    int j   = rem & 511;
    float4 a = *(const float4*)(A + (size_t)e);
    float di = g_dinv[b * 512 + i];
    const float* dj = g_dinv + b * 512 + j;
    __half2* ph = (__half2*)(g_Anh + (size_t)e);
    ph[0] = __halves2half2(__float2half_rn(a.x * di * dj[0]),
                           __float2half_rn(a.y * di * dj[1]));
    ph[1] = __halves2half2(__float2half_rn(a.z * di * dj[2]),
                           __float2half_rn(a.w * di * dj[3]));
}

// ---------------------------------------------------------------------------
__global__ void k_prep(const float* __restrict__ Wii, const float* __restrict__ bii,
                       const float* __restrict__ Whi, const float* __restrict__ bhi,
                       const float* __restrict__ Wif, const float* __restrict__ bif_,
                       const float* __restrict__ Whf, const float* __restrict__ bhf,
                       const float* __restrict__ Wig, const float* __restrict__ big_,
                       const float* __restrict__ Whg, const float* __restrict__ bhg,
                       const float* __restrict__ Wio, const float* __restrict__ bio,
                       const float* __restrict__ Who, const float* __restrict__ bho,
                       const float* __restrict__ Wpe, const float* __restrict__ bpe) {
    int n = blockIdx.x;
    int g = n & 3;
    int j = n >> 2;
    int t = threadIdx.x;
    const float* Wi = (g == 0) ? Wii : (g == 1) ? Wif : (g == 2) ? Wig : Wio;
    const float* Wh = (g == 0) ? Whi : (g == 1) ? Whf : (g == 2) ? Whg : Who;
    const float* bi = (g == 0) ? bii : (g == 1) ? bif_ : (g == 2) ? big_ : bio;
    const float* bh = (g == 0) ? bhi : (g == 1) ? bhf : (g == 2) ? bhg : bho;

    __shared__ float wcol[128];
    wcol[t] = Wi[(128 + t) * 128 + j];
    __syncthreads();

    g_Wes[t * 512 + n] = Wi[t * 128 + j];

    float acc = 0.f;
    const float* wpet = Wpe + t * 128;
#pragma unroll 8
    for (int m = 0; m < 128; m++) acc += wpet[m] * wcol[m];

    g_WTh[n * 256 + t]       = __float2half_rn(acc);
    g_WTh[n * 256 + 128 + t] = __float2half_rn(Wh[t * 128 + j]);

    if (t == 0) {
        float ba = bi[j] + bh[j];
        for (int m = 0; m < 128; m++) ba += bpe[m] * wcol[m];
        g_bbig[n] = ba;
    }
}

// ---------------------------------------------------------------------------
__global__ void k_init(const float* __restrict__ X, const float* __restrict__ Wse,
                       const float* __restrict__ bse, const float* __restrict__ Wout,
                       float* __restrict__ out) {
    int row = blockIdx.x;
    int t = threadIdx.x;
    if (row == 0 && t == 0) { g_count = 0u; g_sense = 0u; }
    if (row < 64) {
        __half hh, ll;
        hsplit(Wout[t * 64 + row], hh, ll);
        g_WoTh[row * 128 + t] = hh;
        g_WoTl[row * 128 + t] = ll;
    }
    __shared__ float x0[64];
    if (t < 64) {
        float v = X[(size_t)row * 4096 + t];
        x0[t] = v;
        g_Xi[row * 64 + t] = v;
        out[(size_t)row * 4096 + t] = v;
    }
    __syncthreads();
    float acc = bse[t];
#pragma unroll 8
    for (int k = 0; k < 64; k++) acc += x0[k] * Wse[k * 128 + t];
    g_es[row * 128 + t] = acc;

    g_hrh[0][(size_t)row * 128 + t] = __float2half(0.f);
    g_c[row * 128 + t] = 0.f;
}

// ---------------------------------------------------------------------------
// k_ges: Ges = es @ Wes + bbig (4096 x 512, K=128) fp32, runs once
// ---------------------------------------------------------------------------
__global__ void __launch_bounds__(256) k_ges() {
    int m0 = (blockIdx.x >> 2) * 64;
    int n0 = (blockIdx.x & 3) * 128;

    __shared__ __align__(16) float As[16][68];
    __shared__ __align__(16) float Bs[16][132];

    int tid = threadIdx.x;
    int ty = tid >> 4, tx = tid & 15;
    int ar = tid >> 2, ac = (tid & 3) * 4;
    int br = tid >> 5, bc = (tid & 31) * 4;

    float acc[4][8] = {};

    for (int k0 = 0; k0 < 128; k0 += 16) {
        float4 av = *(const float4*)&g_es[(size_t)(m0 + ar) * 128 + k0 + ac];
        float4 bv0 = *(const float4*)&g_Wes[(size_t)(k0 + br) * 512 + n0 + bc];
        float4 bv1 = *(const float4*)&g_Wes[(size_t)(k0 + br + 8) * 512 + n0 + bc];
        As[ac + 0][ar] = av.x; As[ac + 1][ar] = av.y;
        As[ac + 2][ar] = av.z; As[ac + 3][ar] = av.w;
        *(float4*)&Bs[br][bc] = bv0;
        *(float4*)&Bs[br + 8][bc] = bv1;
        __syncthreads();
#pragma unroll
        for (int kk = 0; kk < 16; kk++) {
            float4 a4 = *(const float4*)&As[kk][ty * 4];
            float4 b0 = *(const float4*)&Bs[kk][tx * 8];
            float4 b1 = *(const float4*)&Bs[kk][tx * 8 + 4];
            float av4[4] = { a4.x, a4.y, a4.z, a4.w };
            float bv8[8] = { b0.x, b0.y, b0.z, b0.w, b1.x, b1.y, b1.z, b1.w };
#pragma unroll
            for (int i = 0; i < 4; i++)
#pragma unroll
                for (int jq = 0; jq < 8; jq++) acc[i][jq] += av4[i] * bv8[jq];
        }
        __syncthreads();
    }

    float bb[8];
#pragma unroll
    for (int q = 0; q < 8; q++) bb[q] = g_bbig[n0 + tx * 8 + q];
#pragma unroll
    for (int r = 0; r < 4; r++) {
        int rr = m0 + ty * 4 + r;
        float* dst = &g_Ges[(size_t)rr * 512 + n0 + tx * 8];
#pragma unroll
        for (int q = 0; q < 8; q++) dst[q] = acc[r][q] + bb[q];
    }
}

// ---------------------------------------------------------------------------
// phase gH: H = An @ h, CTA tile 64x64 (8b x 8m x 2n = 128 tiles)
// B row-major from g_hrh via ldmatrix.trans. An prefetched across bar2 wait.
// ---------------------------------------------------------------------------
__device__ __forceinline__ void phase_gH(char* dsm, int hin, int cta, int tid,
                                         unsigned wait_gen) {
    uint32_t sbase = smem_u32(dsm);
    int wid = tid >> 5, lane = tid & 31;
    int wm = wid >> 2, wn = wid & 3;
    int b  = cta >> 4;
    int m0 = ((cta >> 1) & 7) * 64;
    int n0 = (cta & 1) * 64;

    float acc[2][2][4];
#pragma unroll
    for (int i = 0; i < 2; i++)
#pragma unroll
        for (int j = 0; j < 2; j++)
#pragma unroll
            for (int q = 0; q < 4; q++) acc[i][j][q] = 0.f;

    const __half* Ah0 = g_Anh + (size_t)b * 262144 + (size_t)m0 * 512;
    const __half* Bh0 = g_hrh[hin] + (size_t)b * 512 * 128 + n0;

    auto stg = [&](int cc) -> uint32_t { return sbase + (uint32_t)(cc % 3) * STG; };

    auto issueA = [&](int cc) {
        uint32_t buf = stg(cc);
        int kc = cc * 64;
#pragma unroll
        for (int i = 0; i < 2; i++) {
            int idx = tid + i * 256, r = idx >> 3, c = idx & 7;
            cpa16(buf + r * RS + c * 16, Ah0 + (size_t)r * 512 + kc + c * 8);
        }
    };
    auto issueB = [&](int cc) {
        uint32_t buf = stg(cc);
        int kc = cc * 64;
#pragma unroll
        for (int i = 0; i < 2; i++) {
            int idx = tid + i * 256, r = idx >> 3, c = idx & 7;
            cpa16(buf + GH_T + r * RS + c * 16, Bh0 + (size_t)(kc + r) * 128 + c * 8);
        }
    };
    auto issue = [&](int cc) { issueA(cc); issueB(cc); };

    issueA(0); CP_COMMIT();
    issueA(1); CP_COMMIT();
    gbar_wait(wait_gen);          // h(t-1) complete grid-wide
    issueB(0); CP_COMMIT();
    issueB(1); CP_COMMIT();

    uint32_t bOff = (uint32_t)((lane & 7) + ((lane >> 3) & 1) * 8) * RS
                  + (uint32_t)(wn * 16 + ((lane >> 4) & 1) * 8) * 2;

#pragma unroll 1
    for (int cc = 0; cc < 8; cc++) {
        CP_WAIT1();
        __syncthreads();

        uint32_t buf = stg(cc);
        uint32_t aH = buf + (uint32_t)(wm * 32 + (lane & 15)) * RS + ((lane >> 4) * 16);
        uint32_t bB = buf + GH_T + bOff;
#pragma unroll
        for (int ks = 0; ks < 4; ks++) {
            uint32_t ah[2][4], bh[4];
            ldsm4(ah[0], aH + ks * 32); ldsm4(ah[1], aH + 16 * RS + ks * 32);
            ldsm4t(bh, bB + ks * 16 * RS);
#pragma unroll
            for (int mf = 0; mf < 2; mf++) {
                mmaf(acc[mf][0], ah[mf], &bh[0]); mmaf(acc[mf][1], ah[mf], &bh[2]);
            }
        }
        __syncthreads();
        if (cc + 2 < 8) { issue(cc + 2); CP_COMMIT(); }
    }
    CP_WAIT0();

    int rbase = b * 512 + m0 + wm * 32 + (lane >> 2);
    int cbase = n0 + wn * 16 + (lane & 3) * 2;
#pragma unroll
    for (int mf = 0; mf < 2; mf++) {
#pragma unroll
        for (int nf = 0; nf < 2; nf++) {
            int col = cbase + nf * 8;
            float* d = acc[mf][nf];
            int r0 = rbase + mf * 16;
            *(__half2*)(g_Hh + (size_t)r0 * 128 + col) =
                __halves2half2(__float2half_rn(d[0]), __float2half_rn(d[1]));
            *(__half2*)(g_Hh + (size_t)(r0 + 8) * 128 + col) =
                __halves2half2(__float2half_rn(d[2]), __float2half_rn(d[3]));
        }
    }
}

// ---------------------------------------------------------------------------
// phase gG (barrier-overlapped, 3-stage): gates = Ges + [H | h] @ Wcomb.
// Weights pure fp16 (no lo correction). Epilogue in two 64-row halves.
// ---------------------------------------------------------------------------
__device__ __forceinline__ void phase_gG(char* dsm, int hin, int hout, int cta, int tid,
                                         unsigned wait_gen) {
    uint32_t sbase = smem_u32(dsm);
    int wid = tid >> 5, lane = tid & 31;
    int wm = wid >> 2, wn = wid & 3;
    int m0 = (cta >> 2) * 128;
    int n0 = (cta & 3) * 128;

    float acc[4][4][4];
#pragma unroll
    for (int i = 0; i < 4; i++)
#pragma unroll
        for (int j = 0; j < 4; j++)
#pragma unroll
            for (int q = 0; q < 4; q++) acc[i][j][q] = 0.f;

    auto issue = [&](int cc, uint32_t buf) {
        int kc = cc * 64;
        const __half* Ahs = (kc < 128)
            ? g_Hh + (size_t)m0 * 128 + kc
            : g_hrh[hin] + (size_t)m0 * 128 + (kc - 128);
#pragma unroll
        for (int i = 0; i < 4; i++) {
            int idx = tid + i * 256, r = idx >> 3, c = idx & 7;
            cpa16(buf + r * RS + c * 16, Ahs + (size_t)r * 128 + c * 8);
        }
    };

    uint32_t wtH = sbase + SM_WT
                 + (uint32_t)(wn * 32 + (lane & 7) + ((lane >> 4) & 1) * 8) * WT_RSB
                 + (((lane >> 3) & 1) * 16);

    auto compute = [&](int cc, uint32_t buf) {
        uint32_t aH = buf + (uint32_t)(wm * 64 + (lane & 15)) * RS + ((lane >> 4) * 16);
        uint32_t kb = (uint32_t)cc * 128;
#pragma unroll
        for (int ks = 0; ks < 4; ks++) {
            uint32_t ah[4][4], bh0[4], bh1[4];
#pragma unroll
            for (int mf = 0; mf < 4; mf++)
                ldsm4(ah[mf], aH + mf * 16 * RS + ks * 32);
            ldsm4(bh0, wtH + kb + ks * 32);
            ldsm4(bh1, wtH + 16 * WT_RSB + kb + ks * 32);
#pragma unroll
            for (int mf = 0; mf < 4; mf++) {
                mmaf(acc[mf][0], ah[mf], &bh0[0]); mmaf(acc[mf][1], ah[mf], &bh0[2]);
                mmaf(acc[mf][2], ah[mf], &bh1[0]); mmaf(acc[mf][3], ah[mf], &bh1[2]);
            }
        }
    };

    uint32_t s0 = sbase, s1 = sbase + STG, s2 = sbase + 2 * STG;

    // part 1: h-part chunk 2 (chunk 3 loading)
    issue(2, s0); CP_COMMIT();
    issue(3, s1); CP_COMMIT();
    CP_WAIT1();
    __syncthreads();
    compute(2, s0);

    gbar_wait(wait_gen);          // H(t) complete grid-wide

    issue(0, s2); CP_COMMIT();
    issue(1, s0); CP_COMMIT();
    CP_WAIT2();
    __syncthreads();
    compute(3, s1);
    CP_WAIT1();
    __syncthreads();
    compute(0, s2);
    CP_WAIT0();
    __syncthreads();
    compute(1, s0);

    // epilogue: two 64-row halves; fused gate math + row-major h writes
    float* cst = (float*)dsm;                 // [64][132] = 33792
    int q  = tid & 31;
    int rb = tid >> 5;
    int j  = (n0 >> 2) + q;
    __half* hrho = g_hrh[hout];
#pragma unroll
    for (int half = 0; half < 2; half++) {
        __syncthreads();
        if (wm == half) {
#pragma unroll
            for (int mf = 0; mf < 4; mf++) {
#pragma unroll
                for (int nf = 0; nf < 4; nf++) {
                    int row = mf * 16 + (lane >> 2);
                    int col = wn * 32 + nf * 8 + (lane & 3) * 2;
                    float* d = acc[mf][nf];
                    *(float2*)&cst[row * 132 + col]       = make_float2(d[0], d[1]);
                    *(float2*)&cst[(row + 8) * 132 + col] = make_float2(d[2], d[3]);
                }
            }
        }
        __syncthreads();
#pragma unroll
        for (int i = 0; i < 8; i++) {
            int rl = rb + i * 8;
            int r  = half * 64 + rl;
            int rr = m0 + r;
            float4 pv = *(float4*)&cst[rl * 132 + q * 4];
            float4 ge = *(const float4*)&g_Ges[(size_t)rr * 512 + j * 4];
            float iv = sigm(pv.x + ge.x), fv = sigm(pv.y + ge.y);
            float gv = ftanh(pv.z + ge.z), ov = sigm(pv.w + ge.w);
            size_t cidx = (size_t)rr * 128 + j;
            float cc = fv * g_c[cidx] + iv * gv;
            g_c[cidx] = cc;
            float hv = ov * ftanh(cc);
            hrho[cidx] = __float2half_rn(hv);
        }
    }
    __syncthreads();
}

// ---------------------------------------------------------------------------
// phase out: Xi += h @ Wout + bout ; emit out[:, :, t, :]
// WoT hi/lo persistent in smem; only h (8.5 KB) loaded per call.
// ---------------------------------------------------------------------------
__device__ __forceinline__ void phase_out(char* dsm, int t, int hidx,
                                          const float* __restrict__ bout,
                                          float* __restrict__ out, int cta, int tid) {
    uint32_t sbase = smem_u32(dsm);
    int wid = tid >> 5, lane = tid & 31;
    int mw = wid & 1, nw = wid >> 1;
    int row0 = cta * 32;
    __syncthreads();

    {
        const __half* hh = g_hrh[hidx] + (size_t)row0 * 128;
#pragma unroll
        for (int i = 0; i < 2; i++) {
            int idx = tid + i * 256, r = idx >> 4, c = idx & 15;
            cpa16(sbase + r * OUT_RSB + c * 16, hh + (size_t)r * 128 + c * 8);
        }
        CP_COMMIT();
    }

    int rA = row0 + mw * 16 + (lane >> 2);
    int cA = nw * 16 + (lane & 3) * 2;
    float2 xi[2][2], bo[2];
#pragma unroll
    for (int nf = 0; nf < 2; nf++) {
        int col = cA + nf * 8;
        xi[nf][0] = *(const float2*)&g_Xi[rA * 64 + col];
        xi[nf][1] = *(const float2*)&g_Xi[(rA + 8) * 64 + col];
        bo[nf] = *(const float2*)&bout[col];
    }

    CP_WAIT0();
    __syncthreads();

    uint32_t aH = sbase + (uint32_t)(mw * 16 + (lane & 15)) * OUT_RSB + ((lane >> 4) * 16);
    uint32_t bH = sbase + SM_WOT
                + (uint32_t)(nw * 16 + (lane & 7) + ((lane >> 4) & 1) * 8) * OUT_RSB
                + (((lane >> 3) & 1) * 16);
    uint32_t bL = bH + WOT_SZ;

    float acc[2][4] = {};
    uint32_t hacc[2][2] = {};
#pragma unroll
    for (int ks = 0; ks < 8; ks++) {
        uint32_t ah[4], bh[4], bl[4];
        ldsm4(ah, aH + ks * 32);
        ldsm4(bh, bH + ks * 32);
        ldsm4(bl, bL + ks * 32);
        mmaf(acc[0], ah, &bh[0]); mmaf(acc[1], ah, &bh[2]);
        mmah(hacc[0], ah, &bl[0]); mmah(hacc[1], ah, &bl[2]);
    }

#pragma unroll
    for (int nf = 0; nf < 2; nf++) {
        hmerge(acc[nf], hacc[nf]);
        int col = cA + nf * 8;
        float2 v0 = make_float2(acc[nf][0] + xi[nf][0].x + bo[nf].x,
                                acc[nf][1] + xi[nf][0].y + bo[nf].y);
        float2 v1 = make_float2(acc[nf][2] + xi[nf][1].x + bo[nf].x,
                                acc[nf][3] + xi[nf][1].y + bo[nf].y);
        *(float2*)&g_Xi[rA * 64 + col] = v0;
        *(float2*)&g_Xi[(rA + 8) * 64 + col] = v1;
        *(float2*)&out[(size_t)rA * 4096 + t * 64 + col] = v0;
        *(float2*)&out[(size_t)(rA + 8) * 4096 + t * 64 + col] = v1;
    }
    __syncthreads();
}

// ---------------------------------------------------------------------------
// k_main: persistent kernel, 63 steps. bar2 arrive-only (wait folded into gH).
// ---------------------------------------------------------------------------
__global__ void __launch_bounds__(256) k_main(const float* __restrict__ bout,
                                              float* __restrict__ out) {
    extern __shared__ __align__(16) char dsm[];
    int cta = blockIdx.x, tid = threadIdx.x;

    // persistent weight slices: WTh (per-CTA n-tile) + WoT hi/lo (shared)
    {
        int n0 = (cta & 3) * 128;
        uint32_t wt = smem_u32(dsm) + SM_WT;
#pragma unroll
        for (int i = 0; i < 16; i++) {
            int idx = tid + i * 256;
            int r = idx >> 5, c = idx & 31;
            cpa16(wt + r * WT_RSB + c * 16, g_WTh + (size_t)(n0 + r) * 256 + c * 8);
        }
        uint32_t wo = smem_u32(dsm) + SM_WOT;
#pragma unroll
        for (int i = 0; i < 4; i++) {
            int idx = tid + i * 256;
            int r = idx >> 4, c = idx & 15;
            cpa16(wo + r * OUT_RSB + c * 16,          g_WoTh + (size_t)r * 128 + c * 8);
            cpa16(wo + WOT_SZ + r * OUT_RSB + c * 16, g_WoTl + (size_t)r * 128 + c * 8);
        }
        CP_COMMIT();
        CP_WAIT0();
    }
    __syncthreads();

    unsigned gen = 0;
#pragma unroll 1
    for (int t = 1; t < Tc; t++) {
        int hin = (t - 1) & 1, hout = t & 1;
        phase_gH(dsm, hin, cta, tid, gen);           // waits bar2(t-1) after An prefetch
        ++gen;
        gbar_arrive(gen);                            // bar1: this CTA's H done
        if (t >= 2) phase_out(dsm, t - 1, hin, bout, out, cta, tid);
        phase_gG(dsm, hin, hout, cta, tid, gen);     // h-part + out overlap bar1 wait
        ++gen;
        gbar_arrive(gen);                            // bar2: arrive only
    }
    gbar_wait(gen);
    phase_out(dsm, Tc - 1, (Tc - 1) & 1, bout, out, cta, tid);
}

// ---------------------------------------------------------------------------
extern "C" void kernel_launch(void* const* d_in, const int* in_sizes, int n_in,
                              void* d_out, int out_size) {
    const float* X    = (const float*)d_in[0];
    const float* A    = (const float*)d_in[1];
    const float* Wse  = (const float*)d_in[2];
    const float* bse  = (const float*)d_in[3];
    const float* Wpe  = (const float*)d_in[4];
    const float* bpe  = (const float*)d_in[5];
    const float* Wii  = (const float*)d_in[6];
    const float* bii  = (const float*)d_in[7];
    const float* Whi  = (const float*)d_in[8];
    const float* bhi  = (const float*)d_in[9];
    const float* Wif  = (const float*)d_in[10];
    const float* bif_ = (const float*)d_in[11];
    const float* Whf  = (const float*)d_in[12];
    const float* bhf  = (const float*)d_in[13];
    const float* Wig  = (const float*)d_in[14];
    const float* big_ = (const float*)d_in[15];
    const float* Whg  = (const float*)d_in[16];
    const float* bhg  = (const float*)d_in[17];
    const float* Wio  = (const float*)d_in[18];
    const float* bio  = (const float*)d_in[19];
    const float* Who  = (const float*)d_in[20];
    const float* bho  = (const float*)d_in[21];
    const float* Wout = (const float*)d_in[22];
    const float* bout = (const float*)d_in[23];
    float* out = (float*)d_out;

    cudaFuncSetAttribute(k_main, cudaFuncAttributeMaxDynamicSharedMemorySize, SM_TOTAL);

    k_dinv<<<Rc, 128>>>(A);
    k_an<<<2048, 256>>>(A);
    k_prep<<<512, 128>>>(Wii, bii, Whi, bhi, Wif, bif_, Whf, bhf,
                         Wig, big_, Whg, bhg, Wio, bio, Who, bho, Wpe, bpe);
    k_init<<<Rc, 128>>>(X, Wse, bse, Wout, out);
    k_ges<<<256, 256>>>();
    k_main<<<NCTA, 256, SM_TOTAL>>>(bout, out);
}

// round 16
// speedup vs baseline: 1.7269x; 1.0419x over previous
#include <cuda_runtime.h>
#include <cuda_fp16.h>
#include <math.h>
#include <stdint.h>

// Problem constants
#define Bc   8
#define Nc   512
#define Tc   64
#define NINc 64
#define NHc  128
#define Rc   (Bc * Nc)   // 4096 rows
#define NCTA 128

// ---------------- scratch (device globals) ----------------------------------
__device__ float g_dinv[Rc];
__device__ __half g_Anh[Bc * Nc * Nc];          // An fp16 (4 MB)
__device__ float g_es[Rc * NHc];                // static embedding fp32
__device__ float g_Wes[128 * 512];              // Wi[0:128] interleaved fp32
__device__ float g_bbig[512];
__device__ float g_Ges[Rc * 512];               // es @ Wes + bbig (fp32, interleaved)
__device__ __half g_WTh[512 * 256];             // Wcomb^T fp16: [n][k]
__device__ __half g_WoTh[64 * 128];             // Wout^T hi: [n][k]
__device__ __half g_WoTl[64 * 128];             // Wout^T lo (kept: output path)
__device__ __half g_Hh[Rc * NHc];               // H = An@h, fp16, row-major
__device__ __half g_hrh[2][Rc * NHc];           // h row-major fp16 (double buffered)
__device__ float g_c[Rc * NHc];                 // cell state
__device__ float g_Xi[Rc * NINc];               // running output accumulator
__device__ unsigned g_count;                    // grid barrier arrive counter
__device__ unsigned g_sense;                    // grid barrier generation

// ---------------- helpers ----------------------------------------------------
__device__ __forceinline__ uint32_t smem_u32(const void* p) {
    uint32_t a;
    asm("{ .reg .u64 t; cvta.to.shared.u64 t, %1; cvt.u32.u64 %0, t; }" : "=r"(a) : "l"(p));
    return a;
}
__device__ __forceinline__ float sigm(float x) {
    return __fdividef(1.f, 1.f + __expf(-x));
}
__device__ __forceinline__ float ftanh(float x) {
    float e = __expf(2.f * x);
    return 1.f - __fdividef(2.f, e + 1.f);
}
__device__ __forceinline__ void hsplit(float v, __half& hi, __half& lo) {
    hi = __float2half_rn(v);
    lo = __float2half_rn(v - __half2float(hi));
}
__device__ __forceinline__ void cpa16(uint32_t dst, const void* src) {
    asm volatile("cp.async.cg.shared.global [%0], [%1], 16;" :: "r"(dst), "l"(src) : "memory");
}
#define CP_COMMIT() asm volatile("cp.async.commit_group;" ::: "memory")
#define CP_WAIT2()  asm volatile("cp.async.wait_group 2;" ::: "memory")
#define CP_WAIT1()  asm volatile("cp.async.wait_group 1;" ::: "memory")
#define CP_WAIT0()  asm volatile("cp.async.wait_group 0;" ::: "memory")

__device__ __forceinline__ void ldsm4(uint32_t* r, uint32_t a) {
    asm volatile("ldmatrix.sync.aligned.m8n8.x4.shared.b16 {%0,%1,%2,%3}, [%4];"
        : "=r"(r[0]), "=r"(r[1]), "=r"(r[2]), "=r"(r[3]) : "r"(a));
}
// transposed ldmatrix: row-major [k][n] tile -> B fragments
__device__ __forceinline__ void ldsm4t(uint32_t* r, uint32_t a) {
    asm volatile("ldmatrix.sync.aligned.m8n8.x4.trans.shared.b16 {%0,%1,%2,%3}, [%4];"
        : "=r"(r[0]), "=r"(r[1]), "=r"(r[2]), "=r"(r[3]) : "r"(a));
}
__device__ __forceinline__ void mmaf(float* d, const uint32_t* a, const uint32_t* b) {
    asm volatile("mma.sync.aligned.m16n8k16.row.col.f32.f16.f16.f32 "
        "{%0,%1,%2,%3}, {%4,%5,%6,%7}, {%8,%9}, {%0,%1,%2,%3};"
        : "+f"(d[0]), "+f"(d[1]), "+f"(d[2]), "+f"(d[3])
        : "r"(a[0]), "r"(a[1]), "r"(a[2]), "r"(a[3]), "r"(b[0]), "r"(b[1]));
}
__device__ __forceinline__ void mmah(uint32_t* d, const uint32_t* a, const uint32_t* b) {
    asm volatile("mma.sync.aligned.m16n8k16.row.col.f16.f16.f16.f16 "
        "{%0,%1}, {%2,%3,%4,%5}, {%6,%7}, {%0,%1};"
        : "+r"(d[0]), "+r"(d[1])
        : "r"(a[0]), "r"(a[1]), "r"(a[2]), "r"(a[3]), "r"(b[0]), "r"(b[1]));
}
__device__ __forceinline__ void hmerge(float* d, const uint32_t* h) {
    __half2 q0 = *(const __half2*)&h[0];
    __half2 q1 = *(const __half2*)&h[1];
    d[0] += __half2float(q0.x); d[1] += __half2float(q0.y);
    d[2] += __half2float(q1.x); d[3] += __half2float(q1.y);
}

// grid-wide sense barrier, split into arrive / wait halves
__device__ __forceinline__ void gbar_arrive(unsigned gen) {
    __syncthreads();
    if (threadIdx.x == 0) {
        unsigned prev;
        asm volatile("atom.release.gpu.add.u32 %0, [%1], %2;"
                     : "=r"(prev) : "l"(&g_count), "r"(1u) : "memory");
        if (prev == NCTA - 1) {
            g_count = 0u;
            asm volatile("st.release.gpu.u32 [%0], %1;" :: "l"(&g_sense), "r"(gen) : "memory");
        }
    }
}
__device__ __forceinline__ void gbar_wait(unsigned gen) {
    if (threadIdx.x == 0) {
        unsigned s;
        do {
            asm volatile("ld.acquire.gpu.u32 %0, [%1];" : "=r"(s) : "l"(&g_sense) : "memory");
        } while (s < gen);
    }
    __syncthreads();
}

#define RS 144          // stage tile row stride (72 halves)
#define GH_T   9216     // gH tile: 64 rows x RS
#define STG    18432    // unified stage size
#define SM_WT    55296  // after 3 stages
#define WT_RSB   528
#define WT_SZ    67584
#define SM_WOT   122880 // SM_WT + WT_SZ
#define WOT_SZ   17408
#define OUT_RSB  272
#define SM_GES   157696 // SM_WOT + 2*WOT_SZ ; Ges tile 128x128 fp32
#define SM_TOTAL 223232 // SM_GES + 65536

// ---------------------------------------------------------------------------
__global__ void k_dinv(const float* __restrict__ A) {
    int row = blockIdx.x;
    const float* arow = A + (size_t)row * Nc;
    float s = 0.f;
    for (int j = threadIdx.x; j < Nc; j += blockDim.x) s += arow[j];
    __shared__ float sh[128];
    sh[threadIdx.x] = s;
    __syncthreads();
    for (int off = 64; off > 0; off >>= 1) {
        if (threadIdx.x < off) sh[threadIdx.x] += sh[threadIdx.x + off];
        __syncthreads();
    }
    if (threadIdx.x == 0) {
        float d = sh[0];
        g_dinv[row] = (d > 0.f) ? rsqrtf(d) : 0.f;
    }
}

__global__ void k_an(const float* __restrict__ A) {
    int idx = blockIdx.x * blockDim.x + threadIdx.x;
    int e = idx * 4;
    int b   = e >> 18;
    int rem = e & 262143;
    int i   = rem >> 9;
    int j   = rem & 511;
    float4 a = *(const float4*)(A + (size_t)e);
    float di = g_dinv[b * 512 + i];
    const float* dj = g_dinv + b * 512 + j;
    __half2* ph = (__half2*)(g_Anh + (size_t)e);
    ph[0] = __halves2half2(__float2half_rn(a.x * di * dj[0]),
                           __float2half_rn(a.y * di * dj[1]));
    ph[1] = __halves2half2(__float2half_rn(a.z * di * dj[2]),
                           __float2half_rn(a.w * di * dj[3]));
}

// ---------------------------------------------------------------------------
__global__ void k_prep(const float* __restrict__ Wii, const float* __restrict__ bii,
                       const float* __restrict__ Whi, const float* __restrict__ bhi,
                       const float* __restrict__ Wif, const float* __restrict__ bif_,
                       const float* __restrict__ Whf, const float* __restrict__ bhf,
                       const float* __restrict__ Wig, const float* __restrict__ big_,
                       const float* __restrict__ Whg, const float* __restrict__ bhg,
                       const float* __restrict__ Wio, const float* __restrict__ bio,
                       const float* __restrict__ Who, const float* __restrict__ bho,
                       const float* __restrict__ Wpe, const float* __restrict__ bpe) {
    int n = blockIdx.x;
    int g = n & 3;
    int j = n >> 2;
    int t = threadIdx.x;
    const float* Wi = (g == 0) ? Wii : (g == 1) ? Wif : (g == 2) ? Wig : Wio;
    const float* Wh = (g == 0) ? Whi : (g == 1) ? Whf : (g == 2) ? Whg : Who;
    const float* bi = (g == 0) ? bii : (g == 1) ? bif_ : (g == 2) ? big_ : bio;
    const float* bh = (g == 0) ? bhi : (g == 1) ? bhf : (g == 2) ? bhg : bho;

    __shared__ float wcol[128];
    wcol[t] = Wi[(128 + t) * 128 + j];
    __syncthreads();

    g_Wes[t * 512 + n] = Wi[t * 128 + j];

    float acc = 0.f;
    const float* wpet = Wpe + t * 128;
#pragma unroll 8
    for (int m = 0; m < 128; m++) acc += wpet[m] * wcol[m];

    g_WTh[n * 256 + t]       = __float2half_rn(acc);
    g_WTh[n * 256 + 128 + t] = __float2half_rn(Wh[t * 128 + j]);

    if (t == 0) {
        float ba = bi[j] + bh[j];
        for (int m = 0; m < 128; m++) ba += bpe[m] * wcol[m];
        g_bbig[n] = ba;
    }
}

// ---------------------------------------------------------------------------
__global__ void k_init(const float* __restrict__ X, const float* __restrict__ Wse,
                       const float* __restrict__ bse, const float* __restrict__ Wout,
                       float* __restrict__ out) {
    int row = blockIdx.x;
    int t = threadIdx.x;
    if (row == 0 && t == 0) { g_count = 0u; g_sense = 0u; }
    if (row < 64) {
        __half hh, ll;
        hsplit(Wout[t * 64 + row], hh, ll);
        g_WoTh[row * 128 + t] = hh;
        g_WoTl[row * 128 + t] = ll;
    }
    __shared__ float x0[64];
    if (t < 64) {
        float v = X[(size_t)row * 4096 + t];
        x0[t] = v;
        g_Xi[row * 64 + t] = v;
        out[(size_t)row * 4096 + t] = v;
    }
    __syncthreads();
    float acc = bse[t];
#pragma unroll 8
    for (int k = 0; k < 64; k++) acc += x0[k] * Wse[k * 128 + t];
    g_es[row * 128 + t] = acc;

    g_hrh[0][(size_t)row * 128 + t] = __float2half(0.f);
    g_c[row * 128 + t] = 0.f;
}

// ---------------------------------------------------------------------------
// k_ges: Ges = es @ Wes + bbig (4096 x 512, K=128) fp32, runs once
// ---------------------------------------------------------------------------
__global__ void __launch_bounds__(256) k_ges() {
    int m0 = (blockIdx.x >> 2) * 64;
    int n0 = (blockIdx.x & 3) * 128;

    __shared__ __align__(16) float As[16][68];
    __shared__ __align__(16) float Bs[16][132];

    int tid = threadIdx.x;
    int ty = tid >> 4, tx = tid & 15;
    int ar = tid >> 2, ac = (tid & 3) * 4;
    int br = tid >> 5, bc = (tid & 31) * 4;

    float acc[4][8] = {};

    for (int k0 = 0; k0 < 128; k0 += 16) {
        float4 av = *(const float4*)&g_es[(size_t)(m0 + ar) * 128 + k0 + ac];
        float4 bv0 = *(const float4*)&g_Wes[(size_t)(k0 + br) * 512 + n0 + bc];
        float4 bv1 = *(const float4*)&g_Wes[(size_t)(k0 + br + 8) * 512 + n0 + bc];
        As[ac + 0][ar] = av.x; As[ac + 1][ar] = av.y;
        As[ac + 2][ar] = av.z; As[ac + 3][ar] = av.w;
        *(float4*)&Bs[br][bc] = bv0;
        *(float4*)&Bs[br + 8][bc] = bv1;
        __syncthreads();
#pragma unroll
        for (int kk = 0; kk < 16; kk++) {
            float4 a4 = *(const float4*)&As[kk][ty * 4];
            float4 b0 = *(const float4*)&Bs[kk][tx * 8];
            float4 b1 = *(const float4*)&Bs[kk][tx * 8 + 4];
            float av4[4] = { a4.x, a4.y, a4.z, a4.w };
            float bv8[8] = { b0.x, b0.y, b0.z, b0.w, b1.x, b1.y, b1.z, b1.w };
#pragma unroll
            for (int i = 0; i < 4; i++)
#pragma unroll
                for (int jq = 0; jq < 8; jq++) acc[i][jq] += av4[i] * bv8[jq];
        }
        __syncthreads();
    }

    float bb[8];
#pragma unroll
    for (int q = 0; q < 8; q++) bb[q] = g_bbig[n0 + tx * 8 + q];
#pragma unroll
    for (int r = 0; r < 4; r++) {
        int rr = m0 + ty * 4 + r;
        float* dst = &g_Ges[(size_t)rr * 512 + n0 + tx * 8];
#pragma unroll
        for (int q = 0; q < 8; q++) dst[q] = acc[r][q] + bb[q];
    }
}

// ---------------------------------------------------------------------------
// phase gH: H = An @ h, CTA tile 64x64 (8b x 8m x 2n = 128 tiles)
// B row-major from g_hrh via ldmatrix.trans. An prefetched across bar2 wait.
// ---------------------------------------------------------------------------
__device__ __forceinline__ void phase_gH(char* dsm, int hin, int cta, int tid,
                                         unsigned wait_gen) {
    uint32_t sbase = smem_u32(dsm);
    int wid = tid >> 5, lane = tid & 31;
    int wm = wid >> 2, wn = wid & 3;
    int b  = cta >> 4;
    int m0 = ((cta >> 1) & 7) * 64;
    int n0 = (cta & 1) * 64;

    float acc[2][2][4];
#pragma unroll
    for (int i = 0; i < 2; i++)
#pragma unroll
        for (int j = 0; j < 2; j++)
#pragma unroll
            for (int q = 0; q < 4; q++) acc[i][j][q] = 0.f;

    const __half* Ah0 = g_Anh + (size_t)b * 262144 + (size_t)m0 * 512;
    const __half* Bh0 = g_hrh[hin] + (size_t)b * 512 * 128 + n0;

    auto stg = [&](int cc) -> uint32_t { return sbase + (uint32_t)(cc % 3) * STG; };

    auto issueA = [&](int cc) {
        uint32_t buf = stg(cc);
        int kc = cc * 64;
#pragma unroll
        for (int i = 0; i < 2; i++) {
            int idx = tid + i * 256, r = idx >> 3, c = idx & 7;
            cpa16(buf + r * RS + c * 16, Ah0 + (size_t)r * 512 + kc + c * 8);
        }
    };
    auto issueB = [&](int cc) {
        uint32_t buf = stg(cc);
        int kc = cc * 64;
#pragma unroll
        for (int i = 0; i < 2; i++) {
            int idx = tid + i * 256, r = idx >> 3, c = idx & 7;
            cpa16(buf + GH_T + r * RS + c * 16, Bh0 + (size_t)(kc + r) * 128 + c * 8);
        }
    };
    auto issue = [&](int cc) { issueA(cc); issueB(cc); };

    issueA(0); CP_COMMIT();
    issueA(1); CP_COMMIT();
    gbar_wait(wait_gen);          // h(t-1) complete grid-wide
    issueB(0); CP_COMMIT();
    issueB(1); CP_COMMIT();

    uint32_t bOff = (uint32_t)((lane & 7) + ((lane >> 3) & 1) * 8) * RS
                  + (uint32_t)(wn * 16 + ((lane >> 4) & 1) * 8) * 2;

#pragma unroll 1
    for (int cc = 0; cc < 8; cc++) {
        CP_WAIT1();
        __syncthreads();

        uint32_t buf = stg(cc);
        uint32_t aH = buf + (uint32_t)(wm * 32 + (lane & 15)) * RS + ((lane >> 4) * 16);
        uint32_t bB = buf + GH_T + bOff;
#pragma unroll
        for (int ks = 0; ks < 4; ks++) {
            uint32_t ah[2][4], bh[4];
            ldsm4(ah[0], aH + ks * 32); ldsm4(ah[1], aH + 16 * RS + ks * 32);
            ldsm4t(bh, bB + ks * 16 * RS);
#pragma unroll
            for (int mf = 0; mf < 2; mf++) {
                mmaf(acc[mf][0], ah[mf], &bh[0]); mmaf(acc[mf][1], ah[mf], &bh[2]);
            }
        }
        __syncthreads();
        if (cc + 2 < 8) { issue(cc + 2); CP_COMMIT(); }
    }
    CP_WAIT0();

    int rbase = b * 512 + m0 + wm * 32 + (lane >> 2);
    int cbase = n0 + wn * 16 + (lane & 3) * 2;
#pragma unroll
    for (int mf = 0; mf < 2; mf++) {
#pragma unroll
        for (int nf = 0; nf < 2; nf++) {
            int col = cbase + nf * 8;
            float* d = acc[mf][nf];
            int r0 = rbase + mf * 16;
            *(__half2*)(g_Hh + (size_t)r0 * 128 + col) =
                __halves2half2(__float2half_rn(d[0]), __float2half_rn(d[1]));
            *(__half2*)(g_Hh + (size_t)(r0 + 8) * 128 + col) =
                __halves2half2(__float2half_rn(d[2]), __float2half_rn(d[3]));
        }
    }
}

// ---------------------------------------------------------------------------
// phase gG (barrier-overlapped, 3-stage): gates = Ges + [H | h] @ Wcomb.
// Weights pure fp16. Ges tile read from persistent smem. Epilogue in halves.
// ---------------------------------------------------------------------------
__device__ __forceinline__ void phase_gG(char* dsm, int hin, int hout, int cta, int tid,
                                         unsigned wait_gen) {
    uint32_t sbase = smem_u32(dsm);
    int wid = tid >> 5, lane = tid & 31;
    int wm = wid >> 2, wn = wid & 3;
    int m0 = (cta >> 2) * 128;
    int n0 = (cta & 3) * 128;

    float acc[4][4][4];
#pragma unroll
    for (int i = 0; i < 4; i++)
#pragma unroll
        for (int j = 0; j < 4; j++)
#pragma unroll
            for (int q = 0; q < 4; q++) acc[i][j][q] = 0.f;

    auto issue = [&](int cc, uint32_t buf) {
        int kc = cc * 64;
        const __half* Ahs = (kc < 128)
            ? g_Hh + (size_t)m0 * 128 + kc
            : g_hrh[hin] + (size_t)m0 * 128 + (kc - 128);
#pragma unroll
        for (int i = 0; i < 4; i++) {
            int idx = tid + i * 256, r = idx >> 3, c = idx & 7;
            cpa16(buf + r * RS + c * 16, Ahs + (size_t)r * 128 + c * 8);
        }
    };

    uint32_t wtH = sbase + SM_WT
                 + (uint32_t)(wn * 32 + (lane & 7) + ((lane >> 4) & 1) * 8) * WT_RSB
                 + (((lane >> 3) & 1) * 16);

    auto compute = [&](int cc, uint32_t buf) {
        uint32_t aH = buf + (uint32_t)(wm * 64 + (lane & 15)) * RS + ((lane >> 4) * 16);
        uint32_t kb = (uint32_t)cc * 128;
#pragma unroll
        for (int ks = 0; ks < 4; ks++) {
            uint32_t ah[4][4], bh0[4], bh1[4];
#pragma unroll
            for (int mf = 0; mf < 4; mf++)
                ldsm4(ah[mf], aH + mf * 16 * RS + ks * 32);
            ldsm4(bh0, wtH + kb + ks * 32);
            ldsm4(bh1, wtH + 16 * WT_RSB + kb + ks * 32);
#pragma unroll
            for (int mf = 0; mf < 4; mf++) {
                mmaf(acc[mf][0], ah[mf], &bh0[0]); mmaf(acc[mf][1], ah[mf], &bh0[2]);
                mmaf(acc[mf][2], ah[mf], &bh1[0]); mmaf(acc[mf][3], ah[mf], &bh1[2]);
            }
        }
    };

    uint32_t s0 = sbase, s1 = sbase + STG, s2 = sbase + 2 * STG;

    // part 1: h-part chunk 2 (chunk 3 loading)
    issue(2, s0); CP_COMMIT();
    issue(3, s1); CP_COMMIT();
    CP_WAIT1();
    __syncthreads();
    compute(2, s0);

    gbar_wait(wait_gen);          // H(t) complete grid-wide

    issue(0, s2); CP_COMMIT();
    issue(1, s0); CP_COMMIT();
    CP_WAIT2();
    __syncthreads();
    compute(3, s1);
    CP_WAIT1();
    __syncthreads();
    compute(0, s2);
    CP_WAIT0();
    __syncthreads();
    compute(1, s0);

    // epilogue: two 64-row halves; gate math with Ges from persistent smem
    float* cst = (float*)dsm;                 // [64][132] = 33792
    const char* gesb = dsm + SM_GES;          // [128][128] fp32, row stride 512B
    int q  = tid & 31;
    int rb = tid >> 5;
    int j  = (n0 >> 2) + q;
    __half* hrho = g_hrh[hout];
#pragma unroll
    for (int half = 0; half < 2; half++) {
        __syncthreads();
        if (wm == half) {
#pragma unroll
            for (int mf = 0; mf < 4; mf++) {
#pragma unroll
                for (int nf = 0; nf < 4; nf++) {
                    int row = mf * 16 + (lane >> 2);
                    int col = wn * 32 + nf * 8 + (lane & 3) * 2;
                    float* d = acc[mf][nf];
                    *(float2*)&cst[row * 132 + col]       = make_float2(d[0], d[1]);
                    *(float2*)&cst[(row + 8) * 132 + col] = make_float2(d[2], d[3]);
                }
            }
        }
        __syncthreads();
#pragma unroll
        for (int i = 0; i < 8; i++) {
            int rl = rb + i * 8;
            int r  = half * 64 + rl;
            int rr = m0 + r;
            float4 pv = *(float4*)&cst[rl * 132 + q * 4];
            float4 ge = *(const float4*)(gesb + (size_t)r * 512 + q * 16);
            float iv = sigm(pv.x + ge.x), fv = sigm(pv.y + ge.y);
            float gv = ftanh(pv.z + ge.z), ov = sigm(pv.w + ge.w);
            size_t cidx = (size_t)rr * 128 + j;
            float cc = fv * g_c[cidx] + iv * gv;
            g_c[cidx] = cc;
            float hv = ov * ftanh(cc);
            hrho[cidx] = __float2half_rn(hv);
        }
    }
    __syncthreads();
}

// ---------------------------------------------------------------------------
// phase out: Xi += h @ Wout + bout ; emit out[:, :, t, :]
// WoT hi/lo persistent in smem; only h (8.5 KB) loaded per call.
// ---------------------------------------------------------------------------
__device__ __forceinline__ void phase_out(char* dsm, int t, int hidx,
                                          const float* __restrict__ bout,
                                          float* __restrict__ out, int cta, int tid) {
    uint32_t sbase = smem_u32(dsm);
    int wid = tid >> 5, lane = tid & 31;
    int mw = wid & 1, nw = wid >> 1;
    int row0 = cta * 32;
    __syncthreads();

    {
        const __half* hh = g_hrh[hidx] + (size_t)row0 * 128;
#pragma unroll
        for (int i = 0; i < 2; i++) {
            int idx = tid + i * 256, r = idx >> 4, c = idx & 15;
            cpa16(sbase + r * OUT_RSB + c * 16, hh + (size_t)r * 128 + c * 8);
        }
        CP_COMMIT();
    }

    int rA = row0 + mw * 16 + (lane >> 2);
    int cA = nw * 16 + (lane & 3) * 2;
    float2 xi[2][2], bo[2];
#pragma unroll
    for (int nf = 0; nf < 2; nf++) {
        int col = cA + nf * 8;
        xi[nf][0] = *(const float2*)&g_Xi[rA * 64 + col];
        xi[nf][1] = *(const float2*)&g_Xi[(rA + 8) * 64 + col];
        bo[nf] = *(const float2*)&bout[col];
    }

    CP_WAIT0();
    __syncthreads();

    uint32_t aH = sbase + (uint32_t)(mw * 16 + (lane & 15)) * OUT_RSB + ((lane >> 4) * 16);
    uint32_t bH = sbase + SM_WOT
                + (uint32_t)(nw * 16 + (lane & 7) + ((lane >> 4) & 1) * 8) * OUT_RSB
                + (((lane >> 3) & 1) * 16);
    uint32_t bL = bH + WOT_SZ;

    float acc[2][4] = {};
    uint32_t hacc[2][2] = {};
#pragma unroll
    for (int ks = 0; ks < 8; ks++) {
        uint32_t ah[4], bh[4], bl[4];
        ldsm4(ah, aH + ks * 32);
        ldsm4(bh, bH + ks * 32);
        ldsm4(bl, bL + ks * 32);
        mmaf(acc[0], ah, &bh[0]); mmaf(acc[1], ah, &bh[2]);
        mmah(hacc[0], ah, &bl[0]); mmah(hacc[1], ah, &bl[2]);
    }

#pragma unroll
    for (int nf = 0; nf < 2; nf++) {
        hmerge(acc[nf], hacc[nf]);
        int col = cA + nf * 8;
        float2 v0 = make_float2(acc[nf][0] + xi[nf][0].x + bo[nf].x,
                                acc[nf][1] + xi[nf][0].y + bo[nf].y);
        float2 v1 = make_float2(acc[nf][2] + xi[nf][1].x + bo[nf].x,
                                acc[nf][3] + xi[nf][1].y + bo[nf].y);
        *(float2*)&g_Xi[rA * 64 + col] = v0;
        *(float2*)&g_Xi[(rA + 8) * 64 + col] = v1;
        *(float2*)&out[(size_t)rA * 4096 + t * 64 + col] = v0;
        *(float2*)&out[(size_t)(rA + 8) * 4096 + t * 64 + col] = v1;
    }
    __syncthreads();
}

// ---------------------------------------------------------------------------
// k_main: persistent kernel, 63 steps. bar2 arrive-only (wait folded into gH).
// Prologue persists WTh n-slice, WoT hi/lo, and this CTA's Ges tile in smem.
// ---------------------------------------------------------------------------
__global__ void __launch_bounds__(256) k_main(const float* __restrict__ bout,
                                              float* __restrict__ out) {
    extern __shared__ __align__(16) char dsm[];
    int cta = blockIdx.x, tid = threadIdx.x;

    {
        int n0 = (cta & 3) * 128;
        int m0 = (cta >> 2) * 128;
        uint32_t wt = smem_u32(dsm) + SM_WT;
#pragma unroll
        for (int i = 0; i < 16; i++) {
            int idx = tid + i * 256;
            int r = idx >> 5, c = idx & 31;
            cpa16(wt + r * WT_RSB + c * 16, g_WTh + (size_t)(n0 + r) * 256 + c * 8);
        }
        uint32_t wo = smem_u32(dsm) + SM_WOT;
#pragma unroll
        for (int i = 0; i < 4; i++) {
            int idx = tid + i * 256;
            int r = idx >> 4, c = idx & 15;
            cpa16(wo + r * OUT_RSB + c * 16,          g_WoTh + (size_t)r * 128 + c * 8);
            cpa16(wo + WOT_SZ + r * OUT_RSB + c * 16, g_WoTl + (size_t)r * 128 + c * 8);
        }
        uint32_t gs = smem_u32(dsm) + SM_GES;
#pragma unroll
        for (int i = 0; i < 16; i++) {
            int idx = tid + i * 256;
            int r = idx >> 5, c = idx & 31;
            cpa16(gs + r * 512 + c * 16, g_Ges + (size_t)(m0 + r) * 512 + n0 + c * 4);
        }
        CP_COMMIT();
        CP_WAIT0();
    }
    __syncthreads();

    unsigned gen = 0;
#pragma unroll 1
    for (int t = 1; t < Tc; t++) {
        int hin = (t - 1) & 1, hout = t & 1;
        phase_gH(dsm, hin, cta, tid, gen);           // waits bar2(t-1) after An prefetch
        ++gen;
        gbar_arrive(gen);                            // bar1: this CTA's H done
        if (t >= 2) phase_out(dsm, t - 1, hin, bout, out, cta, tid);
        phase_gG(dsm, hin, hout, cta, tid, gen);     // h-part + out overlap bar1 wait
        ++gen;
        gbar_arrive(gen);                            // bar2: arrive only
    }
    gbar_wait(gen);
    phase_out(dsm, Tc - 1, (Tc - 1) & 1, bout, out, cta, tid);
}

// ---------------------------------------------------------------------------
extern "C" void kernel_launch(void* const* d_in, const int* in_sizes, int n_in,
                              void* d_out, int out_size) {
    const float* X    = (const float*)d_in[0];
    const float* A    = (const float*)d_in[1];
    const float* Wse  = (const float*)d_in[2];
    const float* bse  = (const float*)d_in[3];
    const float* Wpe  = (const float*)d_in[4];
    const float* bpe  = (const float*)d_in[5];
    const float* Wii  = (const float*)d_in[6];
    const float* bii  = (const float*)d_in[7];
    const float* Whi  = (const float*)d_in[8];
    const float* bhi  = (const float*)d_in[9];
    const float* Wif  = (const float*)d_in[10];
    const float* bif_ = (const float*)d_in[11];
    const float* Whf  = (const float*)d_in[12];
    const float* bhf  = (const float*)d_in[13];
    const float* Wig  = (const float*)d_in[14];
    const float* big_ = (const float*)d_in[15];
    const float* Whg  = (const float*)d_in[16];
    const float* bhg  = (const float*)d_in[17];
    const float* Wio  = (const float*)d_in[18];
    const float* bio  = (const float*)d_in[19];
    const float* Who  = (const float*)d_in[20];
    const float* bho  = (const float*)d_in[21];
    const float* Wout = (const float*)d_in[22];
    const float* bout = (const float*)d_in[23];
    float* out = (float*)d_out;

    cudaFuncSetAttribute(k_main, cudaFuncAttributeMaxDynamicSharedMemorySize, SM_TOTAL);

    k_dinv<<<Rc, 128>>>(A);
    k_an<<<2048, 256>>>(A);
    k_prep<<<512, 128>>>(Wii, bii, Whi, bhi, Wif, bif_, Whf, bhf,
                         Wig, big_, Whg, bhg, Wio, bio, Who, bho, Wpe, bpe);
    k_init<<<Rc, 128>>>(X, Wse, bse, Wout, out);
    k_ges<<<256, 256>>>();
    k_main<<<NCTA, 256, SM_TOTAL>>>(bout, out);
}

// round 17
// speedup vs baseline: 1.8026x; 1.0439x over previous
#include <cuda_runtime.h>
#include <cuda_fp16.h>
#include <math.h>
#include <stdint.h>

// Problem constants
#define Bc   8
#define Nc   512
#define Tc   64
#define NINc 64
#define NHc  128
#define Rc   (Bc * Nc)   // 4096 rows
#define NCTA 128

// ---------------- scratch (device globals) ----------------------------------
__device__ float g_dinv[Rc];
__device__ __half g_Anh[Bc * Nc * Nc];          // An fp16 (4 MB)
__device__ float g_es[Rc * NHc];                // static embedding fp32
__device__ float g_Wes[128 * 512];              // Wi[0:128] interleaved fp32
__device__ float g_bbig[512];
__device__ float g_Ges[Rc * 512];               // es @ Wes + bbig (fp32, interleaved)
__device__ __half g_WTh[512 * 256];             // Wcomb^T fp16: [n][k]
__device__ __half g_WoTh[64 * 128];             // Wout^T hi: [n][k]
__device__ __half g_WoTl[64 * 128];             // Wout^T lo (kept: output path)
__device__ __half g_Hh[Rc * NHc];               // H = An@h, fp16, row-major
__device__ __half g_hrh[2][Rc * NHc];           // h row-major fp16 (double buffered)
__device__ float g_c[Rc * NHc];                 // cell state
__device__ float g_Xi[Rc * NINc];               // running output accumulator
__device__ unsigned g_count;                    // grid barrier arrive counter
__device__ unsigned g_sense;                    // grid barrier generation

// ---------------- helpers ----------------------------------------------------
__device__ __forceinline__ uint32_t smem_u32(const void* p) {
    uint32_t a;
    asm("{ .reg .u64 t; cvta.to.shared.u64 t, %1; cvt.u32.u64 %0, t; }" : "=r"(a) : "l"(p));
    return a;
}
__device__ __forceinline__ float sigm(float x) {
    return __fdividef(1.f, 1.f + __expf(-x));
}
__device__ __forceinline__ float ftanh(float x) {
    float e = __expf(2.f * x);
    return 1.f - __fdividef(2.f, e + 1.f);
}
__device__ __forceinline__ void hsplit(float v, __half& hi, __half& lo) {
    hi = __float2half_rn(v);
    lo = __float2half_rn(v - __half2float(hi));
}
__device__ __forceinline__ void cpa16(uint32_t dst, const void* src) {
    asm volatile("cp.async.cg.shared.global [%0], [%1], 16;" :: "r"(dst), "l"(src) : "memory");
}
#define CP_COMMIT() asm volatile("cp.async.commit_group;" ::: "memory")
#define CP_WAIT2()  asm volatile("cp.async.wait_group 2;" ::: "memory")
#define CP_WAIT1()  asm volatile("cp.async.wait_group 1;" ::: "memory")
#define CP_WAIT0()  asm volatile("cp.async.wait_group 0;" ::: "memory")

__device__ __forceinline__ void ldsm4(uint32_t* r, uint32_t a) {
    asm volatile("ldmatrix.sync.aligned.m8n8.x4.shared.b16 {%0,%1,%2,%3}, [%4];"
        : "=r"(r[0]), "=r"(r[1]), "=r"(r[2]), "=r"(r[3]) : "r"(a));
}
__device__ __forceinline__ void ldsm4t(uint32_t* r, uint32_t a) {
    asm volatile("ldmatrix.sync.aligned.m8n8.x4.trans.shared.b16 {%0,%1,%2,%3}, [%4];"
        : "=r"(r[0]), "=r"(r[1]), "=r"(r[2]), "=r"(r[3]) : "r"(a));
}
__device__ __forceinline__ void mmaf(float* d, const uint32_t* a, const uint32_t* b) {
    asm volatile("mma.sync.aligned.m16n8k16.row.col.f32.f16.f16.f32 "
        "{%0,%1,%2,%3}, {%4,%5,%6,%7}, {%8,%9}, {%0,%1,%2,%3};"
        : "+f"(d[0]), "+f"(d[1]), "+f"(d[2]), "+f"(d[3])
        : "r"(a[0]), "r"(a[1]), "r"(a[2]), "r"(a[3]), "r"(b[0]), "r"(b[1]));
}
__device__ __forceinline__ void mmah(uint32_t* d, const uint32_t* a, const uint32_t* b) {
    asm volatile("mma.sync.aligned.m16n8k16.row.col.f16.f16.f16.f16 "
        "{%0,%1}, {%2,%3,%4,%5}, {%6,%7}, {%0,%1};"
        : "+r"(d[0]), "+r"(d[1])
        : "r"(a[0]), "r"(a[1]), "r"(a[2]), "r"(a[3]), "r"(b[0]), "r"(b[1]));
}
__device__ __forceinline__ void hmerge(float* d, const uint32_t* h) {
    __half2 q0 = *(const __half2*)&h[0];
    __half2 q1 = *(const __half2*)&h[1];
    d[0] += __half2float(q0.x); d[1] += __half2float(q0.y);
    d[2] += __half2float(q1.x); d[3] += __half2float(q1.y);
}

// grid-wide sense barrier, split into arrive / wait halves
__device__ __forceinline__ void gbar_arrive(unsigned gen) {
    __syncthreads();
    if (threadIdx.x == 0) {
        unsigned prev;
        asm volatile("atom.release.gpu.add.u32 %0, [%1], %2;"
                     : "=r"(prev) : "l"(&g_count), "r"(1u) : "memory");
        if (prev == NCTA - 1) {
            g_count = 0u;
            asm volatile("st.release.gpu.u32 [%0], %1;" :: "l"(&g_sense), "r"(gen) : "memory");
        }
    }
}
__device__ __forceinline__ void gbar_wait(unsigned gen) {
    if (threadIdx.x == 0) {
        unsigned s;
        do {
            asm volatile("ld.acquire.gpu.u32 %0, [%1];" : "=r"(s) : "l"(&g_sense) : "memory");
        } while (s < gen);
    }
    __syncthreads();
}

#define RS 144          // stage tile row stride (72 halves)
#define GH_T   9216     // gH tile: 64 rows x RS
#define STG    18432    // unified stage size
#define SM_WT    55296  // after 3 stages
#define WT_RSB   528
#define WT_SZ    67584
#define SM_WOT   122880 // SM_WT + WT_SZ
#define WOT_SZ   17408
#define OUT_RSB  272
#define SM_GES   157696 // SM_WOT + 2*WOT_SZ ; Ges tile 128x128 fp32
#define SM_TOTAL 223232 // SM_GES + 65536

// ---------------------------------------------------------------------------
__global__ void k_dinv(const float* __restrict__ A) {
    int row = blockIdx.x;
    const float* arow = A + (size_t)row * Nc;
    float s = 0.f;
    for (int j = threadIdx.x; j < Nc; j += blockDim.x) s += arow[j];
    __shared__ float sh[128];
    sh[threadIdx.x] = s;
    __syncthreads();
    for (int off = 64; off > 0; off >>= 1) {
        if (threadIdx.x < off) sh[threadIdx.x] += sh[threadIdx.x + off];
        __syncthreads();
    }
    if (threadIdx.x == 0) {
        float d = sh[0];
        g_dinv[row] = (d > 0.f) ? rsqrtf(d) : 0.f;
    }
}

__global__ void k_an(const float* __restrict__ A) {
    int idx = blockIdx.x * blockDim.x + threadIdx.x;
    int e = idx * 4;
    int b   = e >> 18;
    int rem = e & 262143;
    int i   = rem >> 9;
    int j   = rem & 511;
    float4 a = *(const float4*)(A + (size_t)e);
    float di = g_dinv[b * 512 + i];
    const float* dj = g_dinv + b * 512 + j;
    __half2* ph = (__half2*)(g_Anh + (size_t)e);
    ph[0] = __halves2half2(__float2half_rn(a.x * di * dj[0]),
                           __float2half_rn(a.y * di * dj[1]));
    ph[1] = __halves2half2(__float2half_rn(a.z * di * dj[2]),
                           __float2half_rn(a.w * di * dj[3]));
}

// ---------------------------------------------------------------------------
__global__ void k_prep(const float* __restrict__ Wii, const float* __restrict__ bii,
                       const float* __restrict__ Whi, const float* __restrict__ bhi,
                       const float* __restrict__ Wif, const float* __restrict__ bif_,
                       const float* __restrict__ Whf, const float* __restrict__ bhf,
                       const float* __restrict__ Wig, const float* __restrict__ big_,
                       const float* __restrict__ Whg, const float* __restrict__ bhg,
                       const float* __restrict__ Wio, const float* __restrict__ bio,
                       const float* __restrict__ Who, const float* __restrict__ bho,
                       const float* __restrict__ Wpe, const float* __restrict__ bpe) {
    int n = blockIdx.x;
    int g = n & 3;
    int j = n >> 2;
    int t = threadIdx.x;
    const float* Wi = (g == 0) ? Wii : (g == 1) ? Wif : (g == 2) ? Wig : Wio;
    const float* Wh = (g == 0) ? Whi : (g == 1) ? Whf : (g == 2) ? Whg : Who;
    const float* bi = (g == 0) ? bii : (g == 1) ? bif_ : (g == 2) ? big_ : bio;
    const float* bh = (g == 0) ? bhi : (g == 1) ? bhf : (g == 2) ? bhg : bho;

    __shared__ float wcol[128];
    wcol[t] = Wi[(128 + t) * 128 + j];
    __syncthreads();

    g_Wes[t * 512 + n] = Wi[t * 128 + j];

    float acc = 0.f;
    const float* wpet = Wpe + t * 128;
#pragma unroll 8
    for (int m = 0; m < 128; m++) acc += wpet[m] * wcol[m];

    g_WTh[n * 256 + t]       = __float2half_rn(acc);
    g_WTh[n * 256 + 128 + t] = __float2half_rn(Wh[t * 128 + j]);

    if (t == 0) {
        float ba = bi[j] + bh[j];
        for (int m = 0; m < 128; m++) ba += bpe[m] * wcol[m];
        g_bbig[n] = ba;
    }
}

// ---------------------------------------------------------------------------
__global__ void k_init(const float* __restrict__ X, const float* __restrict__ Wse,
                       const float* __restrict__ bse, const float* __restrict__ Wout,
                       float* __restrict__ out) {
    int row = blockIdx.x;
    int t = threadIdx.x;
    if (row == 0 && t == 0) { g_count = 0u; g_sense = 0u; }
    if (row < 64) {
        __half hh, ll;
        hsplit(Wout[t * 64 + row], hh, ll);
        g_WoTh[row * 128 + t] = hh;
        g_WoTl[row * 128 + t] = ll;
    }
    __shared__ float x0[64];
    if (t < 64) {
        float v = X[(size_t)row * 4096 + t];
        x0[t] = v;
        g_Xi[row * 64 + t] = v;
        out[(size_t)row * 4096 + t] = v;
    }
    __syncthreads();
    float acc = bse[t];
#pragma unroll 8
    for (int k = 0; k < 64; k++) acc += x0[k] * Wse[k * 128 + t];
    g_es[row * 128 + t] = acc;

    g_hrh[0][(size_t)row * 128 + t] = __float2half(0.f);
    g_c[row * 128 + t] = 0.f;
}

// ---------------------------------------------------------------------------
// k_ges: Ges = es @ Wes + bbig (4096 x 512, K=128) fp32, runs once
// ---------------------------------------------------------------------------
__global__ void __launch_bounds__(256) k_ges() {
    int m0 = (blockIdx.x >> 2) * 64;
    int n0 = (blockIdx.x & 3) * 128;

    __shared__ __align__(16) float As[16][68];
    __shared__ __align__(16) float Bs[16][132];

    int tid = threadIdx.x;
    int ty = tid >> 4, tx = tid & 15;
    int ar = tid >> 2, ac = (tid & 3) * 4;
    int br = tid >> 5, bc = (tid & 31) * 4;

    float acc[4][8] = {};

    for (int k0 = 0; k0 < 128; k0 += 16) {
        float4 av = *(const float4*)&g_es[(size_t)(m0 + ar) * 128 + k0 + ac];
        float4 bv0 = *(const float4*)&g_Wes[(size_t)(k0 + br) * 512 + n0 + bc];
        float4 bv1 = *(const float4*)&g_Wes[(size_t)(k0 + br + 8) * 512 + n0 + bc];
        As[ac + 0][ar] = av.x; As[ac + 1][ar] = av.y;
        As[ac + 2][ar] = av.z; As[ac + 3][ar] = av.w;
        *(float4*)&Bs[br][bc] = bv0;
        *(float4*)&Bs[br + 8][bc] = bv1;
        __syncthreads();
#pragma unroll
        for (int kk = 0; kk < 16; kk++) {
            float4 a4 = *(const float4*)&As[kk][ty * 4];
            float4 b0 = *(const float4*)&Bs[kk][tx * 8];
            float4 b1 = *(const float4*)&Bs[kk][tx * 8 + 4];
            float av4[4] = { a4.x, a4.y, a4.z, a4.w };
            float bv8[8] = { b0.x, b0.y, b0.z, b0.w, b1.x, b1.y, b1.z, b1.w };
#pragma unroll
            for (int i = 0; i < 4; i++)
#pragma unroll
                for (int jq = 0; jq < 8; jq++) acc[i][jq] += av4[i] * bv8[jq];
        }
        __syncthreads();
    }

    float bb[8];
#pragma unroll
    for (int q = 0; q < 8; q++) bb[q] = g_bbig[n0 + tx * 8 + q];
#pragma unroll
    for (int r = 0; r < 4; r++) {
        int rr = m0 + ty * 4 + r;
        float* dst = &g_Ges[(size_t)rr * 512 + n0 + tx * 8];
#pragma unroll
        for (int q = 0; q < 8; q++) dst[q] = acc[r][q] + bb[q];
    }
}

// ---------------------------------------------------------------------------
// phase gH: H = An @ h, CTA tile 64x64. Early-issue, single sync per chunk.
// ---------------------------------------------------------------------------
__device__ __forceinline__ void phase_gH(char* dsm, int hin, int cta, int tid,
                                         unsigned wait_gen) {
    uint32_t sbase = smem_u32(dsm);
    int wid = tid >> 5, lane = tid & 31;
    int wm = wid >> 2, wn = wid & 3;
    int b  = cta >> 4;
    int m0 = ((cta >> 1) & 7) * 64;
    int n0 = (cta & 1) * 64;

    float acc[2][2][4];
#pragma unroll
    for (int i = 0; i < 2; i++)
#pragma unroll
        for (int j = 0; j < 2; j++)
#pragma unroll
            for (int q = 0; q < 4; q++) acc[i][j][q] = 0.f;

    const __half* Ah0 = g_Anh + (size_t)b * 262144 + (size_t)m0 * 512;
    const __half* Bh0 = g_hrh[hin] + (size_t)b * 512 * 128 + n0;

    auto stg = [&](int cc) -> uint32_t { return sbase + (uint32_t)(cc % 3) * STG; };

    auto issueA = [&](int cc) {
        uint32_t buf = stg(cc);
        int kc = cc * 64;
#pragma unroll
        for (int i = 0; i < 2; i++) {
            int idx = tid + i * 256, r = idx >> 3, c = idx & 7;
            cpa16(buf + r * RS + c * 16, Ah0 + (size_t)r * 512 + kc + c * 8);
        }
    };
    auto issueB = [&](int cc) {
        uint32_t buf = stg(cc);
        int kc = cc * 64;
#pragma unroll
        for (int i = 0; i < 2; i++) {
            int idx = tid + i * 256, r = idx >> 3, c = idx & 7;
            cpa16(buf + GH_T + r * RS + c * 16, Bh0 + (size_t)(kc + r) * 128 + c * 8);
        }
    };
    auto issue = [&](int cc) { issueA(cc); issueB(cc); };

    issueA(0); CP_COMMIT();
    issueA(1); CP_COMMIT();
    gbar_wait(wait_gen);          // h(t-1) complete grid-wide
    issueB(0); CP_COMMIT();
    issueB(1); CP_COMMIT();

    uint32_t bOff = (uint32_t)((lane & 7) + ((lane >> 3) & 1) * 8) * RS
                  + (uint32_t)(wn * 16 + ((lane >> 4) & 1) * 8) * 2;

#pragma unroll 1
    for (int cc = 0; cc < 8; cc++) {
        CP_WAIT1();
        __syncthreads();
        // early issue: stage (cc+2)%3's last readers finished before this sync
        if (cc + 2 < 8) { issue(cc + 2); CP_COMMIT(); }

        uint32_t buf = stg(cc);
        uint32_t aH = buf + (uint32_t)(wm * 32 + (lane & 15)) * RS + ((lane >> 4) * 16);
        uint32_t bB = buf + GH_T + bOff;
#pragma unroll
        for (int ks = 0; ks < 4; ks++) {
            uint32_t ah[2][4], bh[4];
            ldsm4(ah[0], aH + ks * 32); ldsm4(ah[1], aH + 16 * RS + ks * 32);
            ldsm4t(bh, bB + ks * 16 * RS);
#pragma unroll
            for (int mf = 0; mf < 2; mf++) {
                mmaf(acc[mf][0], ah[mf], &bh[0]); mmaf(acc[mf][1], ah[mf], &bh[2]);
            }
        }
    }
    CP_WAIT0();

    int rbase = b * 512 + m0 + wm * 32 + (lane >> 2);
    int cbase = n0 + wn * 16 + (lane & 3) * 2;
#pragma unroll
    for (int mf = 0; mf < 2; mf++) {
#pragma unroll
        for (int nf = 0; nf < 2; nf++) {
            int col = cbase + nf * 8;
            float* d = acc[mf][nf];
            int r0 = rbase + mf * 16;
            *(__half2*)(g_Hh + (size_t)r0 * 128 + col) =
                __halves2half2(__float2half_rn(d[0]), __float2half_rn(d[1]));
            *(__half2*)(g_Hh + (size_t)(r0 + 8) * 128 + col) =
                __halves2half2(__float2half_rn(d[2]), __float2half_rn(d[3]));
        }
    }
}

// ---------------------------------------------------------------------------
// phase gG with integrated out(t-1): the out h-tile load and compute are
// folded into gG part 1 so out's load latency hides under c2's flight and
// out's compute fills c2's remaining latency.
// ---------------------------------------------------------------------------
__device__ __forceinline__ void phase_gGout(char* dsm, int hin, int hout, int cta, int tid,
                                            unsigned wait_gen, bool do_out, int t_out,
                                            const float* __restrict__ bout,
                                            float* __restrict__ outp) {
    uint32_t sbase = smem_u32(dsm);
    int wid = tid >> 5, lane = tid & 31;
    int wm = wid >> 2, wn = wid & 3;
    int m0 = (cta >> 2) * 128;
    int n0 = (cta & 3) * 128;

    uint32_t s0 = sbase, s1 = sbase + STG, s2 = sbase + 2 * STG;

    auto issue = [&](int cc, uint32_t buf) {
        int kc = cc * 64;
        const __half* Ahs = (kc < 128)
            ? g_Hh + (size_t)m0 * 128 + kc
            : g_hrh[hin] + (size_t)m0 * 128 + (kc - 128);
#pragma unroll
        for (int i = 0; i < 4; i++) {
            int idx = tid + i * 256, r = idx >> 3, c = idx & 7;
            cpa16(buf + r * RS + c * 16, Ahs + (size_t)r * 128 + c * 8);
        }
    };

    // ---- part 0: issue out-h (into s2) + gG c2, c3
    if (do_out) {
        const __half* hh = g_hrh[hin] + (size_t)(cta * 32) * 128;
#pragma unroll
        for (int i = 0; i < 2; i++) {
            int idx = tid + i * 256, r = idx >> 4, c = idx & 15;
            cpa16(s2 + r * OUT_RSB + c * 16, hh + (size_t)r * 128 + c * 8);
        }
        CP_COMMIT();
    }
    issue(2, s0); CP_COMMIT();
    issue(3, s1); CP_COMMIT();

    // ---- out compute (overlaps c2/c3 flight); gG acc zeroed after
    if (do_out) {
        int mw = wid & 1, nw = wid >> 1;
        int row0 = cta * 32;
        int rA = row0 + mw * 16 + (lane >> 2);
        int cA = nw * 16 + (lane & 3) * 2;
        float2 xi[2][2], bo[2];
#pragma unroll
        for (int nf = 0; nf < 2; nf++) {
            int col = cA + nf * 8;
            xi[nf][0] = *(const float2*)&g_Xi[rA * 64 + col];
            xi[nf][1] = *(const float2*)&g_Xi[(rA + 8) * 64 + col];
            bo[nf] = *(const float2*)&bout[col];
        }
        CP_WAIT2();          // out-h done; c2,c3 still flying
        __syncthreads();

        uint32_t aH = s2 + (uint32_t)(mw * 16 + (lane & 15)) * OUT_RSB + ((lane >> 4) * 16);
        uint32_t bH = sbase + SM_WOT
                    + (uint32_t)(nw * 16 + (lane & 7) + ((lane >> 4) & 1) * 8) * OUT_RSB
                    + (((lane >> 3) & 1) * 16);
        uint32_t bL = bH + WOT_SZ;

        float oacc[2][4] = {};
        uint32_t ohacc[2][2] = {};
#pragma unroll
        for (int ks = 0; ks < 8; ks++) {
            uint32_t ah[4], bh[4], bl[4];
            ldsm4(ah, aH + ks * 32);
            ldsm4(bh, bH + ks * 32);
            ldsm4(bl, bL + ks * 32);
            mmaf(oacc[0], ah, &bh[0]); mmaf(oacc[1], ah, &bh[2]);
            mmah(ohacc[0], ah, &bl[0]); mmah(ohacc[1], ah, &bl[2]);
        }
#pragma unroll
        for (int nf = 0; nf < 2; nf++) {
            hmerge(oacc[nf], ohacc[nf]);
            int col = cA + nf * 8;
            float2 v0 = make_float2(oacc[nf][0] + xi[nf][0].x + bo[nf].x,
                                    oacc[nf][1] + xi[nf][0].y + bo[nf].y);
            float2 v1 = make_float2(oacc[nf][2] + xi[nf][1].x + bo[nf].x,
                                    oacc[nf][3] + xi[nf][1].y + bo[nf].y);
            *(float2*)&g_Xi[rA * 64 + col] = v0;
            *(float2*)&g_Xi[(rA + 8) * 64 + col] = v1;
            *(float2*)&outp[(size_t)rA * 4096 + t_out * 64 + col] = v0;
            *(float2*)&outp[(size_t)(rA + 8) * 4096 + t_out * 64 + col] = v1;
        }
    }

    float acc[4][4][4];
#pragma unroll
    for (int i = 0; i < 4; i++)
#pragma unroll
        for (int j = 0; j < 4; j++)
#pragma unroll
            for (int q = 0; q < 4; q++) acc[i][j][q] = 0.f;

    uint32_t wtH = sbase + SM_WT
                 + (uint32_t)(wn * 32 + (lane & 7) + ((lane >> 4) & 1) * 8) * WT_RSB
                 + (((lane >> 3) & 1) * 16);

    auto compute = [&](int cc, uint32_t buf) {
        uint32_t aH = buf + (uint32_t)(wm * 64 + (lane & 15)) * RS + ((lane >> 4) * 16);
        uint32_t kb = (uint32_t)cc * 128;
#pragma unroll
        for (int ks = 0; ks < 4; ks++) {
            uint32_t ah[4][4], bh0[4], bh1[4];
#pragma unroll
            for (int mf = 0; mf < 4; mf++)
                ldsm4(ah[mf], aH + mf * 16 * RS + ks * 32);
            ldsm4(bh0, wtH + kb + ks * 32);
            ldsm4(bh1, wtH + 16 * WT_RSB + kb + ks * 32);
#pragma unroll
            for (int mf = 0; mf < 4; mf++) {
                mmaf(acc[mf][0], ah[mf], &bh0[0]); mmaf(acc[mf][1], ah[mf], &bh0[2]);
                mmaf(acc[mf][2], ah[mf], &bh1[0]); mmaf(acc[mf][3], ah[mf], &bh1[2]);
            }
        }
    };

    // part 1: h-part chunk 2 (chunk 3 loading)
    CP_WAIT1();
    __syncthreads();
    compute(2, s0);

    gbar_wait(wait_gen);          // H(t) complete grid-wide; also fences s2/s0

    issue(0, s2); CP_COMMIT();
    issue(1, s0); CP_COMMIT();
    CP_WAIT2();
    __syncthreads();
    compute(3, s1);
    CP_WAIT1();
    __syncthreads();
    compute(0, s2);
    CP_WAIT0();
    __syncthreads();
    compute(1, s0);

    // epilogue: two 64-row halves; gate math with Ges from persistent smem
    float* cst = (float*)dsm;                 // [64][132] = 33792
    const char* gesb = dsm + SM_GES;          // [128][128] fp32, row stride 512B
    int q  = tid & 31;
    int rb = tid >> 5;
    int j  = (n0 >> 2) + q;
    __half* hrho = g_hrh[hout];
#pragma unroll
    for (int half = 0; half < 2; half++) {
        __syncthreads();
        if (wm == half) {
#pragma unroll
            for (int mf = 0; mf < 4; mf++) {
#pragma unroll
                for (int nf = 0; nf < 4; nf++) {
                    int row = mf * 16 + (lane >> 2);
                    int col = wn * 32 + nf * 8 + (lane & 3) * 2;
                    float* d = acc[half * 4 + mf - half * 4][nf]; // == acc[mf][nf]
                    d = acc[mf][nf];
                    *(float2*)&cst[row * 132 + col]       = make_float2(d[0], d[1]);
                    *(float2*)&cst[(row + 8) * 132 + col] = make_float2(d[2], d[3]);
                }
            }
        }
        __syncthreads();
#pragma unroll
        for (int i = 0; i < 8; i++) {
            int rl = rb + i * 8;
            int r  = half * 64 + rl;
            int rr = m0 + r;
            float4 pv = *(float4*)&cst[rl * 132 + q * 4];
            float4 ge = *(const float4*)(gesb + (size_t)r * 512 + q * 16);
            float iv = sigm(pv.x + ge.x), fv = sigm(pv.y + ge.y);
            float gv = ftanh(pv.z + ge.z), ov = sigm(pv.w + ge.w);
            size_t cidx = (size_t)rr * 128 + j;
            float cc = fv * g_c[cidx] + iv * gv;
            g_c[cidx] = cc;
            float hv = ov * ftanh(cc);
            hrho[cidx] = __float2half_rn(hv);
        }
    }
    __syncthreads();
}

// ---------------------------------------------------------------------------
// phase out (standalone, final step): Xi += h @ Wout + bout ; emit out slice
// ---------------------------------------------------------------------------
__device__ __forceinline__ void phase_out(char* dsm, int t, int hidx,
                                          const float* __restrict__ bout,
                                          float* __restrict__ out, int cta, int tid) {
    uint32_t sbase = smem_u32(dsm);
    int wid = tid >> 5, lane = tid & 31;
    int mw = wid & 1, nw = wid >> 1;
    int row0 = cta * 32;
    __syncthreads();

    {
        const __half* hh = g_hrh[hidx] + (size_t)row0 * 128;
#pragma unroll
        for (int i = 0; i < 2; i++) {
            int idx = tid + i * 256, r = idx >> 4, c = idx & 15;
            cpa16(sbase + r * OUT_RSB + c * 16, hh + (size_t)r * 128 + c * 8);
        }
        CP_COMMIT();
    }

    int rA = row0 + mw * 16 + (lane >> 2);
    int cA = nw * 16 + (lane & 3) * 2;
    float2 xi[2][2], bo[2];
#pragma unroll
    for (int nf = 0; nf < 2; nf++) {
        int col = cA + nf * 8;
        xi[nf][0] = *(const float2*)&g_Xi[rA * 64 + col];
        xi[nf][1] = *(const float2*)&g_Xi[(rA + 8) * 64 + col];
        bo[nf] = *(const float2*)&bout[col];
    }

    CP_WAIT0();
    __syncthreads();

    uint32_t aH = sbase + (uint32_t)(mw * 16 + (lane & 15)) * OUT_RSB + ((lane >> 4) * 16);
    uint32_t bH = sbase + SM_WOT
                + (uint32_t)(nw * 16 + (lane & 7) + ((lane >> 4) & 1) * 8) * OUT_RSB
                + (((lane >> 3) & 1) * 16);
    uint32_t bL = bH + WOT_SZ;

    float acc[2][4] = {};
    uint32_t hacc[2][2] = {};
#pragma unroll
    for (int ks = 0; ks < 8; ks++) {
        uint32_t ah[4], bh[4], bl[4];
        ldsm4(ah, aH + ks * 32);
        ldsm4(bh, bH + ks * 32);
        ldsm4(bl, bL + ks * 32);
        mmaf(acc[0], ah, &bh[0]); mmaf(acc[1], ah, &bh[2]);
        mmah(hacc[0], ah, &bl[0]); mmah(hacc[1], ah, &bl[2]);
    }

#pragma unroll
    for (int nf = 0; nf < 2; nf++) {
        hmerge(acc[nf], hacc[nf]);
        int col = cA + nf * 8;
        float2 v0 = make_float2(acc[nf][0] + xi[nf][0].x + bo[nf].x,
                                acc[nf][1] + xi[nf][0].y + bo[nf].y);
        float2 v1 = make_float2(acc[nf][2] + xi[nf][1].x + bo[nf].x,
                                acc[nf][3] + xi[nf][1].y + bo[nf].y);
        *(float2*)&g_Xi[rA * 64 + col] = v0;
        *(float2*)&g_Xi[(rA + 8) * 64 + col] = v1;
        *(float2*)&out[(size_t)rA * 4096 + t * 64 + col] = v0;
        *(float2*)&out[(size_t)(rA + 8) * 4096 + t * 64 + col] = v1;
    }
    __syncthreads();
}

// ---------------------------------------------------------------------------
// k_main: persistent kernel, 63 steps. bar2 arrive-only (wait folded into gH).
// out(t-1) folded into gG part 1.
// ---------------------------------------------------------------------------
__global__ void __launch_bounds__(256) k_main(const float* __restrict__ bout,
                                              float* __restrict__ out) {
    extern __shared__ __align__(16) char dsm[];
    int cta = blockIdx.x, tid = threadIdx.x;

    {
        int n0 = (cta & 3) * 128;
        int m0 = (cta >> 2) * 128;
        uint32_t wt = smem_u32(dsm) + SM_WT;
#pragma unroll
        for (int i = 0; i < 16; i++) {
            int idx = tid + i * 256;
            int r = idx >> 5, c = idx & 31;
            cpa16(wt + r * WT_RSB + c * 16, g_WTh + (size_t)(n0 + r) * 256 + c * 8);
        }
        uint32_t wo = smem_u32(dsm) + SM_WOT;
#pragma unroll
        for (int i = 0; i < 4; i++) {
            int idx = tid + i * 256;
            int r = idx >> 4, c = idx & 15;
            cpa16(wo + r * OUT_RSB + c * 16,          g_WoTh + (size_t)r * 128 + c * 8);
            cpa16(wo + WOT_SZ + r * OUT_RSB + c * 16, g_WoTl + (size_t)r * 128 + c * 8);
        }
        uint32_t gs = smem_u32(dsm) + SM_GES;
#pragma unroll
        for (int i = 0; i < 16; i++) {
            int idx = tid + i * 256;
            int r = idx >> 5, c = idx & 31;
            cpa16(gs + r * 512 + c * 16, g_Ges + (size_t)(m0 + r) * 512 + n0 + c * 4);
        }
        CP_COMMIT();
        CP_WAIT0();
    }
    __syncthreads();

    unsigned gen = 0;
#pragma unroll 1
    for (int t = 1; t < Tc; t++) {
        int hin = (t - 1) & 1, hout = t & 1;
        phase_gH(dsm, hin, cta, tid, gen);           // waits bar2(t-1) after An prefetch
        ++gen;
        gbar_arrive(gen);                            // bar1: this CTA's H done
        phase_gGout(dsm, hin, hout, cta, tid, gen,
                    t >= 2, t - 1, bout, out);       // out + h-part overlap bar1 wait
        ++gen;
        gbar_arrive(gen);                            // bar2: arrive only
    }
    gbar_wait(gen);
    phase_out(dsm, Tc - 1, (Tc - 1) & 1, bout, out, cta, tid);
}

// ---------------------------------------------------------------------------
extern "C" void kernel_launch(void* const* d_in, const int* in_sizes, int n_in,
                              void* d_out, int out_size) {
    const float* X    = (const float*)d_in[0];
    const float* A    = (const float*)d_in[1];
    const float* Wse  = (const float*)d_in[2];
    const float* bse  = (const float*)d_in[3];
    const float* Wpe  = (const float*)d_in[4];
    const float* bpe  = (const float*)d_in[5];
    const float* Wii  = (const float*)d_in[6];
    const float* bii  = (const float*)d_in[7];
    const float* Whi  = (const float*)d_in[8];
    const float* bhi  = (const float*)d_in[9];
    const float* Wif  = (const float*)d_in[10];
    const float* bif_ = (const float*)d_in[11];
    const float* Whf  = (const float*)d_in[12];
    const float* bhf  = (const float*)d_in[13];
    const float* Wig  = (const float*)d_in[14];
    const float* big_ = (const float*)d_in[15];
    const float* Whg  = (const float*)d_in[16];
    const float* bhg  = (const float*)d_in[17];
    const float* Wio  = (const float*)d_in[18];
    const float* bio  = (const float*)d_in[19];
    const float* Who  = (const float*)d_in[20];
    const float* bho  = (const float*)d_in[21];
    const float* Wout = (const float*)d_in[22];
    const float* bout = (const float*)d_in[23];
    float* out = (float*)d_out;

    cudaFuncSetAttribute(k_main, cudaFuncAttributeMaxDynamicSharedMemorySize, SM_TOTAL);

    k_dinv<<<Rc, 128>>>(A);
    k_an<<<2048, 256>>>(A);
    k_prep<<<512, 128>>>(Wii, bii, Whi, bhi, Wif, bif_, Whf, bhf,
                         Wig, big_, Whg, bhg, Wio, bio, Who, bho, Wpe, bpe);
    k_init<<<Rc, 128>>>(X, Wse, bse, Wout, out);
    k_ges<<<256, 256>>>();
    k_main<<<NCTA, 256, SM_TOTAL>>>(bout, out);
}